// round 6
// baseline (speedup 1.0000x reference)
#include <cuda_runtime.h>
#include <math.h>

// Problem constants
#define Bc   2
#define Sc   2048
#define Dc   1024
#define Hc   16
#define HDc  64
#define Tc   4096      // B*S tokens
#define NEc  16        // G*E experts
#define Mc   1024      // expert hidden
#define KHc  16384     // NE*M

// ---------------- device scratch (no cudaMalloc allowed) ----------------
__device__ float g_q   [4096*1024];
__device__ float g_k   [4096*1024];
__device__ float g_v   [4096*1024];
__device__ float g_attn[4096*1024];
__device__ float g_x1  [4096*1024];
__device__ float g_h   [4096*1024];
__device__ float g_x2  [4096*1024];
__device__ float g_coef[4096*16];
__device__ float g_hid [67108864];   // 4096 x 16384

// ---------------- generic 128x128 GEMM with fused epilogues ----------------
// MODE 0: C = A@B + bias                       (QKV proj)
// MODE 1: C = A@B + bias + res                 (O proj + residual)
// MODE 2: C = coef[i,e] * relu(A@B_e + b1_e)   (MoE up, per-expert B, C ld=16384)
// MODE 3: C = A@B + sum_e coef[i,e]*b2[e,:] + res   (MoE down, K=16384)
template<int MODE>
__global__ __launch_bounds__(256) void gemm_kernel(
    const float* __restrict__ A, int lda,
    const float* __restrict__ Bmat,
    const float* __restrict__ bias,
    const float* __restrict__ res,
    const float* __restrict__ coef,
    float* __restrict__ C, int ldc, int K)
{
    __shared__ float As[16][128];
    __shared__ float Bs[16][128];
    const int tid = threadIdx.x;
    const int ntile = blockIdx.x, mtile = blockIdx.y;
    const int row0 = mtile * 128;
    const int col0 = ntile * 128;

    int e = 0;
    const float* Bp;
    const float* biasp;
    if (MODE == 2) {
        e = ntile >> 3;                                   // 8 n-tiles per expert
        Bp    = Bmat + (size_t)e * Dc * Mc + ((ntile & 7) << 7);
        biasp = bias + e * Mc + ((ntile & 7) << 7);
    } else {
        Bp    = Bmat + col0;
        biasp = bias + col0;
    }

    float acc[8][8];
#pragma unroll
    for (int i = 0; i < 8; i++)
#pragma unroll
        for (int j = 0; j < 8; j++) acc[i][j] = 0.f;

    const int tx = tid & 15, ty = tid >> 4;

    // per-thread load coordinates (2 float4 of A, 2 float4 of B per k-step)
    const int f0 = tid,            f1 = tid + 256;
    const int a0_r = f0 >> 2,      a0_k = (f0 & 3) << 2;
    const int a1_r = f1 >> 2,      a1_k = (f1 & 3) << 2;
    const int b0_k = f0 >> 5,      b0_c = (f0 & 31) << 2;
    const int b1_k = f1 >> 5,      b1_c = (f1 & 31) << 2;

    const float* Arow0 = A + (size_t)(row0 + a0_r) * lda;
    const float* Arow1 = A + (size_t)(row0 + a1_r) * lda;
    const float* Brow0 = Bp + (size_t)b0_k * 1024 + b0_c;
    const float* Brow1 = Bp + (size_t)b1_k * 1024 + b1_c;

    // prefetch kb = 0
    float4 pa0 = *(const float4*)(Arow0 + a0_k);
    float4 pa1 = *(const float4*)(Arow1 + a1_k);
    float4 pb0 = *(const float4*)(Brow0);
    float4 pb1 = *(const float4*)(Brow1);

    for (int kb = 0; kb < K; kb += 16) {
        // commit prefetched tile to smem
        As[a0_k + 0][a0_r] = pa0.x; As[a0_k + 1][a0_r] = pa0.y;
        As[a0_k + 2][a0_r] = pa0.z; As[a0_k + 3][a0_r] = pa0.w;
        As[a1_k + 0][a1_r] = pa1.x; As[a1_k + 1][a1_r] = pa1.y;
        As[a1_k + 2][a1_r] = pa1.z; As[a1_k + 3][a1_r] = pa1.w;
        *(float4*)&Bs[b0_k][b0_c] = pb0;
        *(float4*)&Bs[b1_k][b1_c] = pb1;
        __syncthreads();

        // issue next tile's global loads (latency hidden under compute)
        if (kb + 16 < K) {
            pa0 = *(const float4*)(Arow0 + kb + 16 + a0_k);
            pa1 = *(const float4*)(Arow1 + kb + 16 + a1_k);
            pb0 = *(const float4*)(Brow0 + (size_t)(kb + 16) * 1024);
            pb1 = *(const float4*)(Brow1 + (size_t)(kb + 16) * 1024);
        }

#pragma unroll
        for (int kk = 0; kk < 16; kk++) {
            float a[8], bv[8];
            *(float4*)&a[0]  = *(const float4*)&As[kk][ty * 8];
            *(float4*)&a[4]  = *(const float4*)&As[kk][ty * 8 + 4];
            *(float4*)&bv[0] = *(const float4*)&Bs[kk][tx * 8];
            *(float4*)&bv[4] = *(const float4*)&Bs[kk][tx * 8 + 4];
#pragma unroll
            for (int i = 0; i < 8; i++)
#pragma unroll
                for (int j = 0; j < 8; j++) acc[i][j] += a[i] * bv[j];
        }
        __syncthreads();
    }

#pragma unroll
    for (int ii = 0; ii < 8; ii++) {
        const int i = row0 + ty * 8 + ii;
        float cf = 0.f;
        float cf16[16];
        if (MODE == 2) cf = coef[(size_t)i * 16 + e];
        if (MODE == 3) {
#pragma unroll
            for (int e2 = 0; e2 < 16; e2++) cf16[e2] = coef[(size_t)i * 16 + e2];
        }
#pragma unroll
        for (int jj = 0; jj < 8; jj++) {
            const int jl = tx * 8 + jj;
            const int j  = col0 + jl;
            float v2 = acc[ii][jj];
            if (MODE == 0 || MODE == 1 || MODE == 2) v2 += biasp[jl];
            if (MODE == 1) v2 += res[(size_t)i * Dc + j];
            if (MODE == 2) v2 = fmaxf(v2, 0.f) * cf;
            if (MODE == 3) {
#pragma unroll
                for (int e2 = 0; e2 < 16; e2++) v2 += cf16[e2] * biasp[e2 * Dc + jl];
                v2 += res[(size_t)i * Dc + j];
            }
            C[(size_t)i * ldc + j] = v2;
        }
    }
}

// ---------------- flash attention, 64x64 tiles, causal ----------------
// Qs/Ps row stride = 68 floats (multiple of 4 -> all float4 accesses 16B aligned)
#define QS_LD 68
__global__ __launch_bounds__(256) void attn_kernel(
    const float* __restrict__ q, const float* __restrict__ k,
    const float* __restrict__ v, float* __restrict__ o)
{
    extern __shared__ float sm[];
    float* Qs = sm;                     // [64][QS_LD]
    float* Kt = sm + 64 * QS_LD;        // [64][64]  (d-major: Kt[d][c])
    float* Vs = Kt + 64 * 64;           // [64][64]
    float* Ps = Vs + 64 * 64;           // [64][QS_LD]

    const int tid = threadIdx.x;
    const int qb = blockIdx.x, h = blockIdx.y, b = blockIdx.z;
    const size_t base = ((size_t)b * Sc) * Dc + h * HDc;

#pragma unroll
    for (int it = 0; it < 4; it++) {
        int f = tid + it * 256;
        int rr = f >> 4, d4 = (f & 15) << 2;
        *(float4*)&Qs[rr * QS_LD + d4] =
            *(const float4*)(q + base + (size_t)(qb * 64 + rr) * Dc + d4);
    }

    const int r = tid >> 2, cg = tid & 3;
    const int qi = qb * 64 + r;
    float out[16];
#pragma unroll
    for (int j2 = 0; j2 < 16; j2++) out[j2] = 0.f;
    float mrun = -1e30f, lrun = 0.f;

    for (int kb = 0; kb <= qb; kb++) {
        __syncthreads();
#pragma unroll
        for (int it = 0; it < 4; it++) {
            int f = tid + it * 256;
            int rr = f >> 4, d4 = (f & 15) << 2;
            float4 kv = *(const float4*)(k + base + (size_t)(kb * 64 + rr) * Dc + d4);
            Kt[(d4 + 0) * 64 + rr] = kv.x; Kt[(d4 + 1) * 64 + rr] = kv.y;
            Kt[(d4 + 2) * 64 + rr] = kv.z; Kt[(d4 + 3) * 64 + rr] = kv.w;
            *(float4*)&Vs[rr * 64 + d4] =
                *(const float4*)(v + base + (size_t)(kb * 64 + rr) * Dc + d4);
        }
        __syncthreads();

        float s[16];
#pragma unroll
        for (int c = 0; c < 16; c++) s[c] = 0.f;
#pragma unroll 4
        for (int d = 0; d < 64; d++) {
            float qv = Qs[r * QS_LD + d];
            const float* kp = &Kt[d * 64 + cg * 16];
            float4 k0 = *(const float4*)(kp);
            float4 k1 = *(const float4*)(kp + 4);
            float4 k2 = *(const float4*)(kp + 8);
            float4 k3 = *(const float4*)(kp + 12);
            s[0] += qv * k0.x; s[1] += qv * k0.y; s[2] += qv * k0.z; s[3] += qv * k0.w;
            s[4] += qv * k1.x; s[5] += qv * k1.y; s[6] += qv * k1.z; s[7] += qv * k1.w;
            s[8] += qv * k2.x; s[9] += qv * k2.y; s[10]+= qv * k2.z; s[11]+= qv * k2.w;
            s[12]+= qv * k3.x; s[13]+= qv * k3.y; s[14]+= qv * k3.z; s[15]+= qv * k3.w;
        }

        float mloc = -1e30f;
#pragma unroll
        for (int c = 0; c < 16; c++) {
            float sv = s[c] * 0.125f;            // 1/sqrt(64)
            int kj = kb * 64 + cg * 16 + c;
            if (kj > qi) sv = -1e9f;             // causal mask (matches ref)
            s[c] = sv;
            mloc = fmaxf(mloc, sv);
        }
        mloc = fmaxf(mloc, __shfl_xor_sync(0xffffffffu, mloc, 1));
        mloc = fmaxf(mloc, __shfl_xor_sync(0xffffffffu, mloc, 2));
        const float mnew  = fmaxf(mrun, mloc);
        const float alpha = __expf(mrun - mnew);
        float lloc = 0.f;
#pragma unroll
        for (int c = 0; c < 16; c++) { float p = __expf(s[c] - mnew); s[c] = p; lloc += p; }
        lloc += __shfl_xor_sync(0xffffffffu, lloc, 1);
        lloc += __shfl_xor_sync(0xffffffffu, lloc, 2);
        lrun = lrun * alpha + lloc;
        mrun = mnew;
#pragma unroll
        for (int j2 = 0; j2 < 16; j2++) out[j2] *= alpha;

#pragma unroll
        for (int c = 0; c < 16; c++) Ps[r * QS_LD + cg * 16 + c] = s[c];
        __syncwarp();

#pragma unroll 2
        for (int c = 0; c < 64; c++) {
            float p = Ps[r * QS_LD + c];
            const float* vp = &Vs[c * 64 + cg * 16];
            float4 v0 = *(const float4*)vp,      v1 = *(const float4*)(vp + 4);
            float4 v2 = *(const float4*)(vp + 8), v3 = *(const float4*)(vp + 12);
            out[0] += p * v0.x; out[1] += p * v0.y; out[2] += p * v0.z; out[3] += p * v0.w;
            out[4] += p * v1.x; out[5] += p * v1.y; out[6] += p * v1.z; out[7] += p * v1.w;
            out[8] += p * v2.x; out[9] += p * v2.y; out[10]+= p * v2.z; out[11]+= p * v2.w;
            out[12]+= p * v3.x; out[13]+= p * v3.y; out[14]+= p * v3.z; out[15]+= p * v3.w;
        }
    }

    const float invl = 1.f / lrun;
#pragma unroll
    for (int j2 = 0; j2 < 16; j2++)
        o[base + (size_t)qi * Dc + cg * 16 + j2] = out[j2] * invl;
}

// ---------------- LayerNorm (one block per row of 1024) ----------------
__global__ __launch_bounds__(256) void ln_kernel(
    const float* __restrict__ x, const float* __restrict__ gam,
    const float* __restrict__ bet, float* __restrict__ o)
{
    const int row = blockIdx.x, tid = threadIdx.x;
    const float4 v = *(const float4*)(x + (size_t)row * 1024 + tid * 4);
    float s = v.x + v.y + v.z + v.w;
    float q = v.x * v.x + v.y * v.y + v.z * v.z + v.w * v.w;
#pragma unroll
    for (int off = 16; off; off >>= 1) {
        s += __shfl_xor_sync(0xffffffffu, s, off);
        q += __shfl_xor_sync(0xffffffffu, q, off);
    }
    __shared__ float ss[8], sq[8];
    if ((tid & 31) == 0) { ss[tid >> 5] = s; sq[tid >> 5] = q; }
    __syncthreads();
    float S = 0.f, Q = 0.f;
#pragma unroll
    for (int w = 0; w < 8; w++) { S += ss[w]; Q += sq[w]; }
    const float mu  = S * (1.f / 1024.f);
    const float var = Q * (1.f / 1024.f) - mu * mu;
    const float inv = rsqrtf(var + 1e-5f);
    float4 g4 = *(const float4*)(gam + tid * 4);
    float4 b4 = *(const float4*)(bet + tid * 4);
    float4 r4;
    r4.x = (v.x - mu) * inv * g4.x + b4.x;
    r4.y = (v.y - mu) * inv * g4.y + b4.y;
    r4.z = (v.z - mu) * inv * g4.z + b4.z;
    r4.w = (v.w - mu) * inv * g4.w + b4.w;
    *(float4*)(o + (size_t)row * 1024 + tid * 4) = r4;
}

// ---------------- gate: logits + per-gate softmax, /G folded in ----------------
__global__ __launch_bounds__(128) void gate_kernel(
    const float* __restrict__ h, const float* __restrict__ gW,
    const float* __restrict__ gb, float* __restrict__ coef)
{
    const int t = blockIdx.x, tid = threadIdx.x;
    float acc[16];
#pragma unroll
    for (int j = 0; j < 16; j++) acc[j] = 0.f;
    const float* hr = h + (size_t)t * 1024;
    for (int d = tid; d < 1024; d += 128) {
        float hv = hr[d];
#pragma unroll
        for (int g = 0; g < 2; g++)
#pragma unroll
            for (int e = 0; e < 8; e++)
                acc[g * 8 + e] += hv * gW[g * 8192 + d * 8 + e];
    }
    __shared__ float red[16][4];
#pragma unroll
    for (int j = 0; j < 16; j++) {
        float vv = acc[j];
        for (int off = 16; off; off >>= 1) vv += __shfl_xor_sync(0xffffffffu, vv, off);
        if ((tid & 31) == 0) red[j][tid >> 5] = vv;
    }
    __syncthreads();
    if (tid < 16) {
        float lg = red[tid][0] + red[tid][1] + red[tid][2] + red[tid][3] + gb[tid];
        float mx = lg;
        for (int off = 4; off; off >>= 1) mx = fmaxf(mx, __shfl_xor_sync(0xffffu, mx, off));
        float ex = __expf(lg - mx);
        float sm = ex;
        for (int off = 4; off; off >>= 1) sm += __shfl_xor_sync(0xffffu, sm, off);
        coef[(size_t)t * 16 + tid] = ex / sm * 0.5f;   // softmax per gate, /G
    }
}

#define ATTN_SMEM (64 * (QS_LD + 64 + 64 + QS_LD) * 4)

extern "C" void kernel_launch(void* const* d_in, const int* in_sizes, int n_in,
                              void* d_out, int out_size)
{
    const float* input  = (const float*)d_in[0];
    const float* Wq     = (const float*)d_in[1];
    const float* bq     = (const float*)d_in[2];
    const float* Wk     = (const float*)d_in[3];
    const float* bk     = (const float*)d_in[4];
    const float* Wv     = (const float*)d_in[5];
    const float* bv     = (const float*)d_in[6];
    const float* Wo     = (const float*)d_in[7];
    const float* bo     = (const float*)d_in[8];
    const float* ln1_g  = (const float*)d_in[9];
    const float* ln1_b  = (const float*)d_in[10];
    const float* gate_W = (const float*)d_in[11];
    const float* gate_b = (const float*)d_in[12];
    const float* eW1    = (const float*)d_in[13];
    const float* eb1    = (const float*)d_in[14];
    const float* eW2    = (const float*)d_in[15];
    const float* eb2    = (const float*)d_in[16];
    const float* ln2_g  = (const float*)d_in[17];
    const float* ln2_b  = (const float*)d_in[18];
    float* out = (float*)d_out;

    float *q, *k, *v, *attn, *x1, *hbuf, *x2, *coef, *hid;
    cudaGetSymbolAddress((void**)&q,    g_q);
    cudaGetSymbolAddress((void**)&k,    g_k);
    cudaGetSymbolAddress((void**)&v,    g_v);
    cudaGetSymbolAddress((void**)&attn, g_attn);
    cudaGetSymbolAddress((void**)&x1,   g_x1);
    cudaGetSymbolAddress((void**)&hbuf, g_h);
    cudaGetSymbolAddress((void**)&x2,   g_x2);
    cudaGetSymbolAddress((void**)&coef, g_coef);
    cudaGetSymbolAddress((void**)&hid,  g_hid);

    cudaFuncSetAttribute(attn_kernel, cudaFuncAttributeMaxDynamicSharedMemorySize, ATTN_SMEM);

    dim3 blk(256);
    // QKV projections
    gemm_kernel<0><<<dim3(8, 32), blk>>>(input, 1024, Wq, bq, nullptr, nullptr, q, 1024, 1024);
    gemm_kernel<0><<<dim3(8, 32), blk>>>(input, 1024, Wk, bk, nullptr, nullptr, k, 1024, 1024);
    gemm_kernel<0><<<dim3(8, 32), blk>>>(input, 1024, Wv, bv, nullptr, nullptr, v, 1024, 1024);
    // attention
    attn_kernel<<<dim3(32, 16, 2), blk, ATTN_SMEM>>>(q, k, v, attn);
    // O projection + residual, LN1
    gemm_kernel<1><<<dim3(8, 32), blk>>>(attn, 1024, Wo, bo, input, nullptr, x1, 1024, 1024);
    ln_kernel<<<4096, blk>>>(x1, ln1_g, ln1_b, hbuf);
    // gates
    gate_kernel<<<4096, 128>>>(hbuf, gate_W, gate_b, coef);
    // MoE up (fused relu + gate scaling) and down (fused combined bias + residual)
    gemm_kernel<2><<<dim3(128, 32), blk>>>(hbuf, 1024, eW1, eb1, nullptr, coef, hid, 16384, 1024);
    gemm_kernel<3><<<dim3(8, 32),  blk>>>(hid, 16384, eW2, eb2, hbuf, coef, x2, 1024, 16384);
    // LN2 -> output
    ln_kernel<<<4096, blk>>>(x2, ln2_g, ln2_b, out);
}

// round 11
// speedup vs baseline: 1.5263x; 1.5263x over previous
#include <cuda_runtime.h>
#include <cuda_bf16.h>
#include <stdint.h>
#include <math.h>

// Problem constants
#define Bc   2
#define Sc   2048
#define Dc   1024
#define Tc   4096      // B*S tokens

// ---------------- device scratch (no cudaMalloc allowed) ----------------
__device__ float g_q   [4096*1024];
__device__ float g_k   [4096*1024];
__device__ float g_v   [4096*1024];
__device__ float g_attn[4096*1024];
__device__ float g_x1  [4096*1024];
__device__ float g_h   [4096*1024];
__device__ float g_x2  [4096*1024];
__device__ float g_coef[4096*16];
__device__ __nv_bfloat16 g_hhi [4096*1024];
__device__ __nv_bfloat16 g_hlo [4096*1024];
__device__ __nv_bfloat16 g_B1h [16777216];   // [16384 n][1024 k]
__device__ __nv_bfloat16 g_B1l [16777216];
__device__ __nv_bfloat16 g_B2h [16777216];   // [1024 d][16384 k]
__device__ __nv_bfloat16 g_B2l [16777216];
__device__ __nv_bfloat16 g_hidh[67108864];   // [4096][16384]
__device__ __nv_bfloat16 g_hidl[67108864];

// ======================= helpers =======================
__device__ __forceinline__ uint32_t smem_to_u32(const void* p) {
    uint32_t a;
    asm("{ .reg .u64 t; cvta.to.shared.u64 t, %1; cvt.u32.u64 %0, t; }" : "=r"(a) : "l"(p));
    return a;
}
__device__ __forceinline__ void cp_async16(uint32_t saddr, const void* gaddr) {
    asm volatile("cp.async.cg.shared.global [%0], [%1], 16;" :: "r"(saddr), "l"(gaddr));
}
#define CP_COMMIT() asm volatile("cp.async.commit_group;" ::: "memory")
#define CP_WAIT(n)  asm volatile("cp.async.wait_group %0;" :: "n"(n) : "memory")

__device__ __forceinline__ void ldsm_x4(uint32_t* r, uint32_t a) {
    asm volatile("ldmatrix.sync.aligned.m8n8.x4.shared.b16 {%0,%1,%2,%3}, [%4];"
                 : "=r"(r[0]), "=r"(r[1]), "=r"(r[2]), "=r"(r[3]) : "r"(a));
}
__device__ __forceinline__ void ldsm_x2(uint32_t* r, uint32_t a) {
    asm volatile("ldmatrix.sync.aligned.m8n8.x2.shared.b16 {%0,%1}, [%2];"
                 : "=r"(r[0]), "=r"(r[1]) : "r"(a));
}
__device__ __forceinline__ void mma16816(float* c, const uint32_t* a, const uint32_t* b) {
    asm volatile("mma.sync.aligned.m16n8k16.row.col.f32.bf16.bf16.f32 "
                 "{%0,%1,%2,%3}, {%4,%5,%6,%7}, {%8,%9}, {%0,%1,%2,%3};"
                 : "+f"(c[0]), "+f"(c[1]), "+f"(c[2]), "+f"(c[3])
                 : "r"(a[0]), "r"(a[1]), "r"(a[2]), "r"(a[3]), "r"(b[0]), "r"(b[1]));
}

__device__ __forceinline__ uint32_t packbf2(float a, float b, uint32_t& lo) {
    __nv_bfloat16 ha = __float2bfloat16_rn(a), hb = __float2bfloat16_rn(b);
    float la = a - __bfloat162float(ha), lb = b - __bfloat162float(hb);
    __nv_bfloat162 l2 = __halves2bfloat162(__float2bfloat16_rn(la), __float2bfloat16_rn(lb));
    lo = *(uint32_t*)&l2;
    __nv_bfloat162 h2 = __halves2bfloat162(ha, hb);
    return *(uint32_t*)&h2;
}

// ============ mma.sync GEMM: 256x128 CTA tile, bf16 3-term split ============
// MODE 2: hid = coef[t,e]*relu(A@B + b1)   -> bf16 hi/lo   (K=1024, ldOut 16384)
// MODE 3: x2  = A@B + sum_e coef*b2[e] + res -> fp32       (K=16384, ldOut 1024)
// A[row][k] hi/lo bf16, B[n][k] hi/lo bf16 (both K-major).
// smem: 2 chunk buffers of 61440B: Ah(256x80) Al Bh(128x80) Bl; bias_sm @122880
#define MMG_SMEM   131072
#define CHUNK_B    61440
template<int MODE>
__global__ __launch_bounds__(512, 1) void mma_gemm(
    const __nv_bfloat16* __restrict__ Ahi, const __nv_bfloat16* __restrict__ Alo, int lda,
    const __nv_bfloat16* __restrict__ Bhi, const __nv_bfloat16* __restrict__ Blo, int ldb,
    const float* __restrict__ bias, const float* __restrict__ res,
    const float* __restrict__ coef,
    __nv_bfloat16* __restrict__ Ohi, __nv_bfloat16* __restrict__ Olo,
    float* __restrict__ Of, int K)
{
    extern __shared__ char smem[];
    const int tid  = threadIdx.x;
    const int lane = tid & 31, wid = tid >> 5;
    const int wm = wid & 7, wn = wid >> 3;      // warp grid 8m x 2n, warp tile 32x64
    const int row0 = blockIdx.y * 256, col0 = blockIdx.x * 128;
    uint32_t sb = smem_to_u32(smem);

    float* bias_sm = (float*)(smem + 122880);
    if (MODE == 3) {
        for (int i = tid; i < 2048; i += 512)
            bias_sm[i] = bias[(i >> 7) * 1024 + col0 + (i & 127)];
    }

    float acc[2][8][4];
#pragma unroll
    for (int mi = 0; mi < 2; mi++)
#pragma unroll
        for (int ni = 0; ni < 8; ni++)
#pragma unroll
            for (int q = 0; q < 4; q++) acc[mi][ni][q] = 0.f;

    auto issue_chunk = [&](int c) {
        const int kb = c * 32;
        uint32_t bufu = sb + (c & 1) * CHUNK_B;
#pragma unroll
        for (int it = 0; it < 6; it++) {
            int idx = tid + it * 512;               // 0..3071
            const __nv_bfloat16* src;
            uint32_t dst;
            if (idx < 2048) {                       // A: 2 mats x 256 rows x 4 segs
                int m = idx >> 10, rem = idx & 1023, r = rem >> 2, s = rem & 3;
                src = (m ? Alo : Ahi) + (size_t)(row0 + r) * lda + kb + s * 8;
                dst = bufu + m * 20480 + r * 80 + s * 16;
            } else {                                // B: 2 mats x 128 rows x 4 segs
                int i2 = idx - 2048;
                int m = i2 >> 9, rem = i2 & 511, r = rem >> 2, s = rem & 3;
                src = (m ? Blo : Bhi) + (size_t)(col0 + r) * ldb + kb + s * 8;
                dst = bufu + 40960 + m * 10240 + r * 80 + s * 16;
            }
            cp_async16(dst, src);
        }
        CP_COMMIT();
    };

    const int NC = K / 32;
    issue_chunk(0);
    for (int c = 0; c < NC; c++) {
        if (c + 1 < NC) { issue_chunk(c + 1); CP_WAIT(1); }
        else            { CP_WAIT(0); }
        __syncthreads();
        uint32_t base = sb + (c & 1) * CHUNK_B;
        // A frag addresses: x4 tiles {m0-7 k0, m8-15 k0, m0-7 k8, m8-15 k8}
        uint32_t aAh = base + (wm * 32 + (lane & 15)) * 80 + (lane >> 4) * 16;
#pragma unroll
        for (int kk = 0; kk < 2; kk++) {
            uint32_t ah[2][4], al[2][4];
            ldsm_x4(ah[0], aAh + kk * 32);
            ldsm_x4(ah[1], aAh + 16 * 80 + kk * 32);
            ldsm_x4(al[0], aAh + 20480 + kk * 32);
            ldsm_x4(al[1], aAh + 20480 + 16 * 80 + kk * 32);
#pragma unroll
            for (int ni = 0; ni < 8; ni++) {
                uint32_t bh[2], bl[2];
                uint32_t ab = base + 40960 + (wn * 64 + ni * 8 + (lane & 7)) * 80
                              + ((lane >> 3) & 1) * 16 + kk * 32;
                ldsm_x2(bh, ab);
                ldsm_x2(bl, ab + 10240);
                mma16816(acc[0][ni], ah[0], bh);
                mma16816(acc[1][ni], ah[1], bh);
                mma16816(acc[0][ni], ah[0], bl);
                mma16816(acc[1][ni], ah[1], bl);
                mma16816(acc[0][ni], al[0], bh);
                mma16816(acc[1][ni], al[1], bh);
            }
        }
        __syncthreads();
    }

    if (MODE == 2) {
        const int e  = col0 >> 10;
        const int cb = col0 & 1023;
        int   rr[2][2];
        float cf[2][2];
#pragma unroll
        for (int mi = 0; mi < 2; mi++)
#pragma unroll
            for (int h = 0; h < 2; h++) {
                rr[mi][h] = row0 + wm * 32 + mi * 16 + (lane >> 2) + 8 * h;
                cf[mi][h] = coef[(size_t)rr[mi][h] * 16 + e];
            }
#pragma unroll
        for (int mi = 0; mi < 2; mi++)
#pragma unroll
        for (int ni = 0; ni < 8; ni++) {
            int cl = wn * 64 + ni * 8 + (lane & 3) * 2;
            float b0 = bias[e * 1024 + cb + cl];
            float b1 = bias[e * 1024 + cb + cl + 1];
#pragma unroll
            for (int h = 0; h < 2; h++) {
                float v0 = fmaxf(acc[mi][ni][2 * h + 0] + b0, 0.f) * cf[mi][h];
                float v1 = fmaxf(acc[mi][ni][2 * h + 1] + b1, 0.f) * cf[mi][h];
                uint32_t lo, hi = packbf2(v0, v1, lo);
                size_t o = (size_t)rr[mi][h] * 16384 + col0 + cl;
                *(uint32_t*)(Ohi + o) = hi;
                *(uint32_t*)(Olo + o) = lo;
            }
        }
    } else {
#pragma unroll
        for (int mi = 0; mi < 2; mi++)
#pragma unroll
        for (int h = 0; h < 2; h++) {
            int r2 = row0 + wm * 32 + mi * 16 + (lane >> 2) + 8 * h;
            float cf16[16];
#pragma unroll
            for (int e2 = 0; e2 < 4; e2++)
                *(float4*)&cf16[e2 * 4] = *(const float4*)(coef + (size_t)r2 * 16 + e2 * 4);
#pragma unroll
            for (int ni = 0; ni < 8; ni++) {
                int cl = wn * 64 + ni * 8 + (lane & 3) * 2;
                float2 rv = *(const float2*)(res + (size_t)r2 * 1024 + col0 + cl);
                float v0 = acc[mi][ni][2 * h + 0] + rv.x;
                float v1 = acc[mi][ni][2 * h + 1] + rv.y;
#pragma unroll
                for (int e2 = 0; e2 < 16; e2++) {
                    v0 += cf16[e2] * bias_sm[e2 * 128 + cl];
                    v1 += cf16[e2] * bias_sm[e2 * 128 + cl + 1];
                }
                float2 ov; ov.x = v0; ov.y = v1;
                *(float2*)(Of + (size_t)r2 * 1024 + col0 + cl) = ov;
            }
        }
    }
}

// ---------- per-expert 1024x1024 transpose + hi/lo bf16 split ----------
__global__ __launch_bounds__(256) void transpose_split_kernel(
    const float* __restrict__ in, __nv_bfloat16* __restrict__ ohi,
    __nv_bfloat16* __restrict__ olo, int mode)
{
    __shared__ float tsm[32][33];
    const int e = blockIdx.z;
    const int kt = blockIdx.x, nt = blockIdx.y;
    const float* ip = in + ((size_t)e << 20);
    const int tx = threadIdx.x, ty = threadIdx.y;   // 32 x 8
    for (int yy = ty; yy < 32; yy += 8)
        tsm[yy][tx] = ip[(size_t)(kt * 32 + yy) * 1024 + nt * 32 + tx];
    __syncthreads();
    for (int yy = ty; yy < 32; yy += 8) {
        int n = nt * 32 + yy, k = kt * 32 + tx;
        float v = tsm[tx][yy];
        size_t o = (mode == 0) ? ((size_t)(e * 1024 + n) * 1024 + k)
                               : ((size_t)n * 16384 + e * 1024 + k);
        __nv_bfloat16 hi = __float2bfloat16_rn(v);
        ohi[o] = hi;
        olo[o] = __float2bfloat16_rn(v - __bfloat162float(hi));
    }
}

// ---------------- fp32 128x128 GEMM (QKV / O proj) ----------------
template<int MODE>
__global__ __launch_bounds__(256) void gemm_kernel(
    const float* __restrict__ A, int lda,
    const float* __restrict__ Bmat,
    const float* __restrict__ bias,
    const float* __restrict__ res,
    float* __restrict__ C, int ldc, int K)
{
    __shared__ float As[16][128];
    __shared__ float Bs[16][128];
    const int tid = threadIdx.x;
    const int ntile = blockIdx.x, mtile = blockIdx.y;
    const int row0 = mtile * 128, col0 = ntile * 128;
    const float* Bp = Bmat + col0;
    const float* biasp = bias + col0;

    float acc[8][8];
#pragma unroll
    for (int i = 0; i < 8; i++)
#pragma unroll
        for (int j = 0; j < 8; j++) acc[i][j] = 0.f;

    const int tx = tid & 15, ty = tid >> 4;
    const int f0 = tid, f1 = tid + 256;
    const int a0_r = f0 >> 2, a0_k = (f0 & 3) << 2;
    const int a1_r = f1 >> 2, a1_k = (f1 & 3) << 2;
    const int b0_k = f0 >> 5, b0_c = (f0 & 31) << 2;
    const int b1_k = f1 >> 5, b1_c = (f1 & 31) << 2;

    const float* Arow0 = A + (size_t)(row0 + a0_r) * lda;
    const float* Arow1 = A + (size_t)(row0 + a1_r) * lda;
    const float* Brow0 = Bp + (size_t)b0_k * 1024 + b0_c;
    const float* Brow1 = Bp + (size_t)b1_k * 1024 + b1_c;

    float4 pa0 = *(const float4*)(Arow0 + a0_k);
    float4 pa1 = *(const float4*)(Arow1 + a1_k);
    float4 pb0 = *(const float4*)(Brow0);
    float4 pb1 = *(const float4*)(Brow1);

    for (int kb = 0; kb < K; kb += 16) {
        As[a0_k + 0][a0_r] = pa0.x; As[a0_k + 1][a0_r] = pa0.y;
        As[a0_k + 2][a0_r] = pa0.z; As[a0_k + 3][a0_r] = pa0.w;
        As[a1_k + 0][a1_r] = pa1.x; As[a1_k + 1][a1_r] = pa1.y;
        As[a1_k + 2][a1_r] = pa1.z; As[a1_k + 3][a1_r] = pa1.w;
        *(float4*)&Bs[b0_k][b0_c] = pb0;
        *(float4*)&Bs[b1_k][b1_c] = pb1;
        __syncthreads();
        if (kb + 16 < K) {
            pa0 = *(const float4*)(Arow0 + kb + 16 + a0_k);
            pa1 = *(const float4*)(Arow1 + kb + 16 + a1_k);
            pb0 = *(const float4*)(Brow0 + (size_t)(kb + 16) * 1024);
            pb1 = *(const float4*)(Brow1 + (size_t)(kb + 16) * 1024);
        }
#pragma unroll
        for (int kk = 0; kk < 16; kk++) {
            float a[8], bv[8];
            *(float4*)&a[0]  = *(const float4*)&As[kk][ty * 8];
            *(float4*)&a[4]  = *(const float4*)&As[kk][ty * 8 + 4];
            *(float4*)&bv[0] = *(const float4*)&Bs[kk][tx * 8];
            *(float4*)&bv[4] = *(const float4*)&Bs[kk][tx * 8 + 4];
#pragma unroll
            for (int i = 0; i < 8; i++)
#pragma unroll
                for (int j = 0; j < 8; j++) acc[i][j] += a[i] * bv[j];
        }
        __syncthreads();
    }
#pragma unroll
    for (int ii = 0; ii < 8; ii++) {
        const int i = row0 + ty * 8 + ii;
#pragma unroll
        for (int jj = 0; jj < 8; jj++) {
            const int jl = tx * 8 + jj;
            const int j = col0 + jl;
            float v2 = acc[ii][jj] + biasp[jl];
            if (MODE == 1) v2 += res[(size_t)i * Dc + j];
            C[(size_t)i * ldc + j] = v2;
        }
    }
}

// ---------------- flash attention, 64x64 tiles, causal ----------------
#define QS_LD 68
__global__ __launch_bounds__(256) void attn_kernel(
    const float* __restrict__ q, const float* __restrict__ k,
    const float* __restrict__ v, float* __restrict__ o)
{
    extern __shared__ float sm[];
    float* Qs = sm;
    float* Kt = sm + 64 * QS_LD;
    float* Vs = Kt + 64 * 64;
    float* Ps = Vs + 64 * 64;

    const int tid = threadIdx.x;
    const int qb = blockIdx.x, h = blockIdx.y, b = blockIdx.z;
    const size_t base = ((size_t)b * Sc) * Dc + h * 64;

#pragma unroll
    for (int it = 0; it < 4; it++) {
        int f = tid + it * 256;
        int rr = f >> 4, d4 = (f & 15) << 2;
        *(float4*)&Qs[rr * QS_LD + d4] =
            *(const float4*)(q + base + (size_t)(qb * 64 + rr) * Dc + d4);
    }

    const int r = tid >> 2, cg = tid & 3;
    const int qi = qb * 64 + r;
    float out[16];
#pragma unroll
    for (int j2 = 0; j2 < 16; j2++) out[j2] = 0.f;
    float mrun = -1e30f, lrun = 0.f;

    for (int kb = 0; kb <= qb; kb++) {
        __syncthreads();
#pragma unroll
        for (int it = 0; it < 4; it++) {
            int f = tid + it * 256;
            int rr = f >> 4, d4 = (f & 15) << 2;
            float4 kv = *(const float4*)(k + base + (size_t)(kb * 64 + rr) * Dc + d4);
            Kt[(d4 + 0) * 64 + rr] = kv.x; Kt[(d4 + 1) * 64 + rr] = kv.y;
            Kt[(d4 + 2) * 64 + rr] = kv.z; Kt[(d4 + 3) * 64 + rr] = kv.w;
            *(float4*)&Vs[rr * 64 + d4] =
                *(const float4*)(v + base + (size_t)(kb * 64 + rr) * Dc + d4);
        }
        __syncthreads();

        float s[16];
#pragma unroll
        for (int c = 0; c < 16; c++) s[c] = 0.f;
#pragma unroll 4
        for (int d = 0; d < 64; d++) {
            float qv = Qs[r * QS_LD + d];
            const float* kp = &Kt[d * 64 + cg * 16];
            float4 k0 = *(const float4*)(kp);
            float4 k1 = *(const float4*)(kp + 4);
            float4 k2 = *(const float4*)(kp + 8);
            float4 k3 = *(const float4*)(kp + 12);
            s[0] += qv * k0.x; s[1] += qv * k0.y; s[2] += qv * k0.z; s[3] += qv * k0.w;
            s[4] += qv * k1.x; s[5] += qv * k1.y; s[6] += qv * k1.z; s[7] += qv * k1.w;
            s[8] += qv * k2.x; s[9] += qv * k2.y; s[10]+= qv * k2.z; s[11]+= qv * k2.w;
            s[12]+= qv * k3.x; s[13]+= qv * k3.y; s[14]+= qv * k3.z; s[15]+= qv * k3.w;
        }

        float mloc = -1e30f;
#pragma unroll
        for (int c = 0; c < 16; c++) {
            float sv = s[c] * 0.125f;
            int kj = kb * 64 + cg * 16 + c;
            if (kj > qi) sv = -1e9f;
            s[c] = sv;
            mloc = fmaxf(mloc, sv);
        }
        mloc = fmaxf(mloc, __shfl_xor_sync(0xffffffffu, mloc, 1));
        mloc = fmaxf(mloc, __shfl_xor_sync(0xffffffffu, mloc, 2));
        const float mnew = fmaxf(mrun, mloc);
        const float alpha = __expf(mrun - mnew);
        float lloc = 0.f;
#pragma unroll
        for (int c = 0; c < 16; c++) { float p = __expf(s[c] - mnew); s[c] = p; lloc += p; }
        lloc += __shfl_xor_sync(0xffffffffu, lloc, 1);
        lloc += __shfl_xor_sync(0xffffffffu, lloc, 2);
        lrun = lrun * alpha + lloc;
        mrun = mnew;
#pragma unroll
        for (int j2 = 0; j2 < 16; j2++) out[j2] *= alpha;

#pragma unroll
        for (int c = 0; c < 16; c++) Ps[r * QS_LD + cg * 16 + c] = s[c];
        __syncwarp();

#pragma unroll 2
        for (int c = 0; c < 64; c++) {
            float p = Ps[r * QS_LD + c];
            const float* vp = &Vs[c * 64 + cg * 16];
            float4 v0 = *(const float4*)vp, v1 = *(const float4*)(vp + 4);
            float4 v2 = *(const float4*)(vp + 8), v3 = *(const float4*)(vp + 12);
            out[0] += p * v0.x; out[1] += p * v0.y; out[2] += p * v0.z; out[3] += p * v0.w;
            out[4] += p * v1.x; out[5] += p * v1.y; out[6] += p * v1.z; out[7] += p * v1.w;
            out[8] += p * v2.x; out[9] += p * v2.y; out[10]+= p * v2.z; out[11]+= p * v2.w;
            out[12]+= p * v3.x; out[13]+= p * v3.y; out[14]+= p * v3.z; out[15]+= p * v3.w;
        }
    }

    const float invl = 1.f / lrun;
#pragma unroll
    for (int j2 = 0; j2 < 16; j2++)
        o[base + (size_t)qi * Dc + cg * 16 + j2] = out[j2] * invl;
}

// ---------------- LayerNorm (optionally emits bf16 hi/lo split) ----------------
template<bool SPLIT>
__global__ __launch_bounds__(256) void ln_kernel(
    const float* __restrict__ x, const float* __restrict__ gam,
    const float* __restrict__ bet, float* __restrict__ o,
    __nv_bfloat16* __restrict__ ohi, __nv_bfloat16* __restrict__ olo)
{
    const int row = blockIdx.x, tid = threadIdx.x;
    const float4 v = *(const float4*)(x + (size_t)row * 1024 + tid * 4);
    float s = v.x + v.y + v.z + v.w;
    float q = v.x * v.x + v.y * v.y + v.z * v.z + v.w * v.w;
#pragma unroll
    for (int off = 16; off; off >>= 1) {
        s += __shfl_xor_sync(0xffffffffu, s, off);
        q += __shfl_xor_sync(0xffffffffu, q, off);
    }
    __shared__ float ss[8], sq[8];
    if ((tid & 31) == 0) { ss[tid >> 5] = s; sq[tid >> 5] = q; }
    __syncthreads();
    float S = 0.f, Q = 0.f;
#pragma unroll
    for (int w = 0; w < 8; w++) { S += ss[w]; Q += sq[w]; }
    const float mu = S * (1.f / 1024.f);
    const float var = Q * (1.f / 1024.f) - mu * mu;
    const float inv = rsqrtf(var + 1e-5f);
    float4 g4 = *(const float4*)(gam + tid * 4);
    float4 b4 = *(const float4*)(bet + tid * 4);
    float4 r4;
    r4.x = (v.x - mu) * inv * g4.x + b4.x;
    r4.y = (v.y - mu) * inv * g4.y + b4.y;
    r4.z = (v.z - mu) * inv * g4.z + b4.z;
    r4.w = (v.w - mu) * inv * g4.w + b4.w;
    *(float4*)(o + (size_t)row * 1024 + tid * 4) = r4;
    if (SPLIT) {
        uint2 hw, lw;
        hw.x = packbf2(r4.x, r4.y, lw.x);
        hw.y = packbf2(r4.z, r4.w, lw.y);
        *(uint2*)(ohi + (size_t)row * 1024 + tid * 4) = hw;
        *(uint2*)(olo + (size_t)row * 1024 + tid * 4) = lw;
    }
}

// ---------------- gate: logits + per-gate softmax, /G folded in ----------------
__global__ __launch_bounds__(128) void gate_kernel(
    const float* __restrict__ h, const float* __restrict__ gW,
    const float* __restrict__ gb, float* __restrict__ coef)
{
    const int t = blockIdx.x, tid = threadIdx.x;
    float acc[16];
#pragma unroll
    for (int j = 0; j < 16; j++) acc[j] = 0.f;
    const float* hr = h + (size_t)t * 1024;
    for (int d = tid; d < 1024; d += 128) {
        float hv = hr[d];
#pragma unroll
        for (int g = 0; g < 2; g++)
#pragma unroll
            for (int e = 0; e < 8; e++)
                acc[g * 8 + e] += hv * gW[g * 8192 + d * 8 + e];
    }
    __shared__ float red[16][4];
#pragma unroll
    for (int j = 0; j < 16; j++) {
        float vv = acc[j];
        for (int off = 16; off; off >>= 1) vv += __shfl_xor_sync(0xffffffffu, vv, off);
        if ((tid & 31) == 0) red[j][tid >> 5] = vv;
    }
    __syncthreads();
    if (tid < 16) {
        float lg = red[tid][0] + red[tid][1] + red[tid][2] + red[tid][3] + gb[tid];
        float mx = lg;
        for (int off = 4; off; off >>= 1) mx = fmaxf(mx, __shfl_xor_sync(0xffffu, mx, off));
        float ex = __expf(lg - mx);
        float smv = ex;
        for (int off = 4; off; off >>= 1) smv += __shfl_xor_sync(0xffffu, smv, off);
        coef[(size_t)t * 16 + tid] = ex / smv * 0.5f;
    }
}

#define ATTN_SMEM (64 * (QS_LD + 64 + 64 + QS_LD) * 4)

extern "C" void kernel_launch(void* const* d_in, const int* in_sizes, int n_in,
                              void* d_out, int out_size)
{
    const float* input  = (const float*)d_in[0];
    const float* Wq     = (const float*)d_in[1];
    const float* bq     = (const float*)d_in[2];
    const float* Wk     = (const float*)d_in[3];
    const float* bk     = (const float*)d_in[4];
    const float* Wv     = (const float*)d_in[5];
    const float* bv     = (const float*)d_in[6];
    const float* Wo     = (const float*)d_in[7];
    const float* bo     = (const float*)d_in[8];
    const float* ln1_g  = (const float*)d_in[9];
    const float* ln1_b  = (const float*)d_in[10];
    const float* gate_W = (const float*)d_in[11];
    const float* gate_b = (const float*)d_in[12];
    const float* eW1    = (const float*)d_in[13];
    const float* eb1    = (const float*)d_in[14];
    const float* eW2    = (const float*)d_in[15];
    const float* eb2    = (const float*)d_in[16];
    const float* ln2_g  = (const float*)d_in[17];
    const float* ln2_b  = (const float*)d_in[18];
    float* out = (float*)d_out;

    float *q, *k, *v, *attn, *x1, *hbuf, *x2, *coef;
    __nv_bfloat16 *hhi, *hlo, *B1h, *B1l, *B2h, *B2l, *hidh, *hidl;
    cudaGetSymbolAddress((void**)&q,    g_q);
    cudaGetSymbolAddress((void**)&k,    g_k);
    cudaGetSymbolAddress((void**)&v,    g_v);
    cudaGetSymbolAddress((void**)&attn, g_attn);
    cudaGetSymbolAddress((void**)&x1,   g_x1);
    cudaGetSymbolAddress((void**)&hbuf, g_h);
    cudaGetSymbolAddress((void**)&x2,   g_x2);
    cudaGetSymbolAddress((void**)&coef, g_coef);
    cudaGetSymbolAddress((void**)&hhi,  g_hhi);
    cudaGetSymbolAddress((void**)&hlo,  g_hlo);
    cudaGetSymbolAddress((void**)&B1h,  g_B1h);
    cudaGetSymbolAddress((void**)&B1l,  g_B1l);
    cudaGetSymbolAddress((void**)&B2h,  g_B2h);
    cudaGetSymbolAddress((void**)&B2l,  g_B2l);
    cudaGetSymbolAddress((void**)&hidh, g_hidh);
    cudaGetSymbolAddress((void**)&hidl, g_hidl);

    cudaFuncSetAttribute(attn_kernel, cudaFuncAttributeMaxDynamicSharedMemorySize, ATTN_SMEM);
    cudaFuncSetAttribute(mma_gemm<2>, cudaFuncAttributeMaxDynamicSharedMemorySize, MMG_SMEM);
    cudaFuncSetAttribute(mma_gemm<3>, cudaFuncAttributeMaxDynamicSharedMemorySize, MMG_SMEM);

    dim3 blk(256);
    // weight transpose + split (independent of activations)
    transpose_split_kernel<<<dim3(32, 32, 16), dim3(32, 8)>>>(eW1, B1h, B1l, 0);
    transpose_split_kernel<<<dim3(32, 32, 16), dim3(32, 8)>>>(eW2, B2h, B2l, 1);
    // QKV projections (fp32)
    gemm_kernel<0><<<dim3(8, 32), blk>>>(input, 1024, Wq, bq, nullptr, q, 1024, 1024);
    gemm_kernel<0><<<dim3(8, 32), blk>>>(input, 1024, Wk, bk, nullptr, k, 1024, 1024);
    gemm_kernel<0><<<dim3(8, 32), blk>>>(input, 1024, Wv, bv, nullptr, v, 1024, 1024);
    // attention
    attn_kernel<<<dim3(32, 16, 2), blk, ATTN_SMEM>>>(q, k, v, attn);
    // O projection + residual, LN1 (+ bf16 split of h)
    gemm_kernel<1><<<dim3(8, 32), blk>>>(attn, 1024, Wo, bo, input, x1, 1024, 1024);
    ln_kernel<true><<<4096, blk>>>(x1, ln1_g, ln1_b, hbuf, hhi, hlo);
    // gates
    gate_kernel<<<4096, 128>>>(hbuf, gate_W, gate_b, coef);
    // MoE via mma.sync bf16 3-term split
    mma_gemm<2><<<dim3(128, 16), 512, MMG_SMEM>>>(hhi, hlo, 1024, B1h, B1l, 1024,
                                                  eb1, nullptr, coef, hidh, hidl, nullptr, 1024);
    mma_gemm<3><<<dim3(8, 16), 512, MMG_SMEM>>>(hidh, hidl, 16384, B2h, B2l, 16384,
                                                eb2, hbuf, coef, nullptr, nullptr, x2, 16384);
    // LN2 -> output
    ln_kernel<false><<<4096, blk>>>(x2, ln2_g, ln2_b, out, nullptr, nullptr);
}

// round 12
// speedup vs baseline: 1.6551x; 1.0844x over previous
#include <cuda_runtime.h>
#include <cuda_bf16.h>
#include <stdint.h>
#include <math.h>

// Problem constants
#define Bc   2
#define Sc   2048
#define Dc   1024
#define Tc   4096      // B*S tokens

// ---------------- device scratch (no cudaMalloc allowed) ----------------
__device__ float g_q   [4096*1024];
__device__ float g_k   [4096*1024];
__device__ float g_v   [4096*1024];
__device__ float g_attn[4096*1024];
__device__ float g_x1  [4096*1024];
__device__ float g_h   [4096*1024];
__device__ float g_x2  [4096*1024];
__device__ float g_coef[4096*16];
__device__ __nv_bfloat16 g_xhi [4096*1024];  // split of input / attn out
__device__ __nv_bfloat16 g_xlo [4096*1024];
__device__ __nv_bfloat16 g_Wth [4*1024*1024]; // Wq,Wk,Wv,Wo transposed hi
__device__ __nv_bfloat16 g_Wtl [4*1024*1024];
__device__ __nv_bfloat16 g_hhi [4096*1024];
__device__ __nv_bfloat16 g_hlo [4096*1024];
__device__ __nv_bfloat16 g_B1h [16777216];   // [16384 n][1024 k]
__device__ __nv_bfloat16 g_B1l [16777216];
__device__ __nv_bfloat16 g_B2h [16777216];   // [1024 d][16384 k]
__device__ __nv_bfloat16 g_B2l [16777216];
__device__ __nv_bfloat16 g_hidh[67108864];   // [4096][16384]
__device__ __nv_bfloat16 g_hidl[67108864];

// ======================= helpers =======================
__device__ __forceinline__ uint32_t smem_to_u32(const void* p) {
    uint32_t a;
    asm("{ .reg .u64 t; cvta.to.shared.u64 t, %1; cvt.u32.u64 %0, t; }" : "=r"(a) : "l"(p));
    return a;
}
__device__ __forceinline__ void cp_async16(uint32_t saddr, const void* gaddr) {
    asm volatile("cp.async.cg.shared.global [%0], [%1], 16;" :: "r"(saddr), "l"(gaddr));
}
#define CP_COMMIT() asm volatile("cp.async.commit_group;" ::: "memory")
#define CP_WAIT(n)  asm volatile("cp.async.wait_group %0;" :: "n"(n) : "memory")

__device__ __forceinline__ void ldsm_x4(uint32_t* r, uint32_t a) {
    asm volatile("ldmatrix.sync.aligned.m8n8.x4.shared.b16 {%0,%1,%2,%3}, [%4];"
                 : "=r"(r[0]), "=r"(r[1]), "=r"(r[2]), "=r"(r[3]) : "r"(a));
}
__device__ __forceinline__ void ldsm_x2(uint32_t* r, uint32_t a) {
    asm volatile("ldmatrix.sync.aligned.m8n8.x2.shared.b16 {%0,%1}, [%2];"
                 : "=r"(r[0]), "=r"(r[1]) : "r"(a));
}
__device__ __forceinline__ void mma16816(float* c, const uint32_t* a, const uint32_t* b) {
    asm volatile("mma.sync.aligned.m16n8k16.row.col.f32.bf16.bf16.f32 "
                 "{%0,%1,%2,%3}, {%4,%5,%6,%7}, {%8,%9}, {%0,%1,%2,%3};"
                 : "+f"(c[0]), "+f"(c[1]), "+f"(c[2]), "+f"(c[3])
                 : "r"(a[0]), "r"(a[1]), "r"(a[2]), "r"(a[3]), "r"(b[0]), "r"(b[1]));
}

__device__ __forceinline__ uint32_t packbf2(float a, float b, uint32_t& lo) {
    __nv_bfloat16 ha = __float2bfloat16_rn(a), hb = __float2bfloat16_rn(b);
    float la = a - __bfloat162float(ha), lb = b - __bfloat162float(hb);
    __nv_bfloat162 l2 = __halves2bfloat162(__float2bfloat16_rn(la), __float2bfloat16_rn(lb));
    lo = *(uint32_t*)&l2;
    __nv_bfloat162 h2 = __halves2bfloat162(ha, hb);
    return *(uint32_t*)&h2;
}

// ============ mma.sync GEMM: 256x128 CTA tile, bf16 3-term split ============
// MODE 0: C = A@B + bias                         -> fp32  (ldOut 1024)
// MODE 1: C = A@B + bias + res                   -> fp32  (ldOut 1024)
// MODE 2: hid = coef[t,e]*relu(A@B + b1)         -> bf16 hi/lo (ldOut 16384)
// MODE 3: x2  = A@B + sum_e coef*b2[e] + res     -> fp32  (ldOut 1024)
// A[row][k] hi/lo bf16, B[n][k] hi/lo bf16 (both K-major).
// smem: 2 chunk buffers of 61440B: Ah(256x80) Al Bh(128x80) Bl; bias_sm @122880
#define MMG_SMEM   131072
#define CHUNK_B    61440
template<int MODE>
__global__ __launch_bounds__(512, 1) void mma_gemm(
    const __nv_bfloat16* __restrict__ Ahi, const __nv_bfloat16* __restrict__ Alo, int lda,
    const __nv_bfloat16* __restrict__ Bhi, const __nv_bfloat16* __restrict__ Blo, int ldb,
    const float* __restrict__ bias, const float* __restrict__ res,
    const float* __restrict__ coef,
    __nv_bfloat16* __restrict__ Ohi, __nv_bfloat16* __restrict__ Olo,
    float* __restrict__ Of, int K)
{
    extern __shared__ char smem[];
    const int tid  = threadIdx.x;
    const int lane = tid & 31, wid = tid >> 5;
    const int wm = wid & 7, wn = wid >> 3;      // warp grid 8m x 2n, warp tile 32x64
    const int row0 = blockIdx.y * 256, col0 = blockIdx.x * 128;
    uint32_t sb = smem_to_u32(smem);

    float* bias_sm = (float*)(smem + 122880);
    if (MODE == 3) {
        for (int i = tid; i < 2048; i += 512)
            bias_sm[i] = bias[(i >> 7) * 1024 + col0 + (i & 127)];
    }

    float acc[2][8][4];
#pragma unroll
    for (int mi = 0; mi < 2; mi++)
#pragma unroll
        for (int ni = 0; ni < 8; ni++)
#pragma unroll
            for (int q = 0; q < 4; q++) acc[mi][ni][q] = 0.f;

    auto issue_chunk = [&](int c) {
        const int kb = c * 32;
        uint32_t bufu = sb + (c & 1) * CHUNK_B;
#pragma unroll
        for (int it = 0; it < 6; it++) {
            int idx = tid + it * 512;               // 0..3071
            const __nv_bfloat16* src;
            uint32_t dst;
            if (idx < 2048) {                       // A: 2 mats x 256 rows x 4 segs
                int m = idx >> 10, rem = idx & 1023, r = rem >> 2, s = rem & 3;
                src = (m ? Alo : Ahi) + (size_t)(row0 + r) * lda + kb + s * 8;
                dst = bufu + m * 20480 + r * 80 + s * 16;
            } else {                                // B: 2 mats x 128 rows x 4 segs
                int i2 = idx - 2048;
                int m = i2 >> 9, rem = i2 & 511, r = rem >> 2, s = rem & 3;
                src = (m ? Blo : Bhi) + (size_t)(col0 + r) * ldb + kb + s * 8;
                dst = bufu + 40960 + m * 10240 + r * 80 + s * 16;
            }
            cp_async16(dst, src);
        }
        CP_COMMIT();
    };

    const int NC = K / 32;
    issue_chunk(0);
    for (int c = 0; c < NC; c++) {
        if (c + 1 < NC) { issue_chunk(c + 1); CP_WAIT(1); }
        else            { CP_WAIT(0); }
        __syncthreads();
        uint32_t base = sb + (c & 1) * CHUNK_B;
        uint32_t aAh = base + (wm * 32 + (lane & 15)) * 80 + (lane >> 4) * 16;
#pragma unroll
        for (int kk = 0; kk < 2; kk++) {
            uint32_t ah[2][4], al[2][4];
            ldsm_x4(ah[0], aAh + kk * 32);
            ldsm_x4(ah[1], aAh + 16 * 80 + kk * 32);
            ldsm_x4(al[0], aAh + 20480 + kk * 32);
            ldsm_x4(al[1], aAh + 20480 + 16 * 80 + kk * 32);
#pragma unroll
            for (int g = 0; g < 2; g++) {
                uint32_t bh[4][2], bl[4][2];
#pragma unroll
                for (int j = 0; j < 4; j++) {
                    int ni = g * 4 + j;
                    uint32_t ab = base + 40960 + (wn * 64 + ni * 8 + (lane & 7)) * 80
                                  + ((lane >> 3) & 1) * 16 + kk * 32;
                    ldsm_x2(bh[j], ab);
                    ldsm_x2(bl[j], ab + 10240);
                }
                // grouped by term: acc reuse distance = 8 mmas (no RAW stall)
#pragma unroll
                for (int j = 0; j < 4; j++) {
                    mma16816(acc[0][g * 4 + j], ah[0], bh[j]);
                    mma16816(acc[1][g * 4 + j], ah[1], bh[j]);
                }
#pragma unroll
                for (int j = 0; j < 4; j++) {
                    mma16816(acc[0][g * 4 + j], ah[0], bl[j]);
                    mma16816(acc[1][g * 4 + j], ah[1], bl[j]);
                }
#pragma unroll
                for (int j = 0; j < 4; j++) {
                    mma16816(acc[0][g * 4 + j], al[0], bh[j]);
                    mma16816(acc[1][g * 4 + j], al[1], bh[j]);
                }
            }
        }
        __syncthreads();
    }

    if (MODE == 2) {
        const int e  = col0 >> 10;
        const int cb = col0 & 1023;
        int   rr[2][2];
        float cf[2][2];
#pragma unroll
        for (int mi = 0; mi < 2; mi++)
#pragma unroll
            for (int h = 0; h < 2; h++) {
                rr[mi][h] = row0 + wm * 32 + mi * 16 + (lane >> 2) + 8 * h;
                cf[mi][h] = coef[(size_t)rr[mi][h] * 16 + e];
            }
#pragma unroll
        for (int mi = 0; mi < 2; mi++)
#pragma unroll
        for (int ni = 0; ni < 8; ni++) {
            int cl = wn * 64 + ni * 8 + (lane & 3) * 2;
            float b0 = bias[e * 1024 + cb + cl];
            float b1 = bias[e * 1024 + cb + cl + 1];
#pragma unroll
            for (int h = 0; h < 2; h++) {
                float v0 = fmaxf(acc[mi][ni][2 * h + 0] + b0, 0.f) * cf[mi][h];
                float v1 = fmaxf(acc[mi][ni][2 * h + 1] + b1, 0.f) * cf[mi][h];
                uint32_t lo, hi = packbf2(v0, v1, lo);
                size_t o = (size_t)rr[mi][h] * 16384 + col0 + cl;
                *(uint32_t*)(Ohi + o) = hi;
                *(uint32_t*)(Olo + o) = lo;
            }
        }
    } else if (MODE == 3) {
#pragma unroll
        for (int mi = 0; mi < 2; mi++)
#pragma unroll
        for (int h = 0; h < 2; h++) {
            int r2 = row0 + wm * 32 + mi * 16 + (lane >> 2) + 8 * h;
            float cf16[16];
#pragma unroll
            for (int e2 = 0; e2 < 4; e2++)
                *(float4*)&cf16[e2 * 4] = *(const float4*)(coef + (size_t)r2 * 16 + e2 * 4);
#pragma unroll
            for (int ni = 0; ni < 8; ni++) {
                int cl = wn * 64 + ni * 8 + (lane & 3) * 2;
                float2 rv = *(const float2*)(res + (size_t)r2 * 1024 + col0 + cl);
                float v0 = acc[mi][ni][2 * h + 0] + rv.x;
                float v1 = acc[mi][ni][2 * h + 1] + rv.y;
#pragma unroll
                for (int e2 = 0; e2 < 16; e2++) {
                    v0 += cf16[e2] * bias_sm[e2 * 128 + cl];
                    v1 += cf16[e2] * bias_sm[e2 * 128 + cl + 1];
                }
                float2 ov; ov.x = v0; ov.y = v1;
                *(float2*)(Of + (size_t)r2 * 1024 + col0 + cl) = ov;
            }
        }
    } else {
#pragma unroll
        for (int mi = 0; mi < 2; mi++)
#pragma unroll
        for (int h = 0; h < 2; h++) {
            int r2 = row0 + wm * 32 + mi * 16 + (lane >> 2) + 8 * h;
#pragma unroll
            for (int ni = 0; ni < 8; ni++) {
                int cl = wn * 64 + ni * 8 + (lane & 3) * 2;
                float v0 = acc[mi][ni][2 * h + 0] + bias[col0 + cl];
                float v1 = acc[mi][ni][2 * h + 1] + bias[col0 + cl + 1];
                if (MODE == 1) {
                    float2 rv = *(const float2*)(res + (size_t)r2 * 1024 + col0 + cl);
                    v0 += rv.x; v1 += rv.y;
                }
                float2 ov; ov.x = v0; ov.y = v1;
                *(float2*)(Of + (size_t)r2 * 1024 + col0 + cl) = ov;
            }
        }
    }
}

// ---------- 1024x1024 transpose + hi/lo bf16 split (per expert / weight) ----------
__global__ __launch_bounds__(256) void transpose_split_kernel(
    const float* __restrict__ in, __nv_bfloat16* __restrict__ ohi,
    __nv_bfloat16* __restrict__ olo, int mode)
{
    __shared__ float tsm[32][33];
    const int e = blockIdx.z;
    const int kt = blockIdx.x, nt = blockIdx.y;
    const float* ip = in + ((size_t)e << 20);
    const int tx = threadIdx.x, ty = threadIdx.y;   // 32 x 8
    for (int yy = ty; yy < 32; yy += 8)
        tsm[yy][tx] = ip[(size_t)(kt * 32 + yy) * 1024 + nt * 32 + tx];
    __syncthreads();
    for (int yy = ty; yy < 32; yy += 8) {
        int n = nt * 32 + yy, k = kt * 32 + tx;
        float v = tsm[tx][yy];
        size_t o = (mode == 0) ? ((size_t)(e * 1024 + n) * 1024 + k)
                               : ((size_t)n * 16384 + e * 1024 + k);
        __nv_bfloat16 hi = __float2bfloat16_rn(v);
        ohi[o] = hi;
        olo[o] = __float2bfloat16_rn(v - __bfloat162float(hi));
    }
}

// ---------- elementwise fp32 -> bf16 hi/lo split ----------
__global__ __launch_bounds__(256) void split_kernel(
    const float* __restrict__ x, __nv_bfloat16* __restrict__ hi,
    __nv_bfloat16* __restrict__ lo)
{
    size_t i = ((size_t)blockIdx.x * 256 + threadIdx.x) * 4;
    float4 v = *(const float4*)(x + i);
    uint2 hw, lw;
    hw.x = packbf2(v.x, v.y, lw.x);
    hw.y = packbf2(v.z, v.w, lw.y);
    *(uint2*)(hi + i) = hw;
    *(uint2*)(lo + i) = lw;
}

// ---------------- flash attention, 64x64 tiles, causal ----------------
#define QS_LD 68
__global__ __launch_bounds__(256) void attn_kernel(
    const float* __restrict__ q, const float* __restrict__ k,
    const float* __restrict__ v, float* __restrict__ o)
{
    extern __shared__ float sm[];
    float* Qs = sm;
    float* Kt = sm + 64 * QS_LD;
    float* Vs = Kt + 64 * 64;
    float* Ps = Vs + 64 * 64;

    const int tid = threadIdx.x;
    const int qb = blockIdx.x, h = blockIdx.y, b = blockIdx.z;
    const size_t base = ((size_t)b * Sc) * Dc + h * 64;

#pragma unroll
    for (int it = 0; it < 4; it++) {
        int f = tid + it * 256;
        int rr = f >> 4, d4 = (f & 15) << 2;
        *(float4*)&Qs[rr * QS_LD + d4] =
            *(const float4*)(q + base + (size_t)(qb * 64 + rr) * Dc + d4);
    }

    const int r = tid >> 2, cg = tid & 3;
    const int qi = qb * 64 + r;
    float out[16];
#pragma unroll
    for (int j2 = 0; j2 < 16; j2++) out[j2] = 0.f;
    float mrun = -1e30f, lrun = 0.f;

    for (int kb = 0; kb <= qb; kb++) {
        __syncthreads();
#pragma unroll
        for (int it = 0; it < 4; it++) {
            int f = tid + it * 256;
            int rr = f >> 4, d4 = (f & 15) << 2;
            float4 kv = *(const float4*)(k + base + (size_t)(kb * 64 + rr) * Dc + d4);
            Kt[(d4 + 0) * 64 + rr] = kv.x; Kt[(d4 + 1) * 64 + rr] = kv.y;
            Kt[(d4 + 2) * 64 + rr] = kv.z; Kt[(d4 + 3) * 64 + rr] = kv.w;
            *(float4*)&Vs[rr * 64 + d4] =
                *(const float4*)(v + base + (size_t)(kb * 64 + rr) * Dc + d4);
        }
        __syncthreads();

        float s[16];
#pragma unroll
        for (int c = 0; c < 16; c++) s[c] = 0.f;
#pragma unroll 4
        for (int d = 0; d < 64; d++) {
            float qv = Qs[r * QS_LD + d];
            const float* kp = &Kt[d * 64 + cg * 16];
            float4 k0 = *(const float4*)(kp);
            float4 k1 = *(const float4*)(kp + 4);
            float4 k2 = *(const float4*)(kp + 8);
            float4 k3 = *(const float4*)(kp + 12);
            s[0] += qv * k0.x; s[1] += qv * k0.y; s[2] += qv * k0.z; s[3] += qv * k0.w;
            s[4] += qv * k1.x; s[5] += qv * k1.y; s[6] += qv * k1.z; s[7] += qv * k1.w;
            s[8] += qv * k2.x; s[9] += qv * k2.y; s[10]+= qv * k2.z; s[11]+= qv * k2.w;
            s[12]+= qv * k3.x; s[13]+= qv * k3.y; s[14]+= qv * k3.z; s[15]+= qv * k3.w;
        }

        float mloc = -1e30f;
#pragma unroll
        for (int c = 0; c < 16; c++) {
            float sv = s[c] * 0.125f;
            int kj = kb * 64 + cg * 16 + c;
            if (kj > qi) sv = -1e9f;
            s[c] = sv;
            mloc = fmaxf(mloc, sv);
        }
        mloc = fmaxf(mloc, __shfl_xor_sync(0xffffffffu, mloc, 1));
        mloc = fmaxf(mloc, __shfl_xor_sync(0xffffffffu, mloc, 2));
        const float mnew = fmaxf(mrun, mloc);
        const float alpha = __expf(mrun - mnew);
        float lloc = 0.f;
#pragma unroll
        for (int c = 0; c < 16; c++) { float p = __expf(s[c] - mnew); s[c] = p; lloc += p; }
        lloc += __shfl_xor_sync(0xffffffffu, lloc, 1);
        lloc += __shfl_xor_sync(0xffffffffu, lloc, 2);
        lrun = lrun * alpha + lloc;
        mrun = mnew;
#pragma unroll
        for (int j2 = 0; j2 < 16; j2++) out[j2] *= alpha;

#pragma unroll
        for (int c = 0; c < 16; c++) Ps[r * QS_LD + cg * 16 + c] = s[c];
        __syncwarp();

#pragma unroll 2
        for (int c = 0; c < 64; c++) {
            float p = Ps[r * QS_LD + c];
            const float* vp = &Vs[c * 64 + cg * 16];
            float4 v0 = *(const float4*)vp, v1 = *(const float4*)(vp + 4);
            float4 v2 = *(const float4*)(vp + 8), v3 = *(const float4*)(vp + 12);
            out[0] += p * v0.x; out[1] += p * v0.y; out[2] += p * v0.z; out[3] += p * v0.w;
            out[4] += p * v1.x; out[5] += p * v1.y; out[6] += p * v1.z; out[7] += p * v1.w;
            out[8] += p * v2.x; out[9] += p * v2.y; out[10]+= p * v2.z; out[11]+= p * v2.w;
            out[12]+= p * v3.x; out[13]+= p * v3.y; out[14]+= p * v3.z; out[15]+= p * v3.w;
        }
    }

    const float invl = 1.f / lrun;
#pragma unroll
    for (int j2 = 0; j2 < 16; j2++)
        o[base + (size_t)qi * Dc + cg * 16 + j2] = out[j2] * invl;
}

// ---------------- LayerNorm (optionally emits bf16 hi/lo split) ----------------
template<bool SPLIT>
__global__ __launch_bounds__(256) void ln_kernel(
    const float* __restrict__ x, const float* __restrict__ gam,
    const float* __restrict__ bet, float* __restrict__ o,
    __nv_bfloat16* __restrict__ ohi, __nv_bfloat16* __restrict__ olo)
{
    const int row = blockIdx.x, tid = threadIdx.x;
    const float4 v = *(const float4*)(x + (size_t)row * 1024 + tid * 4);
    float s = v.x + v.y + v.z + v.w;
    float q = v.x * v.x + v.y * v.y + v.z * v.z + v.w * v.w;
#pragma unroll
    for (int off = 16; off; off >>= 1) {
        s += __shfl_xor_sync(0xffffffffu, s, off);
        q += __shfl_xor_sync(0xffffffffu, q, off);
    }
    __shared__ float ss[8], sq[8];
    if ((tid & 31) == 0) { ss[tid >> 5] = s; sq[tid >> 5] = q; }
    __syncthreads();
    float S = 0.f, Q = 0.f;
#pragma unroll
    for (int w = 0; w < 8; w++) { S += ss[w]; Q += sq[w]; }
    const float mu = S * (1.f / 1024.f);
    const float var = Q * (1.f / 1024.f) - mu * mu;
    const float inv = rsqrtf(var + 1e-5f);
    float4 g4 = *(const float4*)(gam + tid * 4);
    float4 b4 = *(const float4*)(bet + tid * 4);
    float4 r4;
    r4.x = (v.x - mu) * inv * g4.x + b4.x;
    r4.y = (v.y - mu) * inv * g4.y + b4.y;
    r4.z = (v.z - mu) * inv * g4.z + b4.z;
    r4.w = (v.w - mu) * inv * g4.w + b4.w;
    *(float4*)(o + (size_t)row * 1024 + tid * 4) = r4;
    if (SPLIT) {
        uint2 hw, lw;
        hw.x = packbf2(r4.x, r4.y, lw.x);
        hw.y = packbf2(r4.z, r4.w, lw.y);
        *(uint2*)(ohi + (size_t)row * 1024 + tid * 4) = hw;
        *(uint2*)(olo + (size_t)row * 1024 + tid * 4) = lw;
    }
}

// ---------------- gate: logits + per-gate softmax, /G folded in ----------------
__global__ __launch_bounds__(128) void gate_kernel(
    const float* __restrict__ h, const float* __restrict__ gW,
    const float* __restrict__ gb, float* __restrict__ coef)
{
    const int t = blockIdx.x, tid = threadIdx.x;
    float acc[16];
#pragma unroll
    for (int j = 0; j < 16; j++) acc[j] = 0.f;
    const float* hr = h + (size_t)t * 1024;
    for (int d = tid; d < 1024; d += 128) {
        float hv = hr[d];
#pragma unroll
        for (int g = 0; g < 2; g++)
#pragma unroll
            for (int e = 0; e < 8; e++)
                acc[g * 8 + e] += hv * gW[g * 8192 + d * 8 + e];
    }
    __shared__ float red[16][4];
#pragma unroll
    for (int j = 0; j < 16; j++) {
        float vv = acc[j];
        for (int off = 16; off; off >>= 1) vv += __shfl_xor_sync(0xffffffffu, vv, off);
        if ((tid & 31) == 0) red[j][tid >> 5] = vv;
    }
    __syncthreads();
    if (tid < 16) {
        float lg = red[tid][0] + red[tid][1] + red[tid][2] + red[tid][3] + gb[tid];
        float mx = lg;
        for (int off = 4; off; off >>= 1) mx = fmaxf(mx, __shfl_xor_sync(0xffffu, mx, off));
        float ex = __expf(lg - mx);
        float smv = ex;
        for (int off = 4; off; off >>= 1) smv += __shfl_xor_sync(0xffffu, smv, off);
        coef[(size_t)t * 16 + tid] = ex / smv * 0.5f;
    }
}

#define ATTN_SMEM (64 * (QS_LD + 64 + 64 + QS_LD) * 4)

extern "C" void kernel_launch(void* const* d_in, const int* in_sizes, int n_in,
                              void* d_out, int out_size)
{
    const float* input  = (const float*)d_in[0];
    const float* Wq     = (const float*)d_in[1];
    const float* bq     = (const float*)d_in[2];
    const float* Wk     = (const float*)d_in[3];
    const float* bk     = (const float*)d_in[4];
    const float* Wv     = (const float*)d_in[5];
    const float* bv     = (const float*)d_in[6];
    const float* Wo     = (const float*)d_in[7];
    const float* bo     = (const float*)d_in[8];
    const float* ln1_g  = (const float*)d_in[9];
    const float* ln1_b  = (const float*)d_in[10];
    const float* gate_W = (const float*)d_in[11];
    const float* gate_b = (const float*)d_in[12];
    const float* eW1    = (const float*)d_in[13];
    const float* eb1    = (const float*)d_in[14];
    const float* eW2    = (const float*)d_in[15];
    const float* eb2    = (const float*)d_in[16];
    const float* ln2_g  = (const float*)d_in[17];
    const float* ln2_b  = (const float*)d_in[18];
    float* out = (float*)d_out;

    float *q, *k, *v, *attn, *x1, *hbuf, *x2, *coef;
    __nv_bfloat16 *xhi, *xlo, *Wth, *Wtl, *hhi, *hlo, *B1h, *B1l, *B2h, *B2l, *hidh, *hidl;
    cudaGetSymbolAddress((void**)&q,    g_q);
    cudaGetSymbolAddress((void**)&k,    g_k);
    cudaGetSymbolAddress((void**)&v,    g_v);
    cudaGetSymbolAddress((void**)&attn, g_attn);
    cudaGetSymbolAddress((void**)&x1,   g_x1);
    cudaGetSymbolAddress((void**)&hbuf, g_h);
    cudaGetSymbolAddress((void**)&x2,   g_x2);
    cudaGetSymbolAddress((void**)&coef, g_coef);
    cudaGetSymbolAddress((void**)&xhi,  g_xhi);
    cudaGetSymbolAddress((void**)&xlo,  g_xlo);
    cudaGetSymbolAddress((void**)&Wth,  g_Wth);
    cudaGetSymbolAddress((void**)&Wtl,  g_Wtl);
    cudaGetSymbolAddress((void**)&hhi,  g_hhi);
    cudaGetSymbolAddress((void**)&hlo,  g_hlo);
    cudaGetSymbolAddress((void**)&B1h,  g_B1h);
    cudaGetSymbolAddress((void**)&B1l,  g_B1l);
    cudaGetSymbolAddress((void**)&B2h,  g_B2h);
    cudaGetSymbolAddress((void**)&B2l,  g_B2l);
    cudaGetSymbolAddress((void**)&hidh, g_hidh);
    cudaGetSymbolAddress((void**)&hidl, g_hidl);

    cudaFuncSetAttribute(attn_kernel, cudaFuncAttributeMaxDynamicSharedMemorySize, ATTN_SMEM);
    cudaFuncSetAttribute(mma_gemm<0>, cudaFuncAttributeMaxDynamicSharedMemorySize, MMG_SMEM);
    cudaFuncSetAttribute(mma_gemm<1>, cudaFuncAttributeMaxDynamicSharedMemorySize, MMG_SMEM);
    cudaFuncSetAttribute(mma_gemm<2>, cudaFuncAttributeMaxDynamicSharedMemorySize, MMG_SMEM);
    cudaFuncSetAttribute(mma_gemm<3>, cudaFuncAttributeMaxDynamicSharedMemorySize, MMG_SMEM);

    const int M1 = 1024 * 1024;
    dim3 t32x8(32, 8);
    // weight prep (independent of activations)
    transpose_split_kernel<<<dim3(32, 32, 16), t32x8>>>(eW1, B1h, B1l, 0);
    transpose_split_kernel<<<dim3(32, 32, 16), t32x8>>>(eW2, B2h, B2l, 1);
    transpose_split_kernel<<<dim3(32, 32, 1), t32x8>>>(Wq, Wth + 0 * M1, Wtl + 0 * M1, 0);
    transpose_split_kernel<<<dim3(32, 32, 1), t32x8>>>(Wk, Wth + 1 * M1, Wtl + 1 * M1, 0);
    transpose_split_kernel<<<dim3(32, 32, 1), t32x8>>>(Wv, Wth + 2 * M1, Wtl + 2 * M1, 0);
    transpose_split_kernel<<<dim3(32, 32, 1), t32x8>>>(Wo, Wth + 3 * M1, Wtl + 3 * M1, 0);
    // split input, QKV projections on tensor path
    split_kernel<<<4096, 256>>>(input, xhi, xlo);
    mma_gemm<0><<<dim3(8, 16), 512, MMG_SMEM>>>(xhi, xlo, 1024, Wth + 0 * M1, Wtl + 0 * M1, 1024,
                                                bq, nullptr, nullptr, nullptr, nullptr, q, 1024);
    mma_gemm<0><<<dim3(8, 16), 512, MMG_SMEM>>>(xhi, xlo, 1024, Wth + 1 * M1, Wtl + 1 * M1, 1024,
                                                bk, nullptr, nullptr, nullptr, nullptr, k, 1024);
    mma_gemm<0><<<dim3(8, 16), 512, MMG_SMEM>>>(xhi, xlo, 1024, Wth + 2 * M1, Wtl + 2 * M1, 1024,
                                                bv, nullptr, nullptr, nullptr, nullptr, v, 1024);
    // attention
    attn_kernel<<<dim3(32, 16, 2), 256, ATTN_SMEM>>>(q, k, v, attn);
    // O projection + residual on tensor path (reuse xhi/xlo for attn split)
    split_kernel<<<4096, 256>>>(attn, xhi, xlo);
    mma_gemm<1><<<dim3(8, 16), 512, MMG_SMEM>>>(xhi, xlo, 1024, Wth + 3 * M1, Wtl + 3 * M1, 1024,
                                                bo, input, nullptr, nullptr, nullptr, x1, 1024);
    // LN1 (+ bf16 split of h), gates
    ln_kernel<true><<<4096, 256>>>(x1, ln1_g, ln1_b, hbuf, hhi, hlo);
    gate_kernel<<<4096, 128>>>(hbuf, gate_W, gate_b, coef);
    // MoE via mma.sync bf16 3-term split
    mma_gemm<2><<<dim3(128, 16), 512, MMG_SMEM>>>(hhi, hlo, 1024, B1h, B1l, 1024,
                                                  eb1, nullptr, coef, hidh, hidl, nullptr, 1024);
    mma_gemm<3><<<dim3(8, 16), 512, MMG_SMEM>>>(hidh, hidl, 16384, B2h, B2l, 16384,
                                                eb2, hbuf, coef, nullptr, nullptr, x2, 16384);
    // LN2 -> output
    ln_kernel<false><<<4096, 256>>>(x2, ln2_g, ln2_b, out, nullptr, nullptr);
}

// round 13
// speedup vs baseline: 2.0299x; 1.2265x over previous
#include <cuda_runtime.h>
#include <cuda_fp16.h>
#include <stdint.h>
#include <math.h>

// Problem constants
#define Bc   2
#define Sc   2048
#define Dc   1024
#define Tc   4096      // B*S tokens

// ---------------- device scratch (no cudaMalloc allowed) ----------------
__device__ float g_q   [4096*1024];
__device__ float g_k   [4096*1024];
__device__ float g_v   [4096*1024];
__device__ float g_attn[4096*1024];
__device__ float g_x1  [4096*1024];
__device__ float g_h   [4096*1024];
__device__ float g_x2  [4096*1024];
__device__ float g_coef[4096*16];
__device__ __half g_xhi [4096*1024];   // split of input / attn out
__device__ __half g_xlo [4096*1024];
__device__ __half g_Wth [4*1024*1024]; // Wq,Wk,Wv,Wo transposed (fp16)
__device__ __half g_hhi [4096*1024];
__device__ __half g_hlo [4096*1024];
__device__ __half g_B1h [16777216];    // [16384 n][1024 k] fp16
__device__ __half g_B2h [16777216];    // [1024 d][16384 k] fp16
__device__ __half g_hidh[67108864];    // [4096][16384]
__device__ __half g_hidl[67108864];

// ======================= helpers =======================
__device__ __forceinline__ uint32_t smem_to_u32(const void* p) {
    uint32_t a;
    asm("{ .reg .u64 t; cvta.to.shared.u64 t, %1; cvt.u32.u64 %0, t; }" : "=r"(a) : "l"(p));
    return a;
}
__device__ __forceinline__ void cp_async16(uint32_t saddr, const void* gaddr) {
    asm volatile("cp.async.cg.shared.global [%0], [%1], 16;" :: "r"(saddr), "l"(gaddr));
}
#define CP_COMMIT() asm volatile("cp.async.commit_group;" ::: "memory")
#define CP_WAIT(n)  asm volatile("cp.async.wait_group %0;" :: "n"(n) : "memory")

__device__ __forceinline__ void ldsm_x4(uint32_t* r, uint32_t a) {
    asm volatile("ldmatrix.sync.aligned.m8n8.x4.shared.b16 {%0,%1,%2,%3}, [%4];"
                 : "=r"(r[0]), "=r"(r[1]), "=r"(r[2]), "=r"(r[3]) : "r"(a));
}
__device__ __forceinline__ void ldsm_x2(uint32_t* r, uint32_t a) {
    asm volatile("ldmatrix.sync.aligned.m8n8.x2.shared.b16 {%0,%1}, [%2];"
                 : "=r"(r[0]), "=r"(r[1]) : "r"(a));
}
__device__ __forceinline__ void mma16816(float* c, const uint32_t* a, const uint32_t* b) {
    asm volatile("mma.sync.aligned.m16n8k16.row.col.f32.f16.f16.f32 "
                 "{%0,%1,%2,%3}, {%4,%5,%6,%7}, {%8,%9}, {%0,%1,%2,%3};"
                 : "+f"(c[0]), "+f"(c[1]), "+f"(c[2]), "+f"(c[3])
                 : "r"(a[0]), "r"(a[1]), "r"(a[2]), "r"(a[3]), "r"(b[0]), "r"(b[1]));
}

__device__ __forceinline__ uint32_t packhf2(float a, float b, uint32_t& lo) {
    __half ha = __float2half_rn(a), hb = __float2half_rn(b);
    float la = a - __half2float(ha), lb = b - __half2float(hb);
    __half2 l2 = __halves2half2(__float2half_rn(la), __float2half_rn(lb));
    lo = *(uint32_t*)&l2;
    __half2 h2 = __halves2half2(ha, hb);
    return *(uint32_t*)&h2;
}

// ============ mma.sync GEMM: 256x128 CTA tile, fp16 2-term split ============
// A[row][k] hi/lo fp16 pair; B[n][k] single fp16 (K-major).
// MODE 0: C = A@B + bias                         -> fp32  (ldOut 1024)
// MODE 1: C = A@B + bias + res                   -> fp32  (ldOut 1024)
// MODE 2: hid = coef[t,e]*relu(A@B + b1)         -> fp16 hi/lo (ldOut 16384)
// MODE 3: x2  = A@B + sum_e coef*b2[e] + res     -> fp32  (ldOut 1024)
// smem: 2 chunk buffers of 51200B: Ah(256x80) Al(256x80) B(128x80); bias_sm @102400
#define MMG_SMEM   110592
#define CHUNK_B    51200
template<int MODE>
__global__ __launch_bounds__(512, 1) void mma_gemm(
    const __half* __restrict__ Ahi, const __half* __restrict__ Alo, int lda,
    const __half* __restrict__ Bh, int ldb,
    const float* __restrict__ bias, const float* __restrict__ res,
    const float* __restrict__ coef,
    __half* __restrict__ Ohi, __half* __restrict__ Olo,
    float* __restrict__ Of, int K)
{
    extern __shared__ char smem[];
    const int tid  = threadIdx.x;
    const int lane = tid & 31, wid = tid >> 5;
    const int wm = wid & 7, wn = wid >> 3;      // warp grid 8m x 2n, warp tile 32x64
    const int row0 = blockIdx.y * 256, col0 = blockIdx.x * 128;
    uint32_t sb = smem_to_u32(smem);

    float* bias_sm = (float*)(smem + 102400);
    if (MODE == 3) {
        for (int i = tid; i < 2048; i += 512)
            bias_sm[i] = bias[(i >> 7) * 1024 + col0 + (i & 127)];
    }

    float acc[2][8][4];
#pragma unroll
    for (int mi = 0; mi < 2; mi++)
#pragma unroll
        for (int ni = 0; ni < 8; ni++)
#pragma unroll
            for (int q = 0; q < 4; q++) acc[mi][ni][q] = 0.f;

    auto issue_chunk = [&](int c) {
        const int kb = c * 32;
        uint32_t bufu = sb + (c & 1) * CHUNK_B;
#pragma unroll
        for (int it = 0; it < 5; it++) {
            int idx = tid + it * 512;               // 0..2559
            const __half* src;
            uint32_t dst;
            if (idx < 2048) {                       // A: 2 mats x 256 rows x 4 segs
                int m = idx >> 10, rem = idx & 1023, r = rem >> 2, s = rem & 3;
                src = (m ? Alo : Ahi) + (size_t)(row0 + r) * lda + kb + s * 8;
                dst = bufu + m * 20480 + r * 80 + s * 16;
            } else {                                // B: 128 rows x 4 segs
                int i2 = idx - 2048;
                int r = i2 >> 2, s = i2 & 3;
                src = Bh + (size_t)(col0 + r) * ldb + kb + s * 8;
                dst = bufu + 40960 + r * 80 + s * 16;
            }
            cp_async16(dst, src);
        }
        CP_COMMIT();
    };

    const int NC = K / 32;
    issue_chunk(0);
    for (int c = 0; c < NC; c++) {
        CP_WAIT(0);
        __syncthreads();
        if (c + 1 < NC) issue_chunk(c + 1);
        uint32_t base = sb + (c & 1) * CHUNK_B;
        uint32_t aAh = base + (wm * 32 + (lane & 15)) * 80 + (lane >> 4) * 16;
#pragma unroll
        for (int kk = 0; kk < 2; kk++) {
            uint32_t ah[2][4], al[2][4];
            ldsm_x4(ah[0], aAh + kk * 32);
            ldsm_x4(ah[1], aAh + 16 * 80 + kk * 32);
            ldsm_x4(al[0], aAh + 20480 + kk * 32);
            ldsm_x4(al[1], aAh + 20480 + 16 * 80 + kk * 32);
#pragma unroll
            for (int g = 0; g < 2; g++) {
                uint32_t bf[4][2];
#pragma unroll
                for (int j = 0; j < 4; j++) {
                    int ni = g * 4 + j;
                    uint32_t ab = base + 40960 + (wn * 64 + ni * 8 + (lane & 7)) * 80
                                  + ((lane >> 3) & 1) * 16 + kk * 32;
                    ldsm_x2(bf[j], ab);
                }
                // grouped by term: acc reuse distance = 8 mmas
#pragma unroll
                for (int j = 0; j < 4; j++) {
                    mma16816(acc[0][g * 4 + j], ah[0], bf[j]);
                    mma16816(acc[1][g * 4 + j], ah[1], bf[j]);
                }
#pragma unroll
                for (int j = 0; j < 4; j++) {
                    mma16816(acc[0][g * 4 + j], al[0], bf[j]);
                    mma16816(acc[1][g * 4 + j], al[1], bf[j]);
                }
            }
        }
    }

    if (MODE == 2) {
        const int e  = col0 >> 10;
        const int cb = col0 & 1023;
        int   rr[2][2];
        float cf[2][2];
#pragma unroll
        for (int mi = 0; mi < 2; mi++)
#pragma unroll
            for (int h = 0; h < 2; h++) {
                rr[mi][h] = row0 + wm * 32 + mi * 16 + (lane >> 2) + 8 * h;
                cf[mi][h] = coef[(size_t)rr[mi][h] * 16 + e];
            }
#pragma unroll
        for (int mi = 0; mi < 2; mi++)
#pragma unroll
        for (int ni = 0; ni < 8; ni++) {
            int cl = wn * 64 + ni * 8 + (lane & 3) * 2;
            float b0 = bias[e * 1024 + cb + cl];
            float b1 = bias[e * 1024 + cb + cl + 1];
#pragma unroll
            for (int h = 0; h < 2; h++) {
                float v0 = fmaxf(acc[mi][ni][2 * h + 0] + b0, 0.f) * cf[mi][h];
                float v1 = fmaxf(acc[mi][ni][2 * h + 1] + b1, 0.f) * cf[mi][h];
                uint32_t lo, hi = packhf2(v0, v1, lo);
                size_t o = (size_t)rr[mi][h] * 16384 + col0 + cl;
                *(uint32_t*)(Ohi + o) = hi;
                *(uint32_t*)(Olo + o) = lo;
            }
        }
    } else if (MODE == 3) {
#pragma unroll
        for (int mi = 0; mi < 2; mi++)
#pragma unroll
        for (int h = 0; h < 2; h++) {
            int r2 = row0 + wm * 32 + mi * 16 + (lane >> 2) + 8 * h;
            float cf16[16];
#pragma unroll
            for (int e2 = 0; e2 < 4; e2++)
                *(float4*)&cf16[e2 * 4] = *(const float4*)(coef + (size_t)r2 * 16 + e2 * 4);
#pragma unroll
            for (int ni = 0; ni < 8; ni++) {
                int cl = wn * 64 + ni * 8 + (lane & 3) * 2;
                float2 rv = *(const float2*)(res + (size_t)r2 * 1024 + col0 + cl);
                float v0 = acc[mi][ni][2 * h + 0] + rv.x;
                float v1 = acc[mi][ni][2 * h + 1] + rv.y;
#pragma unroll
                for (int e2 = 0; e2 < 16; e2++) {
                    v0 += cf16[e2] * bias_sm[e2 * 128 + cl];
                    v1 += cf16[e2] * bias_sm[e2 * 128 + cl + 1];
                }
                float2 ov; ov.x = v0; ov.y = v1;
                *(float2*)(Of + (size_t)r2 * 1024 + col0 + cl) = ov;
            }
        }
    } else {
#pragma unroll
        for (int mi = 0; mi < 2; mi++)
#pragma unroll
        for (int h = 0; h < 2; h++) {
            int r2 = row0 + wm * 32 + mi * 16 + (lane >> 2) + 8 * h;
#pragma unroll
            for (int ni = 0; ni < 8; ni++) {
                int cl = wn * 64 + ni * 8 + (lane & 3) * 2;
                float v0 = acc[mi][ni][2 * h + 0] + bias[col0 + cl];
                float v1 = acc[mi][ni][2 * h + 1] + bias[col0 + cl + 1];
                if (MODE == 1) {
                    float2 rv = *(const float2*)(res + (size_t)r2 * 1024 + col0 + cl);
                    v0 += rv.x; v1 += rv.y;
                }
                float2 ov; ov.x = v0; ov.y = v1;
                *(float2*)(Of + (size_t)r2 * 1024 + col0 + cl) = ov;
            }
        }
    }
}

// ---------- 1024x1024 transpose + fp16 convert (per expert / weight) ----------
__global__ __launch_bounds__(256) void transpose_split_kernel(
    const float* __restrict__ in, __half* __restrict__ ohi, int mode)
{
    __shared__ float tsm[32][33];
    const int e = blockIdx.z;
    const int kt = blockIdx.x, nt = blockIdx.y;
    const float* ip = in + ((size_t)e << 20);
    const int tx = threadIdx.x, ty = threadIdx.y;   // 32 x 8
    for (int yy = ty; yy < 32; yy += 8)
        tsm[yy][tx] = ip[(size_t)(kt * 32 + yy) * 1024 + nt * 32 + tx];
    __syncthreads();
    for (int yy = ty; yy < 32; yy += 8) {
        int n = nt * 32 + yy, k = kt * 32 + tx;
        float v = tsm[tx][yy];
        size_t o = (mode == 0) ? ((size_t)(e * 1024 + n) * 1024 + k)
                               : ((size_t)n * 16384 + e * 1024 + k);
        ohi[o] = __float2half_rn(v);
    }
}

// ---------- elementwise fp32 -> fp16 hi/lo split ----------
__global__ __launch_bounds__(256) void split_kernel(
    const float* __restrict__ x, __half* __restrict__ hi, __half* __restrict__ lo)
{
    size_t i = ((size_t)blockIdx.x * 256 + threadIdx.x) * 4;
    float4 v = *(const float4*)(x + i);
    uint2 hw, lw;
    hw.x = packhf2(v.x, v.y, lw.x);
    hw.y = packhf2(v.z, v.w, lw.y);
    *(uint2*)(hi + i) = hw;
    *(uint2*)(lo + i) = lw;
}

// ---------------- flash attention, 64x64 tiles, causal ----------------
#define QS_LD 68
__global__ __launch_bounds__(256) void attn_kernel(
    const float* __restrict__ q, const float* __restrict__ k,
    const float* __restrict__ v, float* __restrict__ o)
{
    extern __shared__ float sm[];
    float* Qs = sm;
    float* Kt = sm + 64 * QS_LD;
    float* Vs = Kt + 64 * 64;
    float* Ps = Vs + 64 * 64;

    const int tid = threadIdx.x;
    const int qb = blockIdx.x, h = blockIdx.y, b = blockIdx.z;
    const size_t base = ((size_t)b * Sc) * Dc + h * 64;

#pragma unroll
    for (int it = 0; it < 4; it++) {
        int f = tid + it * 256;
        int rr = f >> 4, d4 = (f & 15) << 2;
        *(float4*)&Qs[rr * QS_LD + d4] =
            *(const float4*)(q + base + (size_t)(qb * 64 + rr) * Dc + d4);
    }

    const int r = tid >> 2, cg = tid & 3;
    const int qi = qb * 64 + r;
    float out[16];
#pragma unroll
    for (int j2 = 0; j2 < 16; j2++) out[j2] = 0.f;
    float mrun = -1e30f, lrun = 0.f;

    for (int kb = 0; kb <= qb; kb++) {
        __syncthreads();
#pragma unroll
        for (int it = 0; it < 4; it++) {
            int f = tid + it * 256;
            int rr = f >> 4, d4 = (f & 15) << 2;
            float4 kv = *(const float4*)(k + base + (size_t)(kb * 64 + rr) * Dc + d4);
            Kt[(d4 + 0) * 64 + rr] = kv.x; Kt[(d4 + 1) * 64 + rr] = kv.y;
            Kt[(d4 + 2) * 64 + rr] = kv.z; Kt[(d4 + 3) * 64 + rr] = kv.w;
            *(float4*)&Vs[rr * 64 + d4] =
                *(const float4*)(v + base + (size_t)(kb * 64 + rr) * Dc + d4);
        }
        __syncthreads();

        float s[16];
#pragma unroll
        for (int c = 0; c < 16; c++) s[c] = 0.f;
#pragma unroll 4
        for (int d = 0; d < 64; d++) {
            float qv = Qs[r * QS_LD + d];
            const float* kp = &Kt[d * 64 + cg * 16];
            float4 k0 = *(const float4*)(kp);
            float4 k1 = *(const float4*)(kp + 4);
            float4 k2 = *(const float4*)(kp + 8);
            float4 k3 = *(const float4*)(kp + 12);
            s[0] += qv * k0.x; s[1] += qv * k0.y; s[2] += qv * k0.z; s[3] += qv * k0.w;
            s[4] += qv * k1.x; s[5] += qv * k1.y; s[6] += qv * k1.z; s[7] += qv * k1.w;
            s[8] += qv * k2.x; s[9] += qv * k2.y; s[10]+= qv * k2.z; s[11]+= qv * k2.w;
            s[12]+= qv * k3.x; s[13]+= qv * k3.y; s[14]+= qv * k3.z; s[15]+= qv * k3.w;
        }

        float mloc = -1e30f;
#pragma unroll
        for (int c = 0; c < 16; c++) {
            float sv = s[c] * 0.125f;
            int kj = kb * 64 + cg * 16 + c;
            if (kj > qi) sv = -1e9f;
            s[c] = sv;
            mloc = fmaxf(mloc, sv);
        }
        mloc = fmaxf(mloc, __shfl_xor_sync(0xffffffffu, mloc, 1));
        mloc = fmaxf(mloc, __shfl_xor_sync(0xffffffffu, mloc, 2));
        const float mnew = fmaxf(mrun, mloc);
        const float alpha = __expf(mrun - mnew);
        float lloc = 0.f;
#pragma unroll
        for (int c = 0; c < 16; c++) { float p = __expf(s[c] - mnew); s[c] = p; lloc += p; }
        lloc += __shfl_xor_sync(0xffffffffu, lloc, 1);
        lloc += __shfl_xor_sync(0xffffffffu, lloc, 2);
        lrun = lrun * alpha + lloc;
        mrun = mnew;
#pragma unroll
        for (int j2 = 0; j2 < 16; j2++) out[j2] *= alpha;

#pragma unroll
        for (int c = 0; c < 16; c++) Ps[r * QS_LD + cg * 16 + c] = s[c];
        __syncwarp();

#pragma unroll 2
        for (int c = 0; c < 64; c++) {
            float p = Ps[r * QS_LD + c];
            const float* vp = &Vs[c * 64 + cg * 16];
            float4 v0 = *(const float4*)vp, v1 = *(const float4*)(vp + 4);
            float4 v2 = *(const float4*)(vp + 8), v3 = *(const float4*)(vp + 12);
            out[0] += p * v0.x; out[1] += p * v0.y; out[2] += p * v0.z; out[3] += p * v0.w;
            out[4] += p * v1.x; out[5] += p * v1.y; out[6] += p * v1.z; out[7] += p * v1.w;
            out[8] += p * v2.x; out[9] += p * v2.y; out[10]+= p * v2.z; out[11]+= p * v2.w;
            out[12]+= p * v3.x; out[13]+= p * v3.y; out[14]+= p * v3.z; out[15]+= p * v3.w;
        }
    }

    const float invl = 1.f / lrun;
#pragma unroll
    for (int j2 = 0; j2 < 16; j2++)
        o[base + (size_t)qi * Dc + cg * 16 + j2] = out[j2] * invl;
}

// ---------------- LayerNorm (optionally emits fp16 hi/lo split) ----------------
template<bool SPLIT>
__global__ __launch_bounds__(256) void ln_kernel(
    const float* __restrict__ x, const float* __restrict__ gam,
    const float* __restrict__ bet, float* __restrict__ o,
    __half* __restrict__ ohi, __half* __restrict__ olo)
{
    const int row = blockIdx.x, tid = threadIdx.x;
    const float4 v = *(const float4*)(x + (size_t)row * 1024 + tid * 4);
    float s = v.x + v.y + v.z + v.w;
    float q = v.x * v.x + v.y * v.y + v.z * v.z + v.w * v.w;
#pragma unroll
    for (int off = 16; off; off >>= 1) {
        s += __shfl_xor_sync(0xffffffffu, s, off);
        q += __shfl_xor_sync(0xffffffffu, q, off);
    }
    __shared__ float ss[8], sq[8];
    if ((tid & 31) == 0) { ss[tid >> 5] = s; sq[tid >> 5] = q; }
    __syncthreads();
    float S = 0.f, Q = 0.f;
#pragma unroll
    for (int w = 0; w < 8; w++) { S += ss[w]; Q += sq[w]; }
    const float mu = S * (1.f / 1024.f);
    const float var = Q * (1.f / 1024.f) - mu * mu;
    const float inv = rsqrtf(var + 1e-5f);
    float4 g4 = *(const float4*)(gam + tid * 4);
    float4 b4 = *(const float4*)(bet + tid * 4);
    float4 r4;
    r4.x = (v.x - mu) * inv * g4.x + b4.x;
    r4.y = (v.y - mu) * inv * g4.y + b4.y;
    r4.z = (v.z - mu) * inv * g4.z + b4.z;
    r4.w = (v.w - mu) * inv * g4.w + b4.w;
    *(float4*)(o + (size_t)row * 1024 + tid * 4) = r4;
    if (SPLIT) {
        uint2 hw, lw;
        hw.x = packhf2(r4.x, r4.y, lw.x);
        hw.y = packhf2(r4.z, r4.w, lw.y);
        *(uint2*)(ohi + (size_t)row * 1024 + tid * 4) = hw;
        *(uint2*)(olo + (size_t)row * 1024 + tid * 4) = lw;
    }
}

// ---------------- gate: logits + per-gate softmax, /G folded in ----------------
__global__ __launch_bounds__(128) void gate_kernel(
    const float* __restrict__ h, const float* __restrict__ gW,
    const float* __restrict__ gb, float* __restrict__ coef)
{
    const int t = blockIdx.x, tid = threadIdx.x;
    float acc[16];
#pragma unroll
    for (int j = 0; j < 16; j++) acc[j] = 0.f;
    const float* hr = h + (size_t)t * 1024;
    for (int d = tid; d < 1024; d += 128) {
        float hv = hr[d];
#pragma unroll
        for (int g = 0; g < 2; g++)
#pragma unroll
            for (int e = 0; e < 8; e++)
                acc[g * 8 + e] += hv * gW[g * 8192 + d * 8 + e];
    }
    __shared__ float red[16][4];
#pragma unroll
    for (int j = 0; j < 16; j++) {
        float vv = acc[j];
        for (int off = 16; off; off >>= 1) vv += __shfl_xor_sync(0xffffffffu, vv, off);
        if ((tid & 31) == 0) red[j][tid >> 5] = vv;
    }
    __syncthreads();
    if (tid < 16) {
        float lg = red[tid][0] + red[tid][1] + red[tid][2] + red[tid][3] + gb[tid];
        float mx = lg;
        for (int off = 4; off; off >>= 1) mx = fmaxf(mx, __shfl_xor_sync(0xffffu, mx, off));
        float ex = __expf(lg - mx);
        float smv = ex;
        for (int off = 4; off; off >>= 1) smv += __shfl_xor_sync(0xffffu, smv, off);
        coef[(size_t)t * 16 + tid] = ex / smv * 0.5f;
    }
}

#define ATTN_SMEM (64 * (QS_LD + 64 + 64 + QS_LD) * 4)

extern "C" void kernel_launch(void* const* d_in, const int* in_sizes, int n_in,
                              void* d_out, int out_size)
{
    const float* input  = (const float*)d_in[0];
    const float* Wq     = (const float*)d_in[1];
    const float* bq     = (const float*)d_in[2];
    const float* Wk     = (const float*)d_in[3];
    const float* bk     = (const float*)d_in[4];
    const float* Wv     = (const float*)d_in[5];
    const float* bv     = (const float*)d_in[6];
    const float* Wo     = (const float*)d_in[7];
    const float* bo     = (const float*)d_in[8];
    const float* ln1_g  = (const float*)d_in[9];
    const float* ln1_b  = (const float*)d_in[10];
    const float* gate_W = (const float*)d_in[11];
    const float* gate_b = (const float*)d_in[12];
    const float* eW1    = (const float*)d_in[13];
    const float* eb1    = (const float*)d_in[14];
    const float* eW2    = (const float*)d_in[15];
    const float* eb2    = (const float*)d_in[16];
    const float* ln2_g  = (const float*)d_in[17];
    const float* ln2_b  = (const float*)d_in[18];
    float* out = (float*)d_out;

    float *q, *k, *v, *attn, *x1, *hbuf, *x2, *coef;
    __half *xhi, *xlo, *Wth, *hhi, *hlo, *B1h, *B2h, *hidh, *hidl;
    cudaGetSymbolAddress((void**)&q,    g_q);
    cudaGetSymbolAddress((void**)&k,    g_k);
    cudaGetSymbolAddress((void**)&v,    g_v);
    cudaGetSymbolAddress((void**)&attn, g_attn);
    cudaGetSymbolAddress((void**)&x1,   g_x1);
    cudaGetSymbolAddress((void**)&hbuf, g_h);
    cudaGetSymbolAddress((void**)&x2,   g_x2);
    cudaGetSymbolAddress((void**)&coef, g_coef);
    cudaGetSymbolAddress((void**)&xhi,  g_xhi);
    cudaGetSymbolAddress((void**)&xlo,  g_xlo);
    cudaGetSymbolAddress((void**)&Wth,  g_Wth);
    cudaGetSymbolAddress((void**)&hhi,  g_hhi);
    cudaGetSymbolAddress((void**)&hlo,  g_hlo);
    cudaGetSymbolAddress((void**)&B1h,  g_B1h);
    cudaGetSymbolAddress((void**)&B2h,  g_B2h);
    cudaGetSymbolAddress((void**)&hidh, g_hidh);
    cudaGetSymbolAddress((void**)&hidl, g_hidl);

    cudaFuncSetAttribute(attn_kernel, cudaFuncAttributeMaxDynamicSharedMemorySize, ATTN_SMEM);
    cudaFuncSetAttribute(mma_gemm<0>, cudaFuncAttributeMaxDynamicSharedMemorySize, MMG_SMEM);
    cudaFuncSetAttribute(mma_gemm<1>, cudaFuncAttributeMaxDynamicSharedMemorySize, MMG_SMEM);
    cudaFuncSetAttribute(mma_gemm<2>, cudaFuncAttributeMaxDynamicSharedMemorySize, MMG_SMEM);
    cudaFuncSetAttribute(mma_gemm<3>, cudaFuncAttributeMaxDynamicSharedMemorySize, MMG_SMEM);

    const int M1 = 1024 * 1024;
    dim3 t32x8(32, 8);
    // weight prep (independent of activations)
    transpose_split_kernel<<<dim3(32, 32, 16), t32x8>>>(eW1, B1h, 0);
    transpose_split_kernel<<<dim3(32, 32, 16), t32x8>>>(eW2, B2h, 1);
    transpose_split_kernel<<<dim3(32, 32, 1), t32x8>>>(Wq, Wth + 0 * M1, 0);
    transpose_split_kernel<<<dim3(32, 32, 1), t32x8>>>(Wk, Wth + 1 * M1, 0);
    transpose_split_kernel<<<dim3(32, 32, 1), t32x8>>>(Wv, Wth + 2 * M1, 0);
    transpose_split_kernel<<<dim3(32, 32, 1), t32x8>>>(Wo, Wth + 3 * M1, 0);
    // split input, QKV projections on tensor path
    split_kernel<<<4096, 256>>>(input, xhi, xlo);
    mma_gemm<0><<<dim3(8, 16), 512, MMG_SMEM>>>(xhi, xlo, 1024, Wth + 0 * M1, 1024,
                                                bq, nullptr, nullptr, nullptr, nullptr, q, 1024);
    mma_gemm<0><<<dim3(8, 16), 512, MMG_SMEM>>>(xhi, xlo, 1024, Wth + 1 * M1, 1024,
                                                bk, nullptr, nullptr, nullptr, nullptr, k, 1024);
    mma_gemm<0><<<dim3(8, 16), 512, MMG_SMEM>>>(xhi, xlo, 1024, Wth + 2 * M1, 1024,
                                                bv, nullptr, nullptr, nullptr, nullptr, v, 1024);
    // attention
    attn_kernel<<<dim3(32, 16, 2), 256, ATTN_SMEM>>>(q, k, v, attn);
    // O projection + residual on tensor path (reuse xhi/xlo for attn split)
    split_kernel<<<4096, 256>>>(attn, xhi, xlo);
    mma_gemm<1><<<dim3(8, 16), 512, MMG_SMEM>>>(xhi, xlo, 1024, Wth + 3 * M1, 1024,
                                                bo, input, nullptr, nullptr, nullptr, x1, 1024);
    // LN1 (+ fp16 split of h), gates
    ln_kernel<true><<<4096, 256>>>(x1, ln1_g, ln1_b, hbuf, hhi, hlo);
    gate_kernel<<<4096, 128>>>(hbuf, gate_W, gate_b, coef);
    // MoE via mma.sync fp16 2-term split
    mma_gemm<2><<<dim3(128, 16), 512, MMG_SMEM>>>(hhi, hlo, 1024, B1h, 1024,
                                                  eb1, nullptr, coef, hidh, hidl, nullptr, 1024);
    mma_gemm<3><<<dim3(8, 16), 512, MMG_SMEM>>>(hidh, hidl, 16384, B2h, 16384,
                                                eb2, hbuf, coef, nullptr, nullptr, x2, 16384);
    // LN2 -> output
    ln_kernel<false><<<4096, 256>>>(x2, ln2_g, ln2_b, out, nullptr, nullptr);
}

// round 14
// speedup vs baseline: 2.3558x; 1.1606x over previous
#include <cuda_runtime.h>
#include <cuda_fp16.h>
#include <stdint.h>
#include <math.h>

// Problem constants
#define Bc   2
#define Sc   2048
#define Dc   1024
#define Tc   4096      // B*S tokens

// ---------------- device scratch (no cudaMalloc allowed) ----------------
__device__ float g_q   [4096*1024];
__device__ float g_k   [4096*1024];
__device__ float g_v   [4096*1024];
__device__ float g_attn[4096*1024];
__device__ float g_x1  [4096*1024];
__device__ float g_h   [4096*1024];
__device__ float g_x2  [4096*1024];
__device__ float g_coef[4096*16];
__device__ __half g_xhi [4096*1024];   // split of input / attn out
__device__ __half g_xlo [4096*1024];
__device__ __half g_Wth [4*1024*1024]; // Wq,Wk,Wv,Wo transposed (fp16)
__device__ __half g_hhi [4096*1024];
__device__ __half g_hlo [4096*1024];
__device__ __half g_B1h [16777216];    // [16384 n][1024 k] fp16
__device__ __half g_B2h [16777216];    // [1024 d][16384 k] fp16
__device__ __half g_hidh[67108864];    // [4096][16384] fp16

// ======================= helpers =======================
__device__ __forceinline__ uint32_t smem_to_u32(const void* p) {
    uint32_t a;
    asm("{ .reg .u64 t; cvta.to.shared.u64 t, %1; cvt.u32.u64 %0, t; }" : "=r"(a) : "l"(p));
    return a;
}
__device__ __forceinline__ void cp_async16(uint32_t saddr, const void* gaddr) {
    asm volatile("cp.async.cg.shared.global [%0], [%1], 16;" :: "r"(saddr), "l"(gaddr));
}
#define CP_COMMIT() asm volatile("cp.async.commit_group;" ::: "memory")
#define CP_WAIT(n)  asm volatile("cp.async.wait_group %0;" :: "n"(n) : "memory")

__device__ __forceinline__ void ldsm_x4(uint32_t* r, uint32_t a) {
    asm volatile("ldmatrix.sync.aligned.m8n8.x4.shared.b16 {%0,%1,%2,%3}, [%4];"
                 : "=r"(r[0]), "=r"(r[1]), "=r"(r[2]), "=r"(r[3]) : "r"(a));
}
__device__ __forceinline__ void ldsm_x2(uint32_t* r, uint32_t a) {
    asm volatile("ldmatrix.sync.aligned.m8n8.x2.shared.b16 {%0,%1}, [%2];"
                 : "=r"(r[0]), "=r"(r[1]) : "r"(a));
}
__device__ __forceinline__ void mma16816(float* c, const uint32_t* a, const uint32_t* b) {
    asm volatile("mma.sync.aligned.m16n8k16.row.col.f32.f16.f16.f32 "
                 "{%0,%1,%2,%3}, {%4,%5,%6,%7}, {%8,%9}, {%0,%1,%2,%3};"
                 : "+f"(c[0]), "+f"(c[1]), "+f"(c[2]), "+f"(c[3])
                 : "r"(a[0]), "r"(a[1]), "r"(a[2]), "r"(a[3]), "r"(b[0]), "r"(b[1]));
}

__device__ __forceinline__ uint32_t packhf2(float a, float b, uint32_t& lo) {
    __half ha = __float2half_rn(a), hb = __float2half_rn(b);
    float la = a - __half2float(ha), lb = b - __half2float(hb);
    __half2 l2 = __halves2half2(__float2half_rn(la), __float2half_rn(lb));
    lo = *(uint32_t*)&l2;
    __half2 h2 = __halves2half2(ha, hb);
    return *(uint32_t*)&h2;
}

// ============ mma.sync GEMM: 256x128 CTA tile, fp16 NT-term split ============
// A[row][k] fp16 (NT=2: hi/lo pair); B[n][k] single fp16 (K-major).
// MODE 0: C = A@B + bias                         -> fp32  (ldOut 1024)
// MODE 1: C = A@B + bias + res                   -> fp32  (ldOut 1024)
// MODE 2: hid = coef[t,e]*relu(A@B + b1)         -> fp16  (ldOut 16384)
// MODE 3: x2  = A@B + sum_e coef*b2[e] + res     -> fp32  (ldOut 1024)
#define MMG_SMEM   110592
template<int MODE, int NT>
__global__ __launch_bounds__(512, 1) void mma_gemm(
    const __half* __restrict__ Ahi, const __half* __restrict__ Alo, int lda,
    const __half* __restrict__ Bh, int ldb,
    const float* __restrict__ bias, const float* __restrict__ res,
    const float* __restrict__ coef,
    __half* __restrict__ Oh, float* __restrict__ Of, int K)
{
    constexpr int ASZ   = NT * 20480;       // A smem bytes per chunk (256x80 per term)
    constexpr int CHUNK = ASZ + 10240;      // + B (128x80)
    extern __shared__ char smem[];
    const int tid  = threadIdx.x;
    const int lane = tid & 31, wid = tid >> 5;
    const int wm = wid & 7, wn = wid >> 3;  // warp grid 8m x 2n, warp tile 32x64
    const int row0 = blockIdx.y * 256, col0 = blockIdx.x * 128;
    uint32_t sb = smem_to_u32(smem);

    float* bias_sm = (float*)(smem + 2 * CHUNK);
    if (MODE == 3) {
        for (int i = tid; i < 2048; i += 512)
            bias_sm[i] = bias[(i >> 7) * 1024 + col0 + (i & 127)];
    }

    float acc[2][8][4];
#pragma unroll
    for (int mi = 0; mi < 2; mi++)
#pragma unroll
        for (int ni = 0; ni < 8; ni++)
#pragma unroll
            for (int q = 0; q < 4; q++) acc[mi][ni][q] = 0.f;

    auto issue_chunk = [&](int c) {
        const int kb = c * 32;
        uint32_t bufu = sb + (c & 1) * CHUNK;
        constexpr int ATOT = NT * 1024;
#pragma unroll
        for (int it = 0; it < NT * 2 + 1; it++) {
            int idx = tid + it * 512;
            const __half* src;
            uint32_t dst;
            if (idx < ATOT) {                   // A: NT mats x 256 rows x 4 segs
                int m = idx >> 10, rem = idx & 1023, r = rem >> 2, s = rem & 3;
                src = (m ? Alo : Ahi) + (size_t)(row0 + r) * lda + kb + s * 8;
                dst = bufu + m * 20480 + r * 80 + s * 16;
            } else {                            // B: 128 rows x 4 segs
                int i2 = idx - ATOT;
                int r = i2 >> 2, s = i2 & 3;
                src = Bh + (size_t)(col0 + r) * ldb + kb + s * 8;
                dst = bufu + ASZ + r * 80 + s * 16;
            }
            cp_async16(dst, src);
        }
        CP_COMMIT();
    };

    const int NC = K / 32;
    issue_chunk(0);
    for (int c = 0; c < NC; c++) {
        CP_WAIT(0);
        __syncthreads();
        if (c + 1 < NC) issue_chunk(c + 1);
        uint32_t base = sb + (c & 1) * CHUNK;
        uint32_t aAh = base + (wm * 32 + (lane & 15)) * 80 + (lane >> 4) * 16;
#pragma unroll
        for (int kk = 0; kk < 2; kk++) {
            uint32_t ah[2][4], al[2][4];
            ldsm_x4(ah[0], aAh + kk * 32);
            ldsm_x4(ah[1], aAh + 16 * 80 + kk * 32);
            if (NT == 2) {
                ldsm_x4(al[0], aAh + 20480 + kk * 32);
                ldsm_x4(al[1], aAh + 20480 + 16 * 80 + kk * 32);
            }
#pragma unroll
            for (int g = 0; g < 2; g++) {
                uint32_t bf[4][2];
#pragma unroll
                for (int j = 0; j < 4; j++) {
                    int ni = g * 4 + j;
                    uint32_t ab = base + ASZ + (wn * 64 + ni * 8 + (lane & 7)) * 80
                                  + ((lane >> 3) & 1) * 16 + kk * 32;
                    ldsm_x2(bf[j], ab);
                }
#pragma unroll
                for (int j = 0; j < 4; j++) {
                    mma16816(acc[0][g * 4 + j], ah[0], bf[j]);
                    mma16816(acc[1][g * 4 + j], ah[1], bf[j]);
                }
                if (NT == 2) {
#pragma unroll
                    for (int j = 0; j < 4; j++) {
                        mma16816(acc[0][g * 4 + j], al[0], bf[j]);
                        mma16816(acc[1][g * 4 + j], al[1], bf[j]);
                    }
                }
            }
        }
    }

    if (MODE == 2) {
        const int e  = col0 >> 10;
        const int cb = col0 & 1023;
        int   rr[2][2];
        float cf[2][2];
#pragma unroll
        for (int mi = 0; mi < 2; mi++)
#pragma unroll
            for (int h = 0; h < 2; h++) {
                rr[mi][h] = row0 + wm * 32 + mi * 16 + (lane >> 2) + 8 * h;
                cf[mi][h] = coef[(size_t)rr[mi][h] * 16 + e];
            }
#pragma unroll
        for (int mi = 0; mi < 2; mi++)
#pragma unroll
        for (int ni = 0; ni < 8; ni++) {
            int cl = wn * 64 + ni * 8 + (lane & 3) * 2;
            float b0 = bias[e * 1024 + cb + cl];
            float b1 = bias[e * 1024 + cb + cl + 1];
#pragma unroll
            for (int h = 0; h < 2; h++) {
                float v0 = fmaxf(acc[mi][ni][2 * h + 0] + b0, 0.f) * cf[mi][h];
                float v1 = fmaxf(acc[mi][ni][2 * h + 1] + b1, 0.f) * cf[mi][h];
                __half2 h2 = __floats2half2_rn(v0, v1);
                size_t o = (size_t)rr[mi][h] * 16384 + col0 + cl;
                *(__half2*)(Oh + o) = h2;
            }
        }
    } else if (MODE == 3) {
#pragma unroll
        for (int mi = 0; mi < 2; mi++)
#pragma unroll
        for (int h = 0; h < 2; h++) {
            int r2 = row0 + wm * 32 + mi * 16 + (lane >> 2) + 8 * h;
            float cf16[16];
#pragma unroll
            for (int e2 = 0; e2 < 4; e2++)
                *(float4*)&cf16[e2 * 4] = *(const float4*)(coef + (size_t)r2 * 16 + e2 * 4);
#pragma unroll
            for (int ni = 0; ni < 8; ni++) {
                int cl = wn * 64 + ni * 8 + (lane & 3) * 2;
                float2 rv = *(const float2*)(res + (size_t)r2 * 1024 + col0 + cl);
                float v0 = acc[mi][ni][2 * h + 0] + rv.x;
                float v1 = acc[mi][ni][2 * h + 1] + rv.y;
#pragma unroll
                for (int e2 = 0; e2 < 16; e2++) {
                    v0 += cf16[e2] * bias_sm[e2 * 128 + cl];
                    v1 += cf16[e2] * bias_sm[e2 * 128 + cl + 1];
                }
                float2 ov; ov.x = v0; ov.y = v1;
                *(float2*)(Of + (size_t)r2 * 1024 + col0 + cl) = ov;
            }
        }
    } else {
#pragma unroll
        for (int mi = 0; mi < 2; mi++)
#pragma unroll
        for (int h = 0; h < 2; h++) {
            int r2 = row0 + wm * 32 + mi * 16 + (lane >> 2) + 8 * h;
#pragma unroll
            for (int ni = 0; ni < 8; ni++) {
                int cl = wn * 64 + ni * 8 + (lane & 3) * 2;
                float v0 = acc[mi][ni][2 * h + 0] + bias[col0 + cl];
                float v1 = acc[mi][ni][2 * h + 1] + bias[col0 + cl + 1];
                if (MODE == 1) {
                    float2 rv = *(const float2*)(res + (size_t)r2 * 1024 + col0 + cl);
                    v0 += rv.x; v1 += rv.y;
                }
                float2 ov; ov.x = v0; ov.y = v1;
                *(float2*)(Of + (size_t)r2 * 1024 + col0 + cl) = ov;
            }
        }
    }
}

// ---------- 1024x1024 transpose + fp16 convert (per expert / weight) ----------
__global__ __launch_bounds__(256) void transpose_split_kernel(
    const float* __restrict__ in, __half* __restrict__ ohi, int mode)
{
    __shared__ float tsm[32][33];
    const int e = blockIdx.z;
    const int kt = blockIdx.x, nt = blockIdx.y;
    const float* ip = in + ((size_t)e << 20);
    const int tx = threadIdx.x, ty = threadIdx.y;   // 32 x 8
    for (int yy = ty; yy < 32; yy += 8)
        tsm[yy][tx] = ip[(size_t)(kt * 32 + yy) * 1024 + nt * 32 + tx];
    __syncthreads();
    for (int yy = ty; yy < 32; yy += 8) {
        int n = nt * 32 + yy, k = kt * 32 + tx;
        float v = tsm[tx][yy];
        size_t o = (mode == 0) ? ((size_t)(e * 1024 + n) * 1024 + k)
                               : ((size_t)n * 16384 + e * 1024 + k);
        ohi[o] = __float2half_rn(v);
    }
}

// ---------- elementwise fp32 -> fp16 hi/lo split ----------
__global__ __launch_bounds__(256) void split_kernel(
    const float* __restrict__ x, __half* __restrict__ hi, __half* __restrict__ lo)
{
    size_t i = ((size_t)blockIdx.x * 256 + threadIdx.x) * 4;
    float4 v = *(const float4*)(x + i);
    uint2 hw, lw;
    hw.x = packhf2(v.x, v.y, lw.x);
    hw.y = packhf2(v.z, v.w, lw.y);
    *(uint2*)(hi + i) = hw;
    *(uint2*)(lo + i) = lw;
}

// ---------------- flash attention, 64x64 tiles, causal ----------------
#define QS_LD 68
__global__ __launch_bounds__(256) void attn_kernel(
    const float* __restrict__ q, const float* __restrict__ k,
    const float* __restrict__ v, float* __restrict__ o)
{
    extern __shared__ float sm[];
    float* Qs = sm;
    float* Kt = sm + 64 * QS_LD;
    float* Vs = Kt + 64 * 64;
    float* Ps = Vs + 64 * 64;

    const int tid = threadIdx.x;
    const int qb = blockIdx.x, h = blockIdx.y, b = blockIdx.z;
    const size_t base = ((size_t)b * Sc) * Dc + h * 64;

#pragma unroll
    for (int it = 0; it < 4; it++) {
        int f = tid + it * 256;
        int rr = f >> 4, d4 = (f & 15) << 2;
        *(float4*)&Qs[rr * QS_LD + d4] =
            *(const float4*)(q + base + (size_t)(qb * 64 + rr) * Dc + d4);
    }

    const int r = tid >> 2, cg = tid & 3;
    const int qi = qb * 64 + r;
    float out[16];
#pragma unroll
    for (int j2 = 0; j2 < 16; j2++) out[j2] = 0.f;
    float mrun = -1e30f, lrun = 0.f;

    for (int kb = 0; kb <= qb; kb++) {
        __syncthreads();
#pragma unroll
        for (int it = 0; it < 4; it++) {
            int f = tid + it * 256;
            int rr = f >> 4, d4 = (f & 15) << 2;
            float4 kv = *(const float4*)(k + base + (size_t)(kb * 64 + rr) * Dc + d4);
            Kt[(d4 + 0) * 64 + rr] = kv.x; Kt[(d4 + 1) * 64 + rr] = kv.y;
            Kt[(d4 + 2) * 64 + rr] = kv.z; Kt[(d4 + 3) * 64 + rr] = kv.w;
            *(float4*)&Vs[rr * 64 + d4] =
                *(const float4*)(v + base + (size_t)(kb * 64 + rr) * Dc + d4);
        }
        __syncthreads();

        float s[16];
#pragma unroll
        for (int c = 0; c < 16; c++) s[c] = 0.f;
#pragma unroll 4
        for (int d = 0; d < 64; d++) {
            float qv = Qs[r * QS_LD + d];
            const float* kp = &Kt[d * 64 + cg * 16];
            float4 k0 = *(const float4*)(kp);
            float4 k1 = *(const float4*)(kp + 4);
            float4 k2 = *(const float4*)(kp + 8);
            float4 k3 = *(const float4*)(kp + 12);
            s[0] += qv * k0.x; s[1] += qv * k0.y; s[2] += qv * k0.z; s[3] += qv * k0.w;
            s[4] += qv * k1.x; s[5] += qv * k1.y; s[6] += qv * k1.z; s[7] += qv * k1.w;
            s[8] += qv * k2.x; s[9] += qv * k2.y; s[10]+= qv * k2.z; s[11]+= qv * k2.w;
            s[12]+= qv * k3.x; s[13]+= qv * k3.y; s[14]+= qv * k3.z; s[15]+= qv * k3.w;
        }

        float mloc = -1e30f;
#pragma unroll
        for (int c = 0; c < 16; c++) {
            float sv = s[c] * 0.125f;
            int kj = kb * 64 + cg * 16 + c;
            if (kj > qi) sv = -1e9f;
            s[c] = sv;
            mloc = fmaxf(mloc, sv);
        }
        mloc = fmaxf(mloc, __shfl_xor_sync(0xffffffffu, mloc, 1));
        mloc = fmaxf(mloc, __shfl_xor_sync(0xffffffffu, mloc, 2));
        const float mnew = fmaxf(mrun, mloc);
        const float alpha = __expf(mrun - mnew);
        float lloc = 0.f;
#pragma unroll
        for (int c = 0; c < 16; c++) { float p = __expf(s[c] - mnew); s[c] = p; lloc += p; }
        lloc += __shfl_xor_sync(0xffffffffu, lloc, 1);
        lloc += __shfl_xor_sync(0xffffffffu, lloc, 2);
        lrun = lrun * alpha + lloc;
        mrun = mnew;
#pragma unroll
        for (int j2 = 0; j2 < 16; j2++) out[j2] *= alpha;

#pragma unroll
        for (int c = 0; c < 16; c++) Ps[r * QS_LD + cg * 16 + c] = s[c];
        __syncwarp();

#pragma unroll 2
        for (int c = 0; c < 64; c++) {
            float p = Ps[r * QS_LD + c];
            const float* vp = &Vs[c * 64 + cg * 16];
            float4 v0 = *(const float4*)vp, v1 = *(const float4*)(vp + 4);
            float4 v2 = *(const float4*)(vp + 8), v3 = *(const float4*)(vp + 12);
            out[0] += p * v0.x; out[1] += p * v0.y; out[2] += p * v0.z; out[3] += p * v0.w;
            out[4] += p * v1.x; out[5] += p * v1.y; out[6] += p * v1.z; out[7] += p * v1.w;
            out[8] += p * v2.x; out[9] += p * v2.y; out[10]+= p * v2.z; out[11]+= p * v2.w;
            out[12]+= p * v3.x; out[13]+= p * v3.y; out[14]+= p * v3.z; out[15]+= p * v3.w;
        }
    }

    const float invl = 1.f / lrun;
#pragma unroll
    for (int j2 = 0; j2 < 16; j2++)
        o[base + (size_t)qi * Dc + cg * 16 + j2] = out[j2] * invl;
}

// ---------------- LayerNorm (optionally emits fp16 hi/lo split) ----------------
template<bool SPLIT>
__global__ __launch_bounds__(256) void ln_kernel(
    const float* __restrict__ x, const float* __restrict__ gam,
    const float* __restrict__ bet, float* __restrict__ o,
    __half* __restrict__ ohi, __half* __restrict__ olo)
{
    const int row = blockIdx.x, tid = threadIdx.x;
    const float4 v = *(const float4*)(x + (size_t)row * 1024 + tid * 4);
    float s = v.x + v.y + v.z + v.w;
    float q = v.x * v.x + v.y * v.y + v.z * v.z + v.w * v.w;
#pragma unroll
    for (int off = 16; off; off >>= 1) {
        s += __shfl_xor_sync(0xffffffffu, s, off);
        q += __shfl_xor_sync(0xffffffffu, q, off);
    }
    __shared__ float ss[8], sq[8];
    if ((tid & 31) == 0) { ss[tid >> 5] = s; sq[tid >> 5] = q; }
    __syncthreads();
    float S = 0.f, Q = 0.f;
#pragma unroll
    for (int w = 0; w < 8; w++) { S += ss[w]; Q += sq[w]; }
    const float mu = S * (1.f / 1024.f);
    const float var = Q * (1.f / 1024.f) - mu * mu;
    const float inv = rsqrtf(var + 1e-5f);
    float4 g4 = *(const float4*)(gam + tid * 4);
    float4 b4 = *(const float4*)(bet + tid * 4);
    float4 r4;
    r4.x = (v.x - mu) * inv * g4.x + b4.x;
    r4.y = (v.y - mu) * inv * g4.y + b4.y;
    r4.z = (v.z - mu) * inv * g4.z + b4.z;
    r4.w = (v.w - mu) * inv * g4.w + b4.w;
    *(float4*)(o + (size_t)row * 1024 + tid * 4) = r4;
    if (SPLIT) {
        uint2 hw, lw;
        hw.x = packhf2(r4.x, r4.y, lw.x);
        hw.y = packhf2(r4.z, r4.w, lw.y);
        *(uint2*)(ohi + (size_t)row * 1024 + tid * 4) = hw;
        *(uint2*)(olo + (size_t)row * 1024 + tid * 4) = lw;
    }
}

// ---------------- gate: logits + per-gate softmax, /G folded in ----------------
__global__ __launch_bounds__(128) void gate_kernel(
    const float* __restrict__ h, const float* __restrict__ gW,
    const float* __restrict__ gb, float* __restrict__ coef)
{
    const int t = blockIdx.x, tid = threadIdx.x;
    float acc[16];
#pragma unroll
    for (int j = 0; j < 16; j++) acc[j] = 0.f;
    const float* hr = h + (size_t)t * 1024;
    for (int d = tid; d < 1024; d += 128) {
        float hv = hr[d];
#pragma unroll
        for (int g = 0; g < 2; g++)
#pragma unroll
            for (int e = 0; e < 8; e++)
                acc[g * 8 + e] += hv * gW[g * 8192 + d * 8 + e];
    }
    __shared__ float red[16][4];
#pragma unroll
    for (int j = 0; j < 16; j++) {
        float vv = acc[j];
        for (int off = 16; off; off >>= 1) vv += __shfl_xor_sync(0xffffffffu, vv, off);
        if ((tid & 31) == 0) red[j][tid >> 5] = vv;
    }
    __syncthreads();
    if (tid < 16) {
        float lg = red[tid][0] + red[tid][1] + red[tid][2] + red[tid][3] + gb[tid];
        float mx = lg;
        for (int off = 4; off; off >>= 1) mx = fmaxf(mx, __shfl_xor_sync(0xffffu, mx, off));
        float ex = __expf(lg - mx);
        float smv = ex;
        for (int off = 4; off; off >>= 1) smv += __shfl_xor_sync(0xffffu, smv, off);
        coef[(size_t)t * 16 + tid] = ex / smv * 0.5f;
    }
}

#define ATTN_SMEM (64 * (QS_LD + 64 + 64 + QS_LD) * 4)

extern "C" void kernel_launch(void* const* d_in, const int* in_sizes, int n_in,
                              void* d_out, int out_size)
{
    const float* input  = (const float*)d_in[0];
    const float* Wq     = (const float*)d_in[1];
    const float* bq     = (const float*)d_in[2];
    const float* Wk     = (const float*)d_in[3];
    const float* bk     = (const float*)d_in[4];
    const float* Wv     = (const float*)d_in[5];
    const float* bv     = (const float*)d_in[6];
    const float* Wo     = (const float*)d_in[7];
    const float* bo     = (const float*)d_in[8];
    const float* ln1_g  = (const float*)d_in[9];
    const float* ln1_b  = (const float*)d_in[10];
    const float* gate_W = (const float*)d_in[11];
    const float* gate_b = (const float*)d_in[12];
    const float* eW1    = (const float*)d_in[13];
    const float* eb1    = (const float*)d_in[14];
    const float* eW2    = (const float*)d_in[15];
    const float* eb2    = (const float*)d_in[16];
    const float* ln2_g  = (const float*)d_in[17];
    const float* ln2_b  = (const float*)d_in[18];
    float* out = (float*)d_out;

    float *q, *k, *v, *attn, *x1, *hbuf, *x2, *coef;
    __half *xhi, *xlo, *Wth, *hhi, *hlo, *B1h, *B2h, *hidh;
    cudaGetSymbolAddress((void**)&q,    g_q);
    cudaGetSymbolAddress((void**)&k,    g_k);
    cudaGetSymbolAddress((void**)&v,    g_v);
    cudaGetSymbolAddress((void**)&attn, g_attn);
    cudaGetSymbolAddress((void**)&x1,   g_x1);
    cudaGetSymbolAddress((void**)&hbuf, g_h);
    cudaGetSymbolAddress((void**)&x2,   g_x2);
    cudaGetSymbolAddress((void**)&coef, g_coef);
    cudaGetSymbolAddress((void**)&xhi,  g_xhi);
    cudaGetSymbolAddress((void**)&xlo,  g_xlo);
    cudaGetSymbolAddress((void**)&Wth,  g_Wth);
    cudaGetSymbolAddress((void**)&hhi,  g_hhi);
    cudaGetSymbolAddress((void**)&hlo,  g_hlo);
    cudaGetSymbolAddress((void**)&B1h,  g_B1h);
    cudaGetSymbolAddress((void**)&B2h,  g_B2h);
    cudaGetSymbolAddress((void**)&hidh, g_hidh);

    cudaFuncSetAttribute(attn_kernel, cudaFuncAttributeMaxDynamicSharedMemorySize, ATTN_SMEM);
    cudaFuncSetAttribute((const void*)mma_gemm<0,2>, cudaFuncAttributeMaxDynamicSharedMemorySize, MMG_SMEM);
    cudaFuncSetAttribute((const void*)mma_gemm<1,2>, cudaFuncAttributeMaxDynamicSharedMemorySize, MMG_SMEM);
    cudaFuncSetAttribute((const void*)mma_gemm<2,1>, cudaFuncAttributeMaxDynamicSharedMemorySize, MMG_SMEM);
    cudaFuncSetAttribute((const void*)mma_gemm<3,1>, cudaFuncAttributeMaxDynamicSharedMemorySize, MMG_SMEM);

    const int M1 = 1024 * 1024;
    dim3 t32x8(32, 8);
    // weight prep (independent of activations)
    transpose_split_kernel<<<dim3(32, 32, 16), t32x8>>>(eW1, B1h, 0);
    transpose_split_kernel<<<dim3(32, 32, 16), t32x8>>>(eW2, B2h, 1);
    transpose_split_kernel<<<dim3(32, 32, 1), t32x8>>>(Wq, Wth + 0 * M1, 0);
    transpose_split_kernel<<<dim3(32, 32, 1), t32x8>>>(Wk, Wth + 1 * M1, 0);
    transpose_split_kernel<<<dim3(32, 32, 1), t32x8>>>(Wv, Wth + 2 * M1, 0);
    transpose_split_kernel<<<dim3(32, 32, 1), t32x8>>>(Wo, Wth + 3 * M1, 0);
    // split input, QKV projections on tensor path (2-term)
    split_kernel<<<4096, 256>>>(input, xhi, xlo);
    mma_gemm<0,2><<<dim3(8, 16), 512, MMG_SMEM>>>(xhi, xlo, 1024, Wth + 0 * M1, 1024,
                                                  bq, nullptr, nullptr, nullptr, q, 1024);
    mma_gemm<0,2><<<dim3(8, 16), 512, MMG_SMEM>>>(xhi, xlo, 1024, Wth + 1 * M1, 1024,
                                                  bk, nullptr, nullptr, nullptr, k, 1024);
    mma_gemm<0,2><<<dim3(8, 16), 512, MMG_SMEM>>>(xhi, xlo, 1024, Wth + 2 * M1, 1024,
                                                  bv, nullptr, nullptr, nullptr, v, 1024);
    // attention
    attn_kernel<<<dim3(32, 16, 2), 256, ATTN_SMEM>>>(q, k, v, attn);
    // O projection + residual (2-term, reuse xhi/xlo for attn split)
    split_kernel<<<4096, 256>>>(attn, xhi, xlo);
    mma_gemm<1,2><<<dim3(8, 16), 512, MMG_SMEM>>>(xhi, xlo, 1024, Wth + 3 * M1, 1024,
                                                  bo, input, nullptr, nullptr, x1, 1024);
    // LN1 (+ fp16 split of h), gates
    ln_kernel<true><<<4096, 256>>>(x1, ln1_g, ln1_b, hbuf, hhi, hlo);
    gate_kernel<<<4096, 128>>>(hbuf, gate_W, gate_b, coef);
    // MoE via mma.sync, pure fp16 (1-term both sides)
    mma_gemm<2,1><<<dim3(128, 16), 512, MMG_SMEM>>>(hhi, nullptr, 1024, B1h, 1024,
                                                    eb1, nullptr, coef, hidh, nullptr, 1024);
    mma_gemm<3,1><<<dim3(8, 16), 512, MMG_SMEM>>>(hidh, nullptr, 16384, B2h, 16384,
                                                  eb2, hbuf, coef, nullptr, x2, 16384);
    // LN2 -> output
    ln_kernel<false><<<4096, 256>>>(x2, ln2_g, ln2_b, out, nullptr, nullptr);
}

// round 15
// speedup vs baseline: 2.3747x; 1.0080x over previous
#include <cuda_runtime.h>
#include <cuda_fp16.h>
#include <stdint.h>
#include <math.h>

// Problem constants
#define Bc   2
#define Sc   2048
#define Dc   1024
#define Tc   4096      // B*S tokens

// ---------------- device scratch (no cudaMalloc allowed) ----------------
__device__ float g_q   [4096*1024];
__device__ float g_k   [4096*1024];
__device__ float g_v   [4096*1024];
__device__ float g_attn[4096*1024];
__device__ float g_x1  [4096*1024];
__device__ float g_h   [4096*1024];
__device__ float g_x2  [4096*1024];
__device__ float g_coef[4096*16];
__device__ __half g_xhi [4096*1024];   // split of input / attn out
__device__ __half g_xlo [4096*1024];
__device__ __half g_Wth [4*1024*1024]; // Wq,Wk,Wv,Wo transposed (fp16)
__device__ __half g_hhi [4096*1024];
__device__ __half g_hlo [4096*1024];
__device__ __half g_B1h [16777216];    // [16384 n][1024 k] fp16
__device__ __half g_B2h [16777216];    // [1024 d][16384 k] fp16
__device__ __half g_hidh[67108864];    // [4096][16384] fp16

// ======================= helpers =======================
__device__ __forceinline__ uint32_t smem_to_u32(const void* p) {
    uint32_t a;
    asm("{ .reg .u64 t; cvta.to.shared.u64 t, %1; cvt.u32.u64 %0, t; }" : "=r"(a) : "l"(p));
    return a;
}
__device__ __forceinline__ void cp_async16(uint32_t saddr, const void* gaddr) {
    asm volatile("cp.async.cg.shared.global [%0], [%1], 16;" :: "r"(saddr), "l"(gaddr));
}
#define CP_COMMIT() asm volatile("cp.async.commit_group;" ::: "memory")
#define CP_WAIT(n)  asm volatile("cp.async.wait_group %0;" :: "n"(n) : "memory")

__device__ __forceinline__ void ldsm_x4(uint32_t* r, uint32_t a) {
    asm volatile("ldmatrix.sync.aligned.m8n8.x4.shared.b16 {%0,%1,%2,%3}, [%4];"
                 : "=r"(r[0]), "=r"(r[1]), "=r"(r[2]), "=r"(r[3]) : "r"(a));
}
__device__ __forceinline__ void ldsm_x2(uint32_t* r, uint32_t a) {
    asm volatile("ldmatrix.sync.aligned.m8n8.x2.shared.b16 {%0,%1}, [%2];"
                 : "=r"(r[0]), "=r"(r[1]) : "r"(a));
}
__device__ __forceinline__ void mma16816(float* c, const uint32_t* a, const uint32_t* b) {
    asm volatile("mma.sync.aligned.m16n8k16.row.col.f32.f16.f16.f32 "
                 "{%0,%1,%2,%3}, {%4,%5,%6,%7}, {%8,%9}, {%0,%1,%2,%3};"
                 : "+f"(c[0]), "+f"(c[1]), "+f"(c[2]), "+f"(c[3])
                 : "r"(a[0]), "r"(a[1]), "r"(a[2]), "r"(a[3]), "r"(b[0]), "r"(b[1]));
}

__device__ __forceinline__ uint32_t packhf2(float a, float b, uint32_t& lo) {
    __half ha = __float2half_rn(a), hb = __float2half_rn(b);
    float la = a - __half2float(ha), lb = b - __half2float(hb);
    __half2 l2 = __halves2half2(__float2half_rn(la), __float2half_rn(lb));
    lo = *(uint32_t*)&l2;
    __half2 h2 = __halves2half2(ha, hb);
    return *(uint32_t*)&h2;
}

// ============ mma.sync GEMM: 256x128 CTA tile, fp16 NT-term split ============
// A[row][k] fp16 (NT=2: hi/lo pair); B[n][k] single fp16 (K-major).
// MODE 0: C = A@B + bias                         -> fp32  (ldOut 1024)
// MODE 1: C = A@B + bias + res                   -> fp32  (ldOut 1024)
// MODE 2: hid = coef[t,e]*relu(A@B + b1)         -> fp16  (ldOut 16384)
// MODE 3: x2  = A@B + sum_e coef*b2[e] + res     -> fp32  (ldOut 1024)
// STAGES-deep cp.async pipeline (wait_group STAGES-2).
template<int MODE, int NT, int STAGES>
__global__ __launch_bounds__(512, 1) void mma_gemm(
    const __half* __restrict__ Ahi, const __half* __restrict__ Alo, int lda,
    const __half* __restrict__ Bh, int ldb,
    const float* __restrict__ bias, const float* __restrict__ res,
    const float* __restrict__ coef,
    __half* __restrict__ Oh, float* __restrict__ Of, int K)
{
    constexpr int ASZ   = NT * 20480;       // A smem bytes per chunk (256x80 per term)
    constexpr int CHUNK = ASZ + 10240;      // + B (128x80)
    extern __shared__ char smem[];
    const int tid  = threadIdx.x;
    const int lane = tid & 31, wid = tid >> 5;
    const int wm = wid & 7, wn = wid >> 3;  // warp grid 8m x 2n, warp tile 32x64
    const int row0 = blockIdx.y * 256, col0 = blockIdx.x * 128;
    uint32_t sb = smem_to_u32(smem);

    float* bias_sm = (float*)(smem + STAGES * CHUNK);
    if (MODE == 3) {
        for (int i = tid; i < 2048; i += 512)
            bias_sm[i] = bias[(i >> 7) * 1024 + col0 + (i & 127)];
    }

    float acc[2][8][4];
#pragma unroll
    for (int mi = 0; mi < 2; mi++)
#pragma unroll
        for (int ni = 0; ni < 8; ni++)
#pragma unroll
            for (int q = 0; q < 4; q++) acc[mi][ni][q] = 0.f;

    auto issue_chunk = [&](int c) {
        const int kb = c * 32;
        uint32_t bufu = sb + (c % STAGES) * CHUNK;
        constexpr int ATOT = NT * 1024;
#pragma unroll
        for (int it = 0; it < NT * 2 + 1; it++) {
            int idx = tid + it * 512;
            const __half* src;
            uint32_t dst;
            if (idx < ATOT) {                   // A: NT mats x 256 rows x 4 segs
                int m = idx >> 10, rem = idx & 1023, r = rem >> 2, s = rem & 3;
                src = (m ? Alo : Ahi) + (size_t)(row0 + r) * lda + kb + s * 8;
                dst = bufu + m * 20480 + r * 80 + s * 16;
            } else {                            // B: 128 rows x 4 segs
                int i2 = idx - ATOT;
                int r = i2 >> 2, s = i2 & 3;
                src = Bh + (size_t)(col0 + r) * ldb + kb + s * 8;
                dst = bufu + ASZ + r * 80 + s * 16;
            }
            cp_async16(dst, src);
        }
        CP_COMMIT();
    };

    const int NC = K / 32;
#pragma unroll
    for (int s = 0; s < STAGES - 1; s++)
        if (s < NC) issue_chunk(s);
    for (int c = 0; c < NC; c++) {
        CP_WAIT(STAGES - 2);
        __syncthreads();
        if (c + STAGES - 1 < NC) issue_chunk(c + STAGES - 1);
        uint32_t base = sb + (c % STAGES) * CHUNK;
        uint32_t aAh = base + (wm * 32 + (lane & 15)) * 80 + (lane >> 4) * 16;
#pragma unroll
        for (int kk = 0; kk < 2; kk++) {
            uint32_t ah[2][4], al[2][4];
            ldsm_x4(ah[0], aAh + kk * 32);
            ldsm_x4(ah[1], aAh + 16 * 80 + kk * 32);
            if (NT == 2) {
                ldsm_x4(al[0], aAh + 20480 + kk * 32);
                ldsm_x4(al[1], aAh + 20480 + 16 * 80 + kk * 32);
            }
#pragma unroll
            for (int g = 0; g < 2; g++) {
                uint32_t bf[4][2];
#pragma unroll
                for (int j = 0; j < 4; j++) {
                    int ni = g * 4 + j;
                    uint32_t ab = base + ASZ + (wn * 64 + ni * 8 + (lane & 7)) * 80
                                  + ((lane >> 3) & 1) * 16 + kk * 32;
                    ldsm_x2(bf[j], ab);
                }
#pragma unroll
                for (int j = 0; j < 4; j++) {
                    mma16816(acc[0][g * 4 + j], ah[0], bf[j]);
                    mma16816(acc[1][g * 4 + j], ah[1], bf[j]);
                }
                if (NT == 2) {
#pragma unroll
                    for (int j = 0; j < 4; j++) {
                        mma16816(acc[0][g * 4 + j], al[0], bf[j]);
                        mma16816(acc[1][g * 4 + j], al[1], bf[j]);
                    }
                }
            }
        }
    }

    if (MODE == 2) {
        const int e  = col0 >> 10;
        const int cb = col0 & 1023;
        int   rr[2][2];
        float cf[2][2];
#pragma unroll
        for (int mi = 0; mi < 2; mi++)
#pragma unroll
            for (int h = 0; h < 2; h++) {
                rr[mi][h] = row0 + wm * 32 + mi * 16 + (lane >> 2) + 8 * h;
                cf[mi][h] = coef[(size_t)rr[mi][h] * 16 + e];
            }
#pragma unroll
        for (int mi = 0; mi < 2; mi++)
#pragma unroll
        for (int ni = 0; ni < 8; ni++) {
            int cl = wn * 64 + ni * 8 + (lane & 3) * 2;
            float b0 = bias[e * 1024 + cb + cl];
            float b1 = bias[e * 1024 + cb + cl + 1];
#pragma unroll
            for (int h = 0; h < 2; h++) {
                float v0 = fmaxf(acc[mi][ni][2 * h + 0] + b0, 0.f) * cf[mi][h];
                float v1 = fmaxf(acc[mi][ni][2 * h + 1] + b1, 0.f) * cf[mi][h];
                __half2 h2 = __floats2half2_rn(v0, v1);
                size_t o = (size_t)rr[mi][h] * 16384 + col0 + cl;
                *(__half2*)(Oh + o) = h2;
            }
        }
    } else if (MODE == 3) {
#pragma unroll
        for (int mi = 0; mi < 2; mi++)
#pragma unroll
        for (int h = 0; h < 2; h++) {
            int r2 = row0 + wm * 32 + mi * 16 + (lane >> 2) + 8 * h;
            float cf16[16];
#pragma unroll
            for (int e2 = 0; e2 < 4; e2++)
                *(float4*)&cf16[e2 * 4] = *(const float4*)(coef + (size_t)r2 * 16 + e2 * 4);
#pragma unroll
            for (int ni = 0; ni < 8; ni++) {
                int cl = wn * 64 + ni * 8 + (lane & 3) * 2;
                float2 rv = *(const float2*)(res + (size_t)r2 * 1024 + col0 + cl);
                float v0 = acc[mi][ni][2 * h + 0] + rv.x;
                float v1 = acc[mi][ni][2 * h + 1] + rv.y;
#pragma unroll
                for (int e2 = 0; e2 < 16; e2++) {
                    v0 += cf16[e2] * bias_sm[e2 * 128 + cl];
                    v1 += cf16[e2] * bias_sm[e2 * 128 + cl + 1];
                }
                float2 ov; ov.x = v0; ov.y = v1;
                *(float2*)(Of + (size_t)r2 * 1024 + col0 + cl) = ov;
            }
        }
    } else {
#pragma unroll
        for (int mi = 0; mi < 2; mi++)
#pragma unroll
        for (int h = 0; h < 2; h++) {
            int r2 = row0 + wm * 32 + mi * 16 + (lane >> 2) + 8 * h;
#pragma unroll
            for (int ni = 0; ni < 8; ni++) {
                int cl = wn * 64 + ni * 8 + (lane & 3) * 2;
                float v0 = acc[mi][ni][2 * h + 0] + bias[col0 + cl];
                float v1 = acc[mi][ni][2 * h + 1] + bias[col0 + cl + 1];
                if (MODE == 1) {
                    float2 rv = *(const float2*)(res + (size_t)r2 * 1024 + col0 + cl);
                    v0 += rv.x; v1 += rv.y;
                }
                float2 ov; ov.x = v0; ov.y = v1;
                *(float2*)(Of + (size_t)r2 * 1024 + col0 + cl) = ov;
            }
        }
    }
}

// smem sizes per instantiation
#define SMEM_NT1 (4 * (20480 + 10240) + 8192)    // 4-stage, 1-term: 131072
#define SMEM_NT2 (3 * (2 * 20480 + 10240) + 8192) // 3-stage, 2-term: 161792

// ---------- 1024x1024 transpose + fp16 convert (per expert / weight) ----------
__global__ __launch_bounds__(256) void transpose_split_kernel(
    const float* __restrict__ in, __half* __restrict__ ohi, int mode)
{
    __shared__ float tsm[32][33];
    const int e = blockIdx.z;
    const int kt = blockIdx.x, nt = blockIdx.y;
    const float* ip = in + ((size_t)e << 20);
    const int tx = threadIdx.x, ty = threadIdx.y;   // 32 x 8
    for (int yy = ty; yy < 32; yy += 8)
        tsm[yy][tx] = ip[(size_t)(kt * 32 + yy) * 1024 + nt * 32 + tx];
    __syncthreads();
    for (int yy = ty; yy < 32; yy += 8) {
        int n = nt * 32 + yy, k = kt * 32 + tx;
        float v = tsm[tx][yy];
        size_t o = (mode == 0) ? ((size_t)(e * 1024 + n) * 1024 + k)
                               : ((size_t)n * 16384 + e * 1024 + k);
        ohi[o] = __float2half_rn(v);
    }
}

// ---------- elementwise fp32 -> fp16 hi/lo split ----------
__global__ __launch_bounds__(256) void split_kernel(
    const float* __restrict__ x, __half* __restrict__ hi, __half* __restrict__ lo)
{
    size_t i = ((size_t)blockIdx.x * 256 + threadIdx.x) * 4;
    float4 v = *(const float4*)(x + i);
    uint2 hw, lw;
    hw.x = packhf2(v.x, v.y, lw.x);
    hw.y = packhf2(v.z, v.w, lw.y);
    *(uint2*)(hi + i) = hw;
    *(uint2*)(lo + i) = lw;
}

// ---------------- flash attention, 64x64 tiles, causal ----------------
#define QS_LD 68
__global__ __launch_bounds__(256) void attn_kernel(
    const float* __restrict__ q, const float* __restrict__ k,
    const float* __restrict__ v, float* __restrict__ o)
{
    extern __shared__ float sm[];
    float* Qs = sm;
    float* Kt = sm + 64 * QS_LD;
    float* Vs = Kt + 64 * 64;
    float* Ps = Vs + 64 * 64;

    const int tid = threadIdx.x;
    const int qb = blockIdx.x, h = blockIdx.y, b = blockIdx.z;
    const size_t base = ((size_t)b * Sc) * Dc + h * 64;

#pragma unroll
    for (int it = 0; it < 4; it++) {
        int f = tid + it * 256;
        int rr = f >> 4, d4 = (f & 15) << 2;
        *(float4*)&Qs[rr * QS_LD + d4] =
            *(const float4*)(q + base + (size_t)(qb * 64 + rr) * Dc + d4);
    }

    const int r = tid >> 2, cg = tid & 3;
    const int qi = qb * 64 + r;
    float out[16];
#pragma unroll
    for (int j2 = 0; j2 < 16; j2++) out[j2] = 0.f;
    float mrun = -1e30f, lrun = 0.f;

    for (int kb = 0; kb <= qb; kb++) {
        __syncthreads();
#pragma unroll
        for (int it = 0; it < 4; it++) {
            int f = tid + it * 256;
            int rr = f >> 4, d4 = (f & 15) << 2;
            float4 kv = *(const float4*)(k + base + (size_t)(kb * 64 + rr) * Dc + d4);
            Kt[(d4 + 0) * 64 + rr] = kv.x; Kt[(d4 + 1) * 64 + rr] = kv.y;
            Kt[(d4 + 2) * 64 + rr] = kv.z; Kt[(d4 + 3) * 64 + rr] = kv.w;
            *(float4*)&Vs[rr * 64 + d4] =
                *(const float4*)(v + base + (size_t)(kb * 64 + rr) * Dc + d4);
        }
        __syncthreads();

        float s[16];
#pragma unroll
        for (int c = 0; c < 16; c++) s[c] = 0.f;
#pragma unroll 4
        for (int d = 0; d < 64; d++) {
            float qv = Qs[r * QS_LD + d];
            const float* kp = &Kt[d * 64 + cg * 16];
            float4 k0 = *(const float4*)(kp);
            float4 k1 = *(const float4*)(kp + 4);
            float4 k2 = *(const float4*)(kp + 8);
            float4 k3 = *(const float4*)(kp + 12);
            s[0] += qv * k0.x; s[1] += qv * k0.y; s[2] += qv * k0.z; s[3] += qv * k0.w;
            s[4] += qv * k1.x; s[5] += qv * k1.y; s[6] += qv * k1.z; s[7] += qv * k1.w;
            s[8] += qv * k2.x; s[9] += qv * k2.y; s[10]+= qv * k2.z; s[11]+= qv * k2.w;
            s[12]+= qv * k3.x; s[13]+= qv * k3.y; s[14]+= qv * k3.z; s[15]+= qv * k3.w;
        }

        float mloc = -1e30f;
#pragma unroll
        for (int c = 0; c < 16; c++) {
            float sv = s[c] * 0.125f;
            int kj = kb * 64 + cg * 16 + c;
            if (kj > qi) sv = -1e9f;
            s[c] = sv;
            mloc = fmaxf(mloc, sv);
        }
        mloc = fmaxf(mloc, __shfl_xor_sync(0xffffffffu, mloc, 1));
        mloc = fmaxf(mloc, __shfl_xor_sync(0xffffffffu, mloc, 2));
        const float mnew = fmaxf(mrun, mloc);
        const float alpha = __expf(mrun - mnew);
        float lloc = 0.f;
#pragma unroll
        for (int c = 0; c < 16; c++) { float p = __expf(s[c] - mnew); s[c] = p; lloc += p; }
        lloc += __shfl_xor_sync(0xffffffffu, lloc, 1);
        lloc += __shfl_xor_sync(0xffffffffu, lloc, 2);
        lrun = lrun * alpha + lloc;
        mrun = mnew;
#pragma unroll
        for (int j2 = 0; j2 < 16; j2++) out[j2] *= alpha;

#pragma unroll
        for (int c = 0; c < 16; c++) Ps[r * QS_LD + cg * 16 + c] = s[c];
        __syncwarp();

#pragma unroll 2
        for (int c = 0; c < 64; c++) {
            float p = Ps[r * QS_LD + c];
            const float* vp = &Vs[c * 64 + cg * 16];
            float4 v0 = *(const float4*)vp, v1 = *(const float4*)(vp + 4);
            float4 v2 = *(const float4*)(vp + 8), v3 = *(const float4*)(vp + 12);
            out[0] += p * v0.x; out[1] += p * v0.y; out[2] += p * v0.z; out[3] += p * v0.w;
            out[4] += p * v1.x; out[5] += p * v1.y; out[6] += p * v1.z; out[7] += p * v1.w;
            out[8] += p * v2.x; out[9] += p * v2.y; out[10]+= p * v2.z; out[11]+= p * v2.w;
            out[12]+= p * v3.x; out[13]+= p * v3.y; out[14]+= p * v3.z; out[15]+= p * v3.w;
        }
    }

    const float invl = 1.f / lrun;
#pragma unroll
    for (int j2 = 0; j2 < 16; j2++)
        o[base + (size_t)qi * Dc + cg * 16 + j2] = out[j2] * invl;
}

// ---------------- LayerNorm (optionally emits fp16 hi/lo split) ----------------
template<bool SPLIT>
__global__ __launch_bounds__(256) void ln_kernel(
    const float* __restrict__ x, const float* __restrict__ gam,
    const float* __restrict__ bet, float* __restrict__ o,
    __half* __restrict__ ohi, __half* __restrict__ olo)
{
    const int row = blockIdx.x, tid = threadIdx.x;
    const float4 v = *(const float4*)(x + (size_t)row * 1024 + tid * 4);
    float s = v.x + v.y + v.z + v.w;
    float q = v.x * v.x + v.y * v.y + v.z * v.z + v.w * v.w;
#pragma unroll
    for (int off = 16; off; off >>= 1) {
        s += __shfl_xor_sync(0xffffffffu, s, off);
        q += __shfl_xor_sync(0xffffffffu, q, off);
    }
    __shared__ float ss[8], sq[8];
    if ((tid & 31) == 0) { ss[tid >> 5] = s; sq[tid >> 5] = q; }
    __syncthreads();
    float S = 0.f, Q = 0.f;
#pragma unroll
    for (int w = 0; w < 8; w++) { S += ss[w]; Q += sq[w]; }
    const float mu = S * (1.f / 1024.f);
    const float var = Q * (1.f / 1024.f) - mu * mu;
    const float inv = rsqrtf(var + 1e-5f);
    float4 g4 = *(const float4*)(gam + tid * 4);
    float4 b4 = *(const float4*)(bet + tid * 4);
    float4 r4;
    r4.x = (v.x - mu) * inv * g4.x + b4.x;
    r4.y = (v.y - mu) * inv * g4.y + b4.y;
    r4.z = (v.z - mu) * inv * g4.z + b4.z;
    r4.w = (v.w - mu) * inv * g4.w + b4.w;
    *(float4*)(o + (size_t)row * 1024 + tid * 4) = r4;
    if (SPLIT) {
        uint2 hw, lw;
        hw.x = packhf2(r4.x, r4.y, lw.x);
        hw.y = packhf2(r4.z, r4.w, lw.y);
        *(uint2*)(ohi + (size_t)row * 1024 + tid * 4) = hw;
        *(uint2*)(olo + (size_t)row * 1024 + tid * 4) = lw;
    }
}

// ---------------- gate: logits + per-gate softmax, /G folded in ----------------
__global__ __launch_bounds__(128) void gate_kernel(
    const float* __restrict__ h, const float* __restrict__ gW,
    const float* __restrict__ gb, float* __restrict__ coef)
{
    const int t = blockIdx.x, tid = threadIdx.x;
    float acc[16];
#pragma unroll
    for (int j = 0; j < 16; j++) acc[j] = 0.f;
    const float* hr = h + (size_t)t * 1024;
    for (int d = tid; d < 1024; d += 128) {
        float hv = hr[d];
#pragma unroll
        for (int g = 0; g < 2; g++)
#pragma unroll
            for (int e = 0; e < 8; e++)
                acc[g * 8 + e] += hv * gW[g * 8192 + d * 8 + e];
    }
    __shared__ float red[16][4];
#pragma unroll
    for (int j = 0; j < 16; j++) {
        float vv = acc[j];
        for (int off = 16; off; off >>= 1) vv += __shfl_xor_sync(0xffffffffu, vv, off);
        if ((tid & 31) == 0) red[j][tid >> 5] = vv;
    }
    __syncthreads();
    if (tid < 16) {
        float lg = red[tid][0] + red[tid][1] + red[tid][2] + red[tid][3] + gb[tid];
        float mx = lg;
        for (int off = 4; off; off >>= 1) mx = fmaxf(mx, __shfl_xor_sync(0xffffu, mx, off));
        float ex = __expf(lg - mx);
        float smv = ex;
        for (int off = 4; off; off >>= 1) smv += __shfl_xor_sync(0xffffu, smv, off);
        coef[(size_t)t * 16 + tid] = ex / smv * 0.5f;
    }
}

#define ATTN_SMEM (64 * (QS_LD + 64 + 64 + QS_LD) * 4)

extern "C" void kernel_launch(void* const* d_in, const int* in_sizes, int n_in,
                              void* d_out, int out_size)
{
    const float* input  = (const float*)d_in[0];
    const float* Wq     = (const float*)d_in[1];
    const float* bq     = (const float*)d_in[2];
    const float* Wk     = (const float*)d_in[3];
    const float* bk     = (const float*)d_in[4];
    const float* Wv     = (const float*)d_in[5];
    const float* bv     = (const float*)d_in[6];
    const float* Wo     = (const float*)d_in[7];
    const float* bo     = (const float*)d_in[8];
    const float* ln1_g  = (const float*)d_in[9];
    const float* ln1_b  = (const float*)d_in[10];
    const float* gate_W = (const float*)d_in[11];
    const float* gate_b = (const float*)d_in[12];
    const float* eW1    = (const float*)d_in[13];
    const float* eb1    = (const float*)d_in[14];
    const float* eW2    = (const float*)d_in[15];
    const float* eb2    = (const float*)d_in[16];
    const float* ln2_g  = (const float*)d_in[17];
    const float* ln2_b  = (const float*)d_in[18];
    float* out = (float*)d_out;

    float *q, *k, *v, *attn, *x1, *hbuf, *x2, *coef;
    __half *xhi, *xlo, *Wth, *hhi, *hlo, *B1h, *B2h, *hidh;
    cudaGetSymbolAddress((void**)&q,    g_q);
    cudaGetSymbolAddress((void**)&k,    g_k);
    cudaGetSymbolAddress((void**)&v,    g_v);
    cudaGetSymbolAddress((void**)&attn, g_attn);
    cudaGetSymbolAddress((void**)&x1,   g_x1);
    cudaGetSymbolAddress((void**)&hbuf, g_h);
    cudaGetSymbolAddress((void**)&x2,   g_x2);
    cudaGetSymbolAddress((void**)&coef, g_coef);
    cudaGetSymbolAddress((void**)&xhi,  g_xhi);
    cudaGetSymbolAddress((void**)&xlo,  g_xlo);
    cudaGetSymbolAddress((void**)&Wth,  g_Wth);
    cudaGetSymbolAddress((void**)&hhi,  g_hhi);
    cudaGetSymbolAddress((void**)&hlo,  g_hlo);
    cudaGetSymbolAddress((void**)&B1h,  g_B1h);
    cudaGetSymbolAddress((void**)&B2h,  g_B2h);
    cudaGetSymbolAddress((void**)&hidh, g_hidh);

    cudaFuncSetAttribute(attn_kernel, cudaFuncAttributeMaxDynamicSharedMemorySize, ATTN_SMEM);
    cudaFuncSetAttribute((const void*)mma_gemm<0,2,3>, cudaFuncAttributeMaxDynamicSharedMemorySize, SMEM_NT2);
    cudaFuncSetAttribute((const void*)mma_gemm<1,2,3>, cudaFuncAttributeMaxDynamicSharedMemorySize, SMEM_NT2);
    cudaFuncSetAttribute((const void*)mma_gemm<2,1,4>, cudaFuncAttributeMaxDynamicSharedMemorySize, SMEM_NT1);
    cudaFuncSetAttribute((const void*)mma_gemm<3,1,4>, cudaFuncAttributeMaxDynamicSharedMemorySize, SMEM_NT1);

    const int M1 = 1024 * 1024;
    dim3 t32x8(32, 8);
    // weight prep (independent of activations)
    transpose_split_kernel<<<dim3(32, 32, 16), t32x8>>>(eW1, B1h, 0);
    transpose_split_kernel<<<dim3(32, 32, 16), t32x8>>>(eW2, B2h, 1);
    transpose_split_kernel<<<dim3(32, 32, 1), t32x8>>>(Wq, Wth + 0 * M1, 0);
    transpose_split_kernel<<<dim3(32, 32, 1), t32x8>>>(Wk, Wth + 1 * M1, 0);
    transpose_split_kernel<<<dim3(32, 32, 1), t32x8>>>(Wv, Wth + 2 * M1, 0);
    transpose_split_kernel<<<dim3(32, 32, 1), t32x8>>>(Wo, Wth + 3 * M1, 0);
    // split input, QKV projections on tensor path (2-term, 3-stage)
    split_kernel<<<4096, 256>>>(input, xhi, xlo);
    mma_gemm<0,2,3><<<dim3(8, 16), 512, SMEM_NT2>>>(xhi, xlo, 1024, Wth + 0 * M1, 1024,
                                                    bq, nullptr, nullptr, nullptr, q, 1024);
    mma_gemm<0,2,3><<<dim3(8, 16), 512, SMEM_NT2>>>(xhi, xlo, 1024, Wth + 1 * M1, 1024,
                                                    bk, nullptr, nullptr, nullptr, k, 1024);
    mma_gemm<0,2,3><<<dim3(8, 16), 512, SMEM_NT2>>>(xhi, xlo, 1024, Wth + 2 * M1, 1024,
                                                    bv, nullptr, nullptr, nullptr, v, 1024);
    // attention
    attn_kernel<<<dim3(32, 16, 2), 256, ATTN_SMEM>>>(q, k, v, attn);
    // O projection + residual (2-term, reuse xhi/xlo for attn split)
    split_kernel<<<4096, 256>>>(attn, xhi, xlo);
    mma_gemm<1,2,3><<<dim3(8, 16), 512, SMEM_NT2>>>(xhi, xlo, 1024, Wth + 3 * M1, 1024,
                                                    bo, input, nullptr, nullptr, x1, 1024);
    // LN1 (+ fp16 split of h), gates
    ln_kernel<true><<<4096, 256>>>(x1, ln1_g, ln1_b, hbuf, hhi, hlo);
    gate_kernel<<<4096, 128>>>(hbuf, gate_W, gate_b, coef);
    // MoE via mma.sync, pure fp16 (1-term both sides, 4-stage pipeline)
    mma_gemm<2,1,4><<<dim3(128, 16), 512, SMEM_NT1>>>(hhi, nullptr, 1024, B1h, 1024,
                                                      eb1, nullptr, coef, hidh, nullptr, 1024);
    mma_gemm<3,1,4><<<dim3(8, 16), 512, SMEM_NT1>>>(hidh, nullptr, 16384, B2h, 16384,
                                                    eb2, hbuf, coef, nullptr, x2, 16384);
    // LN2 -> output
    ln_kernel<false><<<4096, 256>>>(x2, ln2_g, ln2_b, out, nullptr, nullptr);
}

// round 16
// speedup vs baseline: 2.4920x; 1.0494x over previous
#include <cuda_runtime.h>
#include <cuda_fp16.h>
#include <stdint.h>
#include <math.h>

// Problem constants
#define Bc   2
#define Sc   2048
#define Dc   1024
#define Tc   4096      // B*S tokens

// ---------------- device scratch (no cudaMalloc allowed) ----------------
__device__ float g_q   [4096*1024];
__device__ float g_k   [4096*1024];
__device__ float g_v   [4096*1024];
__device__ float g_attn[4096*1024];
__device__ float g_x1  [4096*1024];
__device__ float g_h   [4096*1024];
__device__ float g_x2  [4096*1024];
__device__ float g_coef[4096*16];
__device__ __half g_xh  [4096*1024];   // fp16 of input / attn out
__device__ __half g_Wth [4*1024*1024]; // Wq,Wk,Wv,Wo transposed (fp16)
__device__ __half g_hh  [4096*1024];   // fp16 of h
__device__ __half g_B1h [16777216];    // [16384 n][1024 k] fp16
__device__ __half g_B2h [16777216];    // [1024 d][16384 k] fp16
__device__ __half g_hidh[67108864];    // [4096][16384] fp16

// ======================= helpers =======================
__device__ __forceinline__ uint32_t smem_to_u32(const void* p) {
    uint32_t a;
    asm("{ .reg .u64 t; cvta.to.shared.u64 t, %1; cvt.u32.u64 %0, t; }" : "=r"(a) : "l"(p));
    return a;
}
__device__ __forceinline__ void cp_async16(uint32_t saddr, const void* gaddr) {
    asm volatile("cp.async.cg.shared.global [%0], [%1], 16;" :: "r"(saddr), "l"(gaddr));
}
#define CP_COMMIT() asm volatile("cp.async.commit_group;" ::: "memory")
#define CP_WAIT(n)  asm volatile("cp.async.wait_group %0;" :: "n"(n) : "memory")

__device__ __forceinline__ void ldsm_x4(uint32_t* r, uint32_t a) {
    asm volatile("ldmatrix.sync.aligned.m8n8.x4.shared.b16 {%0,%1,%2,%3}, [%4];"
                 : "=r"(r[0]), "=r"(r[1]), "=r"(r[2]), "=r"(r[3]) : "r"(a));
}
__device__ __forceinline__ void mma16816(float* c, const uint32_t* a, const uint32_t* b) {
    asm volatile("mma.sync.aligned.m16n8k16.row.col.f32.f16.f16.f32 "
                 "{%0,%1,%2,%3}, {%4,%5,%6,%7}, {%8,%9}, {%0,%1,%2,%3};"
                 : "+f"(c[0]), "+f"(c[1]), "+f"(c[2]), "+f"(c[3])
                 : "r"(a[0]), "r"(a[1]), "r"(a[2]), "r"(a[3]), "r"(b[0]), "r"(b[1]));
}

// ============ mma.sync GEMM: 256x128 CTA tile, fp16 ============
// A[row][k] fp16; B[n][k] fp16 (K-major).
// MODE 0: C = A@B + bias                         -> fp32  (ldOut 1024)
// MODE 1: C = A@B + bias + res                   -> fp32  (ldOut 1024)
// MODE 2: hid = coef[t,e]*relu(A@B + b1)         -> fp16  (ldOut 16384)
// MODE 3: x2  = A@B + sum_e coef*b2[e] + res     -> fp32  (ldOut 1024)
// 4-stage cp.async pipeline (wait_group 2).
#define STAGES 4
#define CHUNK  30720          // A 256x80 (20480) + B 128x80 (10240)
#define MMG_SMEM (STAGES * CHUNK + 8192)   // 131072
template<int MODE>
__global__ __launch_bounds__(512, 1) void mma_gemm(
    const __half* __restrict__ Ah, int lda,
    const __half* __restrict__ Bh, int ldb,
    const float* __restrict__ bias, const float* __restrict__ res,
    const float* __restrict__ coef,
    __half* __restrict__ Oh, float* __restrict__ Of, int K)
{
    extern __shared__ char smem[];
    const int tid  = threadIdx.x;
    const int lane = tid & 31, wid = tid >> 5;
    const int wm = wid & 7, wn = wid >> 3;  // warp grid 8m x 2n, warp tile 32x64
    const int row0 = blockIdx.y * 256, col0 = blockIdx.x * 128;
    uint32_t sb = smem_to_u32(smem);

    float* bias_sm = (float*)(smem + STAGES * CHUNK);
    if (MODE == 3) {
        for (int i = tid; i < 2048; i += 512)
            bias_sm[i] = bias[(i >> 7) * 1024 + col0 + (i & 127)];
    }

    float acc[2][8][4];
#pragma unroll
    for (int mi = 0; mi < 2; mi++)
#pragma unroll
        for (int ni = 0; ni < 8; ni++)
#pragma unroll
            for (int q = 0; q < 4; q++) acc[mi][ni][q] = 0.f;

    auto issue_chunk = [&](int c) {
        const int kb = c * 32;
        uint32_t bufu = sb + (c % STAGES) * CHUNK;
#pragma unroll
        for (int it = 0; it < 3; it++) {
            int idx = tid + it * 512;           // 0..1535
            const __half* src;
            uint32_t dst;
            if (idx < 1024) {                   // A: 256 rows x 4 segs
                int r = idx >> 2, s = idx & 3;
                src = Ah + (size_t)(row0 + r) * lda + kb + s * 8;
                dst = bufu + r * 80 + s * 16;
            } else {                            // B: 128 rows x 4 segs
                int i2 = idx - 1024;
                int r = i2 >> 2, s = i2 & 3;
                src = Bh + (size_t)(col0 + r) * ldb + kb + s * 8;
                dst = bufu + 20480 + r * 80 + s * 16;
            }
            cp_async16(dst, src);
        }
        CP_COMMIT();
    };

    const int NC = K / 32;
#pragma unroll
    for (int s = 0; s < STAGES - 1; s++)
        if (s < NC) issue_chunk(s);
    for (int c = 0; c < NC; c++) {
        CP_WAIT(STAGES - 2);
        __syncthreads();
        if (c + STAGES - 1 < NC) issue_chunk(c + STAGES - 1);
        uint32_t base = sb + (c % STAGES) * CHUNK;
        uint32_t aAh = base + (wm * 32 + (lane & 15)) * 80 + (lane >> 4) * 16;
#pragma unroll
        for (int kk = 0; kk < 2; kk++) {
            uint32_t ah[2][4];
            ldsm_x4(ah[0], aAh + kk * 32);
            ldsm_x4(ah[1], aAh + 16 * 80 + kk * 32);
#pragma unroll
            for (int g = 0; g < 2; g++) {
                // B frags for ni = g*4..g*4+3: 2 x ldsm_x4, each covering an ni pair
                uint32_t bf[8];
#pragma unroll
                for (int pr = 0; pr < 2; pr++) {
                    uint32_t ab = base + 20480
                        + (wn * 64 + (g * 4 + pr * 2 + (lane >> 4)) * 8 + (lane & 7)) * 80
                        + ((lane >> 3) & 1) * 16 + kk * 32;
                    ldsm_x4(&bf[pr * 4], ab);
                }
#pragma unroll
                for (int j = 0; j < 4; j++) {
                    mma16816(acc[0][g * 4 + j], ah[0], &bf[j * 2]);
                    mma16816(acc[1][g * 4 + j], ah[1], &bf[j * 2]);
                }
            }
        }
    }

    if (MODE == 2) {
        const int e  = col0 >> 10;
        const int cb = col0 & 1023;
        int   rr[2][2];
        float cf[2][2];
#pragma unroll
        for (int mi = 0; mi < 2; mi++)
#pragma unroll
            for (int h = 0; h < 2; h++) {
                rr[mi][h] = row0 + wm * 32 + mi * 16 + (lane >> 2) + 8 * h;
                cf[mi][h] = coef[(size_t)rr[mi][h] * 16 + e];
            }
#pragma unroll
        for (int mi = 0; mi < 2; mi++)
#pragma unroll
        for (int ni = 0; ni < 8; ni++) {
            int cl = wn * 64 + ni * 8 + (lane & 3) * 2;
            float b0 = bias[e * 1024 + cb + cl];
            float b1 = bias[e * 1024 + cb + cl + 1];
#pragma unroll
            for (int h = 0; h < 2; h++) {
                float v0 = fmaxf(acc[mi][ni][2 * h + 0] + b0, 0.f) * cf[mi][h];
                float v1 = fmaxf(acc[mi][ni][2 * h + 1] + b1, 0.f) * cf[mi][h];
                __half2 h2 = __floats2half2_rn(v0, v1);
                size_t o = (size_t)rr[mi][h] * 16384 + col0 + cl;
                *(__half2*)(Oh + o) = h2;
            }
        }
    } else if (MODE == 3) {
#pragma unroll
        for (int mi = 0; mi < 2; mi++)
#pragma unroll
        for (int h = 0; h < 2; h++) {
            int r2 = row0 + wm * 32 + mi * 16 + (lane >> 2) + 8 * h;
            float cf16[16];
#pragma unroll
            for (int e2 = 0; e2 < 4; e2++)
                *(float4*)&cf16[e2 * 4] = *(const float4*)(coef + (size_t)r2 * 16 + e2 * 4);
#pragma unroll
            for (int ni = 0; ni < 8; ni++) {
                int cl = wn * 64 + ni * 8 + (lane & 3) * 2;
                float2 rv = *(const float2*)(res + (size_t)r2 * 1024 + col0 + cl);
                float v0 = acc[mi][ni][2 * h + 0] + rv.x;
                float v1 = acc[mi][ni][2 * h + 1] + rv.y;
#pragma unroll
                for (int e2 = 0; e2 < 16; e2++) {
                    v0 += cf16[e2] * bias_sm[e2 * 128 + cl];
                    v1 += cf16[e2] * bias_sm[e2 * 128 + cl + 1];
                }
                float2 ov; ov.x = v0; ov.y = v1;
                *(float2*)(Of + (size_t)r2 * 1024 + col0 + cl) = ov;
            }
        }
    } else {
#pragma unroll
        for (int mi = 0; mi < 2; mi++)
#pragma unroll
        for (int h = 0; h < 2; h++) {
            int r2 = row0 + wm * 32 + mi * 16 + (lane >> 2) + 8 * h;
#pragma unroll
            for (int ni = 0; ni < 8; ni++) {
                int cl = wn * 64 + ni * 8 + (lane & 3) * 2;
                float v0 = acc[mi][ni][2 * h + 0] + bias[col0 + cl];
                float v1 = acc[mi][ni][2 * h + 1] + bias[col0 + cl + 1];
                if (MODE == 1) {
                    float2 rv = *(const float2*)(res + (size_t)r2 * 1024 + col0 + cl);
                    v0 += rv.x; v1 += rv.y;
                }
                float2 ov; ov.x = v0; ov.y = v1;
                *(float2*)(Of + (size_t)r2 * 1024 + col0 + cl) = ov;
            }
        }
    }
}

// ---------- 1024x1024 transpose + fp16 convert (per expert / weight) ----------
__global__ __launch_bounds__(256) void transpose_split_kernel(
    const float* __restrict__ in, __half* __restrict__ ohi, int mode)
{
    __shared__ float tsm[32][33];
    const int e = blockIdx.z;
    const int kt = blockIdx.x, nt = blockIdx.y;
    const float* ip = in + ((size_t)e << 20);
    const int tx = threadIdx.x, ty = threadIdx.y;   // 32 x 8
    for (int yy = ty; yy < 32; yy += 8)
        tsm[yy][tx] = ip[(size_t)(kt * 32 + yy) * 1024 + nt * 32 + tx];
    __syncthreads();
    for (int yy = ty; yy < 32; yy += 8) {
        int n = nt * 32 + yy, k = kt * 32 + tx;
        float v = tsm[tx][yy];
        size_t o = (mode == 0) ? ((size_t)(e * 1024 + n) * 1024 + k)
                               : ((size_t)n * 16384 + e * 1024 + k);
        ohi[o] = __float2half_rn(v);
    }
}

// ---------- elementwise fp32 -> fp16 convert ----------
__global__ __launch_bounds__(256) void cvt_kernel(
    const float* __restrict__ x, __half* __restrict__ hi)
{
    size_t i = ((size_t)blockIdx.x * 256 + threadIdx.x) * 4;
    float4 v = *(const float4*)(x + i);
    __half2 h0 = __floats2half2_rn(v.x, v.y);
    __half2 h1 = __floats2half2_rn(v.z, v.w);
    uint2 hw; hw.x = *(uint32_t*)&h0; hw.y = *(uint32_t*)&h1;
    *(uint2*)(hi + i) = hw;
}

// ---------------- flash attention, 64x64 tiles, causal ----------------
#define QS_LD 68
__global__ __launch_bounds__(256) void attn_kernel(
    const float* __restrict__ q, const float* __restrict__ k,
    const float* __restrict__ v, float* __restrict__ o)
{
    extern __shared__ float sm[];
    float* Qs = sm;
    float* Kt = sm + 64 * QS_LD;
    float* Vs = Kt + 64 * 64;
    float* Ps = Vs + 64 * 64;

    const int tid = threadIdx.x;
    const int qb = blockIdx.x, h = blockIdx.y, b = blockIdx.z;
    const size_t base = ((size_t)b * Sc) * Dc + h * 64;

#pragma unroll
    for (int it = 0; it < 4; it++) {
        int f = tid + it * 256;
        int rr = f >> 4, d4 = (f & 15) << 2;
        *(float4*)&Qs[rr * QS_LD + d4] =
            *(const float4*)(q + base + (size_t)(qb * 64 + rr) * Dc + d4);
    }

    const int r = tid >> 2, cg = tid & 3;
    const int qi = qb * 64 + r;
    float out[16];
#pragma unroll
    for (int j2 = 0; j2 < 16; j2++) out[j2] = 0.f;
    float mrun = -1e30f, lrun = 0.f;

    for (int kb = 0; kb <= qb; kb++) {
        __syncthreads();
#pragma unroll
        for (int it = 0; it < 4; it++) {
            int f = tid + it * 256;
            int rr = f >> 4, d4 = (f & 15) << 2;
            float4 kv = *(const float4*)(k + base + (size_t)(kb * 64 + rr) * Dc + d4);
            Kt[(d4 + 0) * 64 + rr] = kv.x; Kt[(d4 + 1) * 64 + rr] = kv.y;
            Kt[(d4 + 2) * 64 + rr] = kv.z; Kt[(d4 + 3) * 64 + rr] = kv.w;
            *(float4*)&Vs[rr * 64 + d4] =
                *(const float4*)(v + base + (size_t)(kb * 64 + rr) * Dc + d4);
        }
        __syncthreads();

        float s[16];
#pragma unroll
        for (int c = 0; c < 16; c++) s[c] = 0.f;
#pragma unroll 4
        for (int d = 0; d < 64; d++) {
            float qv = Qs[r * QS_LD + d];
            const float* kp = &Kt[d * 64 + cg * 16];
            float4 k0 = *(const float4*)(kp);
            float4 k1 = *(const float4*)(kp + 4);
            float4 k2 = *(const float4*)(kp + 8);
            float4 k3 = *(const float4*)(kp + 12);
            s[0] += qv * k0.x; s[1] += qv * k0.y; s[2] += qv * k0.z; s[3] += qv * k0.w;
            s[4] += qv * k1.x; s[5] += qv * k1.y; s[6] += qv * k1.z; s[7] += qv * k1.w;
            s[8] += qv * k2.x; s[9] += qv * k2.y; s[10]+= qv * k2.z; s[11]+= qv * k2.w;
            s[12]+= qv * k3.x; s[13]+= qv * k3.y; s[14]+= qv * k3.z; s[15]+= qv * k3.w;
        }

        float mloc = -1e30f;
#pragma unroll
        for (int c = 0; c < 16; c++) {
            float sv = s[c] * 0.125f;
            int kj = kb * 64 + cg * 16 + c;
            if (kj > qi) sv = -1e9f;
            s[c] = sv;
            mloc = fmaxf(mloc, sv);
        }
        mloc = fmaxf(mloc, __shfl_xor_sync(0xffffffffu, mloc, 1));
        mloc = fmaxf(mloc, __shfl_xor_sync(0xffffffffu, mloc, 2));
        const float mnew = fmaxf(mrun, mloc);
        const float alpha = __expf(mrun - mnew);
        float lloc = 0.f;
#pragma unroll
        for (int c = 0; c < 16; c++) { float p = __expf(s[c] - mnew); s[c] = p; lloc += p; }
        lloc += __shfl_xor_sync(0xffffffffu, lloc, 1);
        lloc += __shfl_xor_sync(0xffffffffu, lloc, 2);
        lrun = lrun * alpha + lloc;
        mrun = mnew;
#pragma unroll
        for (int j2 = 0; j2 < 16; j2++) out[j2] *= alpha;

#pragma unroll
        for (int c = 0; c < 16; c++) Ps[r * QS_LD + cg * 16 + c] = s[c];
        __syncwarp();

#pragma unroll 2
        for (int c = 0; c < 64; c++) {
            float p = Ps[r * QS_LD + c];
            const float* vp = &Vs[c * 64 + cg * 16];
            float4 v0 = *(const float4*)vp, v1 = *(const float4*)(vp + 4);
            float4 v2 = *(const float4*)(vp + 8), v3 = *(const float4*)(vp + 12);
            out[0] += p * v0.x; out[1] += p * v0.y; out[2] += p * v0.z; out[3] += p * v0.w;
            out[4] += p * v1.x; out[5] += p * v1.y; out[6] += p * v1.z; out[7] += p * v1.w;
            out[8] += p * v2.x; out[9] += p * v2.y; out[10]+= p * v2.z; out[11]+= p * v2.w;
            out[12]+= p * v3.x; out[13]+= p * v3.y; out[14]+= p * v3.z; out[15]+= p * v3.w;
        }
    }

    const float invl = 1.f / lrun;
#pragma unroll
    for (int j2 = 0; j2 < 16; j2++)
        o[base + (size_t)qi * Dc + cg * 16 + j2] = out[j2] * invl;
}

// ---------------- LayerNorm (optionally emits fp16) ----------------
template<bool SPLIT>
__global__ __launch_bounds__(256) void ln_kernel(
    const float* __restrict__ x, const float* __restrict__ gam,
    const float* __restrict__ bet, float* __restrict__ o,
    __half* __restrict__ ohi)
{
    const int row = blockIdx.x, tid = threadIdx.x;
    const float4 v = *(const float4*)(x + (size_t)row * 1024 + tid * 4);
    float s = v.x + v.y + v.z + v.w;
    float q = v.x * v.x + v.y * v.y + v.z * v.z + v.w * v.w;
#pragma unroll
    for (int off = 16; off; off >>= 1) {
        s += __shfl_xor_sync(0xffffffffu, s, off);
        q += __shfl_xor_sync(0xffffffffu, q, off);
    }
    __shared__ float ss[8], sq[8];
    if ((tid & 31) == 0) { ss[tid >> 5] = s; sq[tid >> 5] = q; }
    __syncthreads();
    float S = 0.f, Q = 0.f;
#pragma unroll
    for (int w = 0; w < 8; w++) { S += ss[w]; Q += sq[w]; }
    const float mu = S * (1.f / 1024.f);
    const float var = Q * (1.f / 1024.f) - mu * mu;
    const float inv = rsqrtf(var + 1e-5f);
    float4 g4 = *(const float4*)(gam + tid * 4);
    float4 b4 = *(const float4*)(bet + tid * 4);
    float4 r4;
    r4.x = (v.x - mu) * inv * g4.x + b4.x;
    r4.y = (v.y - mu) * inv * g4.y + b4.y;
    r4.z = (v.z - mu) * inv * g4.z + b4.z;
    r4.w = (v.w - mu) * inv * g4.w + b4.w;
    *(float4*)(o + (size_t)row * 1024 + tid * 4) = r4;
    if (SPLIT) {
        __half2 h0 = __floats2half2_rn(r4.x, r4.y);
        __half2 h1 = __floats2half2_rn(r4.z, r4.w);
        uint2 hw; hw.x = *(uint32_t*)&h0; hw.y = *(uint32_t*)&h1;
        *(uint2*)(ohi + (size_t)row * 1024 + tid * 4) = hw;
    }
}

// ---------------- gate: logits + per-gate softmax, /G folded in ----------------
__global__ __launch_bounds__(128) void gate_kernel(
    const float* __restrict__ h, const float* __restrict__ gW,
    const float* __restrict__ gb, float* __restrict__ coef)
{
    const int t = blockIdx.x, tid = threadIdx.x;
    float acc[16];
#pragma unroll
    for (int j = 0; j < 16; j++) acc[j] = 0.f;
    const float* hr = h + (size_t)t * 1024;
    for (int d = tid; d < 1024; d += 128) {
        float hv = hr[d];
#pragma unroll
        for (int g = 0; g < 2; g++)
#pragma unroll
            for (int e = 0; e < 8; e++)
                acc[g * 8 + e] += hv * gW[g * 8192 + d * 8 + e];
    }
    __shared__ float red[16][4];
#pragma unroll
    for (int j = 0; j < 16; j++) {
        float vv = acc[j];
        for (int off = 16; off; off >>= 1) vv += __shfl_xor_sync(0xffffffffu, vv, off);
        if ((tid & 31) == 0) red[j][tid >> 5] = vv;
    }
    __syncthreads();
    if (tid < 16) {
        float lg = red[tid][0] + red[tid][1] + red[tid][2] + red[tid][3] + gb[tid];
        float mx = lg;
        for (int off = 4; off; off >>= 1) mx = fmaxf(mx, __shfl_xor_sync(0xffffu, mx, off));
        float ex = __expf(lg - mx);
        float smv = ex;
        for (int off = 4; off; off >>= 1) smv += __shfl_xor_sync(0xffffu, smv, off);
        coef[(size_t)t * 16 + tid] = ex / smv * 0.5f;
    }
}

#define ATTN_SMEM (64 * (QS_LD + 64 + 64 + QS_LD) * 4)

extern "C" void kernel_launch(void* const* d_in, const int* in_sizes, int n_in,
                              void* d_out, int out_size)
{
    const float* input  = (const float*)d_in[0];
    const float* Wq     = (const float*)d_in[1];
    const float* bq     = (const float*)d_in[2];
    const float* Wk     = (const float*)d_in[3];
    const float* bk     = (const float*)d_in[4];
    const float* Wv     = (const float*)d_in[5];
    const float* bv     = (const float*)d_in[6];
    const float* Wo     = (const float*)d_in[7];
    const float* bo     = (const float*)d_in[8];
    const float* ln1_g  = (const float*)d_in[9];
    const float* ln1_b  = (const float*)d_in[10];
    const float* gate_W = (const float*)d_in[11];
    const float* gate_b = (const float*)d_in[12];
    const float* eW1    = (const float*)d_in[13];
    const float* eb1    = (const float*)d_in[14];
    const float* eW2    = (const float*)d_in[15];
    const float* eb2    = (const float*)d_in[16];
    const float* ln2_g  = (const float*)d_in[17];
    const float* ln2_b  = (const float*)d_in[18];
    float* out = (float*)d_out;

    float *q, *k, *v, *attn, *x1, *hbuf, *x2, *coef;
    __half *xh, *Wth, *hh, *B1h, *B2h, *hidh;
    cudaGetSymbolAddress((void**)&q,    g_q);
    cudaGetSymbolAddress((void**)&k,    g_k);
    cudaGetSymbolAddress((void**)&v,    g_v);
    cudaGetSymbolAddress((void**)&attn, g_attn);
    cudaGetSymbolAddress((void**)&x1,   g_x1);
    cudaGetSymbolAddress((void**)&hbuf, g_h);
    cudaGetSymbolAddress((void**)&x2,   g_x2);
    cudaGetSymbolAddress((void**)&coef, g_coef);
    cudaGetSymbolAddress((void**)&xh,   g_xh);
    cudaGetSymbolAddress((void**)&Wth,  g_Wth);
    cudaGetSymbolAddress((void**)&hh,   g_hh);
    cudaGetSymbolAddress((void**)&B1h,  g_B1h);
    cudaGetSymbolAddress((void**)&B2h,  g_B2h);
    cudaGetSymbolAddress((void**)&hidh, g_hidh);

    cudaFuncSetAttribute(attn_kernel, cudaFuncAttributeMaxDynamicSharedMemorySize, ATTN_SMEM);
    cudaFuncSetAttribute((const void*)mma_gemm<0>, cudaFuncAttributeMaxDynamicSharedMemorySize, MMG_SMEM);
    cudaFuncSetAttribute((const void*)mma_gemm<1>, cudaFuncAttributeMaxDynamicSharedMemorySize, MMG_SMEM);
    cudaFuncSetAttribute((const void*)mma_gemm<2>, cudaFuncAttributeMaxDynamicSharedMemorySize, MMG_SMEM);
    cudaFuncSetAttribute((const void*)mma_gemm<3>, cudaFuncAttributeMaxDynamicSharedMemorySize, MMG_SMEM);

    const int M1 = 1024 * 1024;
    dim3 t32x8(32, 8);
    // weight prep (independent of activations)
    transpose_split_kernel<<<dim3(32, 32, 16), t32x8>>>(eW1, B1h, 0);
    transpose_split_kernel<<<dim3(32, 32, 16), t32x8>>>(eW2, B2h, 1);
    transpose_split_kernel<<<dim3(32, 32, 1), t32x8>>>(Wq, Wth + 0 * M1, 0);
    transpose_split_kernel<<<dim3(32, 32, 1), t32x8>>>(Wk, Wth + 1 * M1, 0);
    transpose_split_kernel<<<dim3(32, 32, 1), t32x8>>>(Wv, Wth + 2 * M1, 0);
    transpose_split_kernel<<<dim3(32, 32, 1), t32x8>>>(Wo, Wth + 3 * M1, 0);
    // convert input, QKV projections (1-term fp16)
    cvt_kernel<<<4096, 256>>>(input, xh);
    mma_gemm<0><<<dim3(8, 16), 512, MMG_SMEM>>>(xh, 1024, Wth + 0 * M1, 1024,
                                                bq, nullptr, nullptr, nullptr, q, 1024);
    mma_gemm<0><<<dim3(8, 16), 512, MMG_SMEM>>>(xh, 1024, Wth + 1 * M1, 1024,
                                                bk, nullptr, nullptr, nullptr, k, 1024);
    mma_gemm<0><<<dim3(8, 16), 512, MMG_SMEM>>>(xh, 1024, Wth + 2 * M1, 1024,
                                                bv, nullptr, nullptr, nullptr, v, 1024);
    // attention
    attn_kernel<<<dim3(32, 16, 2), 256, ATTN_SMEM>>>(q, k, v, attn);
    // O projection + residual (reuse xh for attn fp16)
    cvt_kernel<<<4096, 256>>>(attn, xh);
    mma_gemm<1><<<dim3(8, 16), 512, MMG_SMEM>>>(xh, 1024, Wth + 3 * M1, 1024,
                                                bo, input, nullptr, nullptr, x1, 1024);
    // LN1 (+ fp16 h), gates
    ln_kernel<true><<<4096, 256>>>(x1, ln1_g, ln1_b, hbuf, hh);
    gate_kernel<<<4096, 128>>>(hbuf, gate_W, gate_b, coef);
    // MoE (pure fp16)
    mma_gemm<2><<<dim3(128, 16), 512, MMG_SMEM>>>(hh, 1024, B1h, 1024,
                                                  eb1, nullptr, coef, hidh, nullptr, 1024);
    mma_gemm<3><<<dim3(8, 16), 512, MMG_SMEM>>>(hidh, 16384, B2h, 16384,
                                                eb2, hbuf, coef, nullptr, x2, 16384);
    // LN2 -> output
    ln_kernel<false><<<4096, 256>>>(x2, ln2_g, ln2_b, out, nullptr);
}

// round 17
// speedup vs baseline: 6.8880x; 2.7640x over previous
#include <cuda_runtime.h>
#include <cuda_fp16.h>
#include <stdint.h>
#include <math.h>

// Problem constants
#define Bc   2
#define Sc   2048
#define Dc   1024
#define Tc   4096      // B*S tokens

// ---------------- device scratch (no cudaMalloc allowed) ----------------
__device__ __half g_q   [4096*1024];
__device__ __half g_k   [4096*1024];
__device__ __half g_v   [4096*1024];
__device__ __half g_attn[4096*1024];
__device__ float g_x1  [4096*1024];
__device__ float g_h   [4096*1024];
__device__ float g_x2  [4096*1024];
__device__ float g_coef[4096*16];
__device__ __half g_xh  [4096*1024];   // fp16 of input
__device__ __half g_Wth [4*1024*1024]; // Wq,Wk,Wv,Wo transposed (fp16)
__device__ __half g_hh  [4096*1024];   // fp16 of h
__device__ __half g_B1h [16777216];    // [16384 n][1024 k] fp16
__device__ __half g_B2h [16777216];    // [1024 d][16384 k] fp16
__device__ __half g_hidh[67108864];    // [4096][16384] fp16

// ======================= helpers =======================
__device__ __forceinline__ uint32_t smem_to_u32(const void* p) {
    uint32_t a;
    asm("{ .reg .u64 t; cvta.to.shared.u64 t, %1; cvt.u32.u64 %0, t; }" : "=r"(a) : "l"(p));
    return a;
}
__device__ __forceinline__ void cp_async16(uint32_t saddr, const void* gaddr) {
    asm volatile("cp.async.cg.shared.global [%0], [%1], 16;" :: "r"(saddr), "l"(gaddr));
}
#define CP_COMMIT() asm volatile("cp.async.commit_group;" ::: "memory")
#define CP_WAIT(n)  asm volatile("cp.async.wait_group %0;" :: "n"(n) : "memory")

__device__ __forceinline__ void ldsm_x4(uint32_t* r, uint32_t a) {
    asm volatile("ldmatrix.sync.aligned.m8n8.x4.shared.b16 {%0,%1,%2,%3}, [%4];"
                 : "=r"(r[0]), "=r"(r[1]), "=r"(r[2]), "=r"(r[3]) : "r"(a));
}
__device__ __forceinline__ void ldsm_x4_t(uint32_t* r, uint32_t a) {
    asm volatile("ldmatrix.sync.aligned.m8n8.x4.trans.shared.b16 {%0,%1,%2,%3}, [%4];"
                 : "=r"(r[0]), "=r"(r[1]), "=r"(r[2]), "=r"(r[3]) : "r"(a));
}
__device__ __forceinline__ void mma16816(float* c, const uint32_t* a, const uint32_t* b) {
    asm volatile("mma.sync.aligned.m16n8k16.row.col.f32.f16.f16.f32 "
                 "{%0,%1,%2,%3}, {%4,%5,%6,%7}, {%8,%9}, {%0,%1,%2,%3};"
                 : "+f"(c[0]), "+f"(c[1]), "+f"(c[2]), "+f"(c[3])
                 : "r"(a[0]), "r"(a[1]), "r"(a[2]), "r"(a[3]), "r"(b[0]), "r"(b[1]));
}

// ============ mma.sync GEMM: 256x128 CTA tile, fp16 ============
// A[row][k] fp16; B[n][k] fp16 (K-major).
// MODE 0: C = A@B + bias                         -> fp16  (ldOut 1024)
// MODE 1: C = A@B + bias + res                   -> fp32  (ldOut 1024)
// MODE 2: hid = coef[t,e]*relu(A@B + b1)         -> fp16  (ldOut 16384)
// MODE 3: x2  = A@B + sum_e coef*b2[e] + res     -> fp32  (ldOut 1024)
#define STAGES 4
#define CHUNK  30720          // A 256x80 (20480) + B 128x80 (10240)
#define MMG_SMEM (STAGES * CHUNK + 8192)   // 131072
template<int MODE>
__global__ __launch_bounds__(512, 1) void mma_gemm(
    const __half* __restrict__ Ah, int lda,
    const __half* __restrict__ Bh, int ldb,
    const float* __restrict__ bias, const float* __restrict__ res,
    const float* __restrict__ coef,
    __half* __restrict__ Oh, float* __restrict__ Of, int K)
{
    extern __shared__ char smem[];
    const int tid  = threadIdx.x;
    const int lane = tid & 31, wid = tid >> 5;
    const int wm = wid & 7, wn = wid >> 3;  // warp grid 8m x 2n, warp tile 32x64
    const int row0 = blockIdx.y * 256, col0 = blockIdx.x * 128;
    uint32_t sb = smem_to_u32(smem);

    float* bias_sm = (float*)(smem + STAGES * CHUNK);
    if (MODE == 3) {
        for (int i = tid; i < 2048; i += 512)
            bias_sm[i] = bias[(i >> 7) * 1024 + col0 + (i & 127)];
    }

    float acc[2][8][4];
#pragma unroll
    for (int mi = 0; mi < 2; mi++)
#pragma unroll
        for (int ni = 0; ni < 8; ni++)
#pragma unroll
            for (int q = 0; q < 4; q++) acc[mi][ni][q] = 0.f;

    auto issue_chunk = [&](int c) {
        const int kb = c * 32;
        uint32_t bufu = sb + (c % STAGES) * CHUNK;
#pragma unroll
        for (int it = 0; it < 3; it++) {
            int idx = tid + it * 512;           // 0..1535
            const __half* src;
            uint32_t dst;
            if (idx < 1024) {                   // A: 256 rows x 4 segs
                int r = idx >> 2, s = idx & 3;
                src = Ah + (size_t)(row0 + r) * lda + kb + s * 8;
                dst = bufu + r * 80 + s * 16;
            } else {                            // B: 128 rows x 4 segs
                int i2 = idx - 1024;
                int r = i2 >> 2, s = i2 & 3;
                src = Bh + (size_t)(col0 + r) * ldb + kb + s * 8;
                dst = bufu + 20480 + r * 80 + s * 16;
            }
            cp_async16(dst, src);
        }
        CP_COMMIT();
    };

    const int NC = K / 32;
#pragma unroll
    for (int s = 0; s < STAGES - 1; s++)
        if (s < NC) issue_chunk(s);
    for (int c = 0; c < NC; c++) {
        CP_WAIT(STAGES - 2);
        __syncthreads();
        if (c + STAGES - 1 < NC) issue_chunk(c + STAGES - 1);
        uint32_t base = sb + (c % STAGES) * CHUNK;
        uint32_t aAh = base + (wm * 32 + (lane & 15)) * 80 + (lane >> 4) * 16;
#pragma unroll
        for (int kk = 0; kk < 2; kk++) {
            uint32_t ah[2][4];
            ldsm_x4(ah[0], aAh + kk * 32);
            ldsm_x4(ah[1], aAh + 16 * 80 + kk * 32);
#pragma unroll
            for (int g = 0; g < 2; g++) {
                uint32_t bf[8];
#pragma unroll
                for (int pr = 0; pr < 2; pr++) {
                    uint32_t ab = base + 20480
                        + (wn * 64 + (g * 4 + pr * 2 + (lane >> 4)) * 8 + (lane & 7)) * 80
                        + ((lane >> 3) & 1) * 16 + kk * 32;
                    ldsm_x4(&bf[pr * 4], ab);
                }
#pragma unroll
                for (int j = 0; j < 4; j++) {
                    mma16816(acc[0][g * 4 + j], ah[0], &bf[j * 2]);
                    mma16816(acc[1][g * 4 + j], ah[1], &bf[j * 2]);
                }
            }
        }
    }

    if (MODE == 2) {
        const int e  = col0 >> 10;
        const int cb = col0 & 1023;
        int   rr[2][2];
        float cf[2][2];
#pragma unroll
        for (int mi = 0; mi < 2; mi++)
#pragma unroll
            for (int h = 0; h < 2; h++) {
                rr[mi][h] = row0 + wm * 32 + mi * 16 + (lane >> 2) + 8 * h;
                cf[mi][h] = coef[(size_t)rr[mi][h] * 16 + e];
            }
#pragma unroll
        for (int mi = 0; mi < 2; mi++)
#pragma unroll
        for (int ni = 0; ni < 8; ni++) {
            int cl = wn * 64 + ni * 8 + (lane & 3) * 2;
            float b0 = bias[e * 1024 + cb + cl];
            float b1 = bias[e * 1024 + cb + cl + 1];
#pragma unroll
            for (int h = 0; h < 2; h++) {
                float v0 = fmaxf(acc[mi][ni][2 * h + 0] + b0, 0.f) * cf[mi][h];
                float v1 = fmaxf(acc[mi][ni][2 * h + 1] + b1, 0.f) * cf[mi][h];
                __half2 h2 = __floats2half2_rn(v0, v1);
                size_t o = (size_t)rr[mi][h] * 16384 + col0 + cl;
                *(__half2*)(Oh + o) = h2;
            }
        }
    } else if (MODE == 3) {
#pragma unroll
        for (int mi = 0; mi < 2; mi++)
#pragma unroll
        for (int h = 0; h < 2; h++) {
            int r2 = row0 + wm * 32 + mi * 16 + (lane >> 2) + 8 * h;
            float cf16[16];
#pragma unroll
            for (int e2 = 0; e2 < 4; e2++)
                *(float4*)&cf16[e2 * 4] = *(const float4*)(coef + (size_t)r2 * 16 + e2 * 4);
#pragma unroll
            for (int ni = 0; ni < 8; ni++) {
                int cl = wn * 64 + ni * 8 + (lane & 3) * 2;
                float2 rv = *(const float2*)(res + (size_t)r2 * 1024 + col0 + cl);
                float v0 = acc[mi][ni][2 * h + 0] + rv.x;
                float v1 = acc[mi][ni][2 * h + 1] + rv.y;
#pragma unroll
                for (int e2 = 0; e2 < 16; e2++) {
                    v0 += cf16[e2] * bias_sm[e2 * 128 + cl];
                    v1 += cf16[e2] * bias_sm[e2 * 128 + cl + 1];
                }
                float2 ov; ov.x = v0; ov.y = v1;
                *(float2*)(Of + (size_t)r2 * 1024 + col0 + cl) = ov;
            }
        }
    } else if (MODE == 1) {
#pragma unroll
        for (int mi = 0; mi < 2; mi++)
#pragma unroll
        for (int h = 0; h < 2; h++) {
            int r2 = row0 + wm * 32 + mi * 16 + (lane >> 2) + 8 * h;
#pragma unroll
            for (int ni = 0; ni < 8; ni++) {
                int cl = wn * 64 + ni * 8 + (lane & 3) * 2;
                float2 rv = *(const float2*)(res + (size_t)r2 * 1024 + col0 + cl);
                float v0 = acc[mi][ni][2 * h + 0] + bias[col0 + cl] + rv.x;
                float v1 = acc[mi][ni][2 * h + 1] + bias[col0 + cl + 1] + rv.y;
                float2 ov; ov.x = v0; ov.y = v1;
                *(float2*)(Of + (size_t)r2 * 1024 + col0 + cl) = ov;
            }
        }
    } else {   // MODE 0: fp16 out
#pragma unroll
        for (int mi = 0; mi < 2; mi++)
#pragma unroll
        for (int h = 0; h < 2; h++) {
            int r2 = row0 + wm * 32 + mi * 16 + (lane >> 2) + 8 * h;
#pragma unroll
            for (int ni = 0; ni < 8; ni++) {
                int cl = wn * 64 + ni * 8 + (lane & 3) * 2;
                float v0 = acc[mi][ni][2 * h + 0] + bias[col0 + cl];
                float v1 = acc[mi][ni][2 * h + 1] + bias[col0 + cl + 1];
                __half2 h2 = __floats2half2_rn(v0, v1);
                *(__half2*)(Oh + (size_t)r2 * 1024 + col0 + cl) = h2;
            }
        }
    }
}

// ---------- 1024x1024 transpose + fp16 convert (per expert / weight) ----------
__global__ __launch_bounds__(256) void transpose_split_kernel(
    const float* __restrict__ in, __half* __restrict__ ohi, int mode)
{
    __shared__ float tsm[32][33];
    const int e = blockIdx.z;
    const int kt = blockIdx.x, nt = blockIdx.y;
    const float* ip = in + ((size_t)e << 20);
    const int tx = threadIdx.x, ty = threadIdx.y;   // 32 x 8
    for (int yy = ty; yy < 32; yy += 8)
        tsm[yy][tx] = ip[(size_t)(kt * 32 + yy) * 1024 + nt * 32 + tx];
    __syncthreads();
    for (int yy = ty; yy < 32; yy += 8) {
        int n = nt * 32 + yy, k = kt * 32 + tx;
        float v = tsm[tx][yy];
        size_t o = (mode == 0) ? ((size_t)(e * 1024 + n) * 1024 + k)
                               : ((size_t)n * 16384 + e * 1024 + k);
        ohi[o] = __float2half_rn(v);
    }
}

// ---------- elementwise fp32 -> fp16 convert ----------
__global__ __launch_bounds__(256) void cvt_kernel(
    const float* __restrict__ x, __half* __restrict__ hi)
{
    size_t i = ((size_t)blockIdx.x * 256 + threadIdx.x) * 4;
    float4 v = *(const float4*)(x + i);
    __half2 h0 = __floats2half2_rn(v.x, v.y);
    __half2 h1 = __floats2half2_rn(v.z, v.w);
    uint2 hw; hw.x = *(uint32_t*)&h0; hw.y = *(uint32_t*)&h1;
    *(uint2*)(hi + i) = hw;
}

// ---------------- flash attention on mma.sync, 64x64 tiles, causal ----------------
// 128 threads = 4 warps; warp w owns q rows [w*16, w*16+16)
#define AT_LD 72
#define ATTN_SMEM (3 * 64 * AT_LD * 2)
__global__ __launch_bounds__(128) void attn_kernel(
    const __half* __restrict__ qh, const __half* __restrict__ kh,
    const __half* __restrict__ vh, __half* __restrict__ oh)
{
    extern __shared__ char smc[];
    __half* Qs = (__half*)smc;            // [64][AT_LD]
    __half* Ks = Qs + 64 * AT_LD;
    __half* Vs = Ks + 64 * AT_LD;
    const int tid = threadIdx.x, lane = tid & 31, wid = tid >> 5;
    const int qb = blockIdx.x, h = blockIdx.y, b = blockIdx.z;
    const size_t base = ((size_t)b * Sc) * Dc + h * 64;
    uint32_t sbQ = smem_to_u32(Qs), sbK = smem_to_u32(Ks), sbV = smem_to_u32(Vs);

    // load Q tile (64 rows x 8 segs of 8 halves)
#pragma unroll
    for (int it = 0; it < 4; it++) {
        int f = tid + it * 128;
        int rr = f >> 3, s = f & 7;
        *(uint4*)(Qs + rr * AT_LD + s * 8) =
            *(const uint4*)(qh + base + (size_t)(qb * 64 + rr) * Dc + s * 8);
    }

    const int qi0 = qb * 64 + wid * 16 + (lane >> 2);   // h2=0 row; h2=1 is +8
    float oacc[8][4];
#pragma unroll
    for (int ni = 0; ni < 8; ni++)
#pragma unroll
        for (int q2 = 0; q2 < 4; q2++) oacc[ni][q2] = 0.f;
    float mrun[2] = {-1e30f, -1e30f}, lrun[2] = {0.f, 0.f};

    for (int kb = 0; kb <= qb; kb++) {
        __syncthreads();
        // load K,V tiles
#pragma unroll
        for (int it = 0; it < 4; it++) {
            int f = tid + it * 128;
            int rr = f >> 3, s = f & 7;
            *(uint4*)(Ks + rr * AT_LD + s * 8) =
                *(const uint4*)(kh + base + (size_t)(kb * 64 + rr) * Dc + s * 8);
            *(uint4*)(Vs + rr * AT_LD + s * 8) =
                *(const uint4*)(vh + base + (size_t)(kb * 64 + rr) * Dc + s * 8);
        }
        __syncthreads();

        // scores = Q @ K^T  (fp32 acc)
        float sacc[8][4];
#pragma unroll
        for (int ni = 0; ni < 8; ni++)
#pragma unroll
            for (int q2 = 0; q2 < 4; q2++) sacc[ni][q2] = 0.f;
        uint32_t aQ = sbQ + (wid * 16 + (lane & 15)) * (AT_LD * 2) + (lane >> 4) * 16;
#pragma unroll
        for (int kk = 0; kk < 4; kk++) {
            uint32_t aq[4];
            ldsm_x4(aq, aQ + kk * 32);
#pragma unroll
            for (int g = 0; g < 2; g++) {
                uint32_t bf[8];
#pragma unroll
                for (int pr = 0; pr < 2; pr++) {
                    uint32_t ab = sbK
                        + ((g * 4 + pr * 2 + (lane >> 4)) * 8 + (lane & 7)) * (AT_LD * 2)
                        + ((lane >> 3) & 1) * 16 + kk * 32;
                    ldsm_x4(&bf[pr * 4], ab);
                }
#pragma unroll
                for (int j = 0; j < 4; j++)
                    mma16816(sacc[g * 4 + j], aq, &bf[j * 2]);
            }
        }

        // scale + causal mask + online softmax (rows: qi0 + 8*h2)
        float mloc[2] = {-1e30f, -1e30f};
#pragma unroll
        for (int ni = 0; ni < 8; ni++)
#pragma unroll
            for (int h2 = 0; h2 < 2; h2++)
#pragma unroll
                for (int cc = 0; cc < 2; cc++) {
                    float sv = sacc[ni][h2 * 2 + cc] * 0.125f;
                    int kj = kb * 64 + ni * 8 + (lane & 3) * 2 + cc;
                    if (kj > qi0 + 8 * h2) sv = -1e9f;
                    sacc[ni][h2 * 2 + cc] = sv;
                    mloc[h2] = fmaxf(mloc[h2], sv);
                }
#pragma unroll
        for (int h2 = 0; h2 < 2; h2++) {
            mloc[h2] = fmaxf(mloc[h2], __shfl_xor_sync(0xffffffffu, mloc[h2], 1));
            mloc[h2] = fmaxf(mloc[h2], __shfl_xor_sync(0xffffffffu, mloc[h2], 2));
        }
        float alpha[2], lloc[2] = {0.f, 0.f};
        uint32_t pa[8][2];   // P in fp16: [ni][h2] = half2(c0,c1)
#pragma unroll
        for (int h2 = 0; h2 < 2; h2++) {
            float mnew = fmaxf(mrun[h2], mloc[h2]);
            alpha[h2] = __expf(mrun[h2] - mnew);
            mrun[h2] = mnew;
        }
#pragma unroll
        for (int ni = 0; ni < 8; ni++)
#pragma unroll
            for (int h2 = 0; h2 < 2; h2++) {
                float p0 = __expf(sacc[ni][h2 * 2 + 0] - mrun[h2]);
                float p1 = __expf(sacc[ni][h2 * 2 + 1] - mrun[h2]);
                lloc[h2] += p0 + p1;
                __half2 ph = __floats2half2_rn(p0, p1);
                pa[ni][h2] = *(uint32_t*)&ph;
            }
#pragma unroll
        for (int h2 = 0; h2 < 2; h2++) {
            lloc[h2] += __shfl_xor_sync(0xffffffffu, lloc[h2], 1);
            lloc[h2] += __shfl_xor_sync(0xffffffffu, lloc[h2], 2);
            lrun[h2] = lrun[h2] * alpha[h2] + lloc[h2];
        }
#pragma unroll
        for (int ni = 0; ni < 8; ni++)
#pragma unroll
            for (int h2 = 0; h2 < 2; h2++) {
                oacc[ni][h2 * 2 + 0] *= alpha[h2];
                oacc[ni][h2 * 2 + 1] *= alpha[h2];
            }

        // out += P @ V  (V^T via ldmatrix trans)
#pragma unroll
        for (int kk = 0; kk < 4; kk++) {
            uint32_t ap[4] = { pa[2 * kk][0], pa[2 * kk][1],
                               pa[2 * kk + 1][0], pa[2 * kk + 1][1] };
#pragma unroll
            for (int dp = 0; dp < 4; dp++) {
                uint32_t bv[4];
                uint32_t av = sbV + (kk * 16 + (lane & 15)) * (AT_LD * 2)
                              + (dp * 16 + (lane >> 4) * 8) * 2;
                ldsm_x4_t(bv, av);
                mma16816(oacc[dp * 2 + 0], ap, &bv[0]);
                mma16816(oacc[dp * 2 + 1], ap, &bv[2]);
            }
        }
    }

    // epilogue: normalize and store fp16
    float invl[2] = {1.f / lrun[0], 1.f / lrun[1]};
#pragma unroll
    for (int ni = 0; ni < 8; ni++)
#pragma unroll
        for (int h2 = 0; h2 < 2; h2++) {
            int row = qb * 64 + wid * 16 + (lane >> 2) + 8 * h2;
            int cl = ni * 8 + (lane & 3) * 2;
            __half2 hv = __floats2half2_rn(oacc[ni][h2 * 2 + 0] * invl[h2],
                                           oacc[ni][h2 * 2 + 1] * invl[h2]);
            *(__half2*)(oh + base + (size_t)row * Dc + cl) = hv;
        }
}

// ---------------- LayerNorm (optionally emits fp16) ----------------
template<bool SPLIT>
__global__ __launch_bounds__(256) void ln_kernel(
    const float* __restrict__ x, const float* __restrict__ gam,
    const float* __restrict__ bet, float* __restrict__ o,
    __half* __restrict__ ohi)
{
    const int row = blockIdx.x, tid = threadIdx.x;
    const float4 v = *(const float4*)(x + (size_t)row * 1024 + tid * 4);
    float s = v.x + v.y + v.z + v.w;
    float q = v.x * v.x + v.y * v.y + v.z * v.z + v.w * v.w;
#pragma unroll
    for (int off = 16; off; off >>= 1) {
        s += __shfl_xor_sync(0xffffffffu, s, off);
        q += __shfl_xor_sync(0xffffffffu, q, off);
    }
    __shared__ float ss[8], sq[8];
    if ((tid & 31) == 0) { ss[tid >> 5] = s; sq[tid >> 5] = q; }
    __syncthreads();
    float S = 0.f, Q = 0.f;
#pragma unroll
    for (int w = 0; w < 8; w++) { S += ss[w]; Q += sq[w]; }
    const float mu = S * (1.f / 1024.f);
    const float var = Q * (1.f / 1024.f) - mu * mu;
    const float inv = rsqrtf(var + 1e-5f);
    float4 g4 = *(const float4*)(gam + tid * 4);
    float4 b4 = *(const float4*)(bet + tid * 4);
    float4 r4;
    r4.x = (v.x - mu) * inv * g4.x + b4.x;
    r4.y = (v.y - mu) * inv * g4.y + b4.y;
    r4.z = (v.z - mu) * inv * g4.z + b4.z;
    r4.w = (v.w - mu) * inv * g4.w + b4.w;
    *(float4*)(o + (size_t)row * 1024 + tid * 4) = r4;
    if (SPLIT) {
        __half2 h0 = __floats2half2_rn(r4.x, r4.y);
        __half2 h1 = __floats2half2_rn(r4.z, r4.w);
        uint2 hw; hw.x = *(uint32_t*)&h0; hw.y = *(uint32_t*)&h1;
        *(uint2*)(ohi + (size_t)row * 1024 + tid * 4) = hw;
    }
}

// ---------------- gate: logits + per-gate softmax, /G folded in ----------------
__global__ __launch_bounds__(128) void gate_kernel(
    const float* __restrict__ h, const float* __restrict__ gW,
    const float* __restrict__ gb, float* __restrict__ coef)
{
    const int t = blockIdx.x, tid = threadIdx.x;
    float acc[16];
#pragma unroll
    for (int j = 0; j < 16; j++) acc[j] = 0.f;
    const float* hr = h + (size_t)t * 1024;
    for (int d = tid; d < 1024; d += 128) {
        float hv = hr[d];
#pragma unroll
        for (int g = 0; g < 2; g++)
#pragma unroll
            for (int e = 0; e < 8; e++)
                acc[g * 8 + e] += hv * gW[g * 8192 + d * 8 + e];
    }
    __shared__ float red[16][4];
#pragma unroll
    for (int j = 0; j < 16; j++) {
        float vv = acc[j];
        for (int off = 16; off; off >>= 1) vv += __shfl_xor_sync(0xffffffffu, vv, off);
        if ((tid & 31) == 0) red[j][tid >> 5] = vv;
    }
    __syncthreads();
    if (tid < 16) {
        float lg = red[tid][0] + red[tid][1] + red[tid][2] + red[tid][3] + gb[tid];
        float mx = lg;
        for (int off = 4; off; off >>= 1) mx = fmaxf(mx, __shfl_xor_sync(0xffffu, mx, off));
        float ex = __expf(lg - mx);
        float smv = ex;
        for (int off = 4; off; off >>= 1) smv += __shfl_xor_sync(0xffffu, smv, off);
        coef[(size_t)t * 16 + tid] = ex / smv * 0.5f;
    }
}

extern "C" void kernel_launch(void* const* d_in, const int* in_sizes, int n_in,
                              void* d_out, int out_size)
{
    const float* input  = (const float*)d_in[0];
    const float* Wq     = (const float*)d_in[1];
    const float* bq     = (const float*)d_in[2];
    const float* Wk     = (const float*)d_in[3];
    const float* bk     = (const float*)d_in[4];
    const float* Wv     = (const float*)d_in[5];
    const float* bv     = (const float*)d_in[6];
    const float* Wo     = (const float*)d_in[7];
    const float* bo     = (const float*)d_in[8];
    const float* ln1_g  = (const float*)d_in[9];
    const float* ln1_b  = (const float*)d_in[10];
    const float* gate_W = (const float*)d_in[11];
    const float* gate_b = (const float*)d_in[12];
    const float* eW1    = (const float*)d_in[13];
    const float* eb1    = (const float*)d_in[14];
    const float* eW2    = (const float*)d_in[15];
    const float* eb2    = (const float*)d_in[16];
    const float* ln2_g  = (const float*)d_in[17];
    const float* ln2_b  = (const float*)d_in[18];
    float* out = (float*)d_out;

    float *x1, *hbuf, *x2, *coef;
    __half *q, *k, *v, *attn, *xh, *Wth, *hh, *B1h, *B2h, *hidh;
    cudaGetSymbolAddress((void**)&q,    g_q);
    cudaGetSymbolAddress((void**)&k,    g_k);
    cudaGetSymbolAddress((void**)&v,    g_v);
    cudaGetSymbolAddress((void**)&attn, g_attn);
    cudaGetSymbolAddress((void**)&x1,   g_x1);
    cudaGetSymbolAddress((void**)&hbuf, g_h);
    cudaGetSymbolAddress((void**)&x2,   g_x2);
    cudaGetSymbolAddress((void**)&coef, g_coef);
    cudaGetSymbolAddress((void**)&xh,   g_xh);
    cudaGetSymbolAddress((void**)&Wth,  g_Wth);
    cudaGetSymbolAddress((void**)&hh,   g_hh);
    cudaGetSymbolAddress((void**)&B1h,  g_B1h);
    cudaGetSymbolAddress((void**)&B2h,  g_B2h);
    cudaGetSymbolAddress((void**)&hidh, g_hidh);

    cudaFuncSetAttribute(attn_kernel, cudaFuncAttributeMaxDynamicSharedMemorySize, ATTN_SMEM);
    cudaFuncSetAttribute((const void*)mma_gemm<0>, cudaFuncAttributeMaxDynamicSharedMemorySize, MMG_SMEM);
    cudaFuncSetAttribute((const void*)mma_gemm<1>, cudaFuncAttributeMaxDynamicSharedMemorySize, MMG_SMEM);
    cudaFuncSetAttribute((const void*)mma_gemm<2>, cudaFuncAttributeMaxDynamicSharedMemorySize, MMG_SMEM);
    cudaFuncSetAttribute((const void*)mma_gemm<3>, cudaFuncAttributeMaxDynamicSharedMemorySize, MMG_SMEM);

    const int M1 = 1024 * 1024;
    dim3 t32x8(32, 8);
    // weight prep (independent of activations)
    transpose_split_kernel<<<dim3(32, 32, 16), t32x8>>>(eW1, B1h, 0);
    transpose_split_kernel<<<dim3(32, 32, 16), t32x8>>>(eW2, B2h, 1);
    transpose_split_kernel<<<dim3(32, 32, 1), t32x8>>>(Wq, Wth + 0 * M1, 0);
    transpose_split_kernel<<<dim3(32, 32, 1), t32x8>>>(Wk, Wth + 1 * M1, 0);
    transpose_split_kernel<<<dim3(32, 32, 1), t32x8>>>(Wv, Wth + 2 * M1, 0);
    transpose_split_kernel<<<dim3(32, 32, 1), t32x8>>>(Wo, Wth + 3 * M1, 0);
    // convert input, QKV projections -> fp16 q/k/v
    cvt_kernel<<<4096, 256>>>(input, xh);
    mma_gemm<0><<<dim3(8, 16), 512, MMG_SMEM>>>(xh, 1024, Wth + 0 * M1, 1024,
                                                bq, nullptr, nullptr, q, nullptr, 1024);
    mma_gemm<0><<<dim3(8, 16), 512, MMG_SMEM>>>(xh, 1024, Wth + 1 * M1, 1024,
                                                bk, nullptr, nullptr, k, nullptr, 1024);
    mma_gemm<0><<<dim3(8, 16), 512, MMG_SMEM>>>(xh, 1024, Wth + 2 * M1, 1024,
                                                bv, nullptr, nullptr, v, nullptr, 1024);
    // attention (mma.sync) -> fp16 attn
    attn_kernel<<<dim3(32, 16, 2), 128, ATTN_SMEM>>>(q, k, v, attn);
    // O projection + residual (A = fp16 attn)
    mma_gemm<1><<<dim3(8, 16), 512, MMG_SMEM>>>(attn, 1024, Wth + 3 * M1, 1024,
                                                bo, input, nullptr, nullptr, x1, 1024);
    // LN1 (+ fp16 h), gates
    ln_kernel<true><<<4096, 256>>>(x1, ln1_g, ln1_b, hbuf, hh);
    gate_kernel<<<4096, 128>>>(hbuf, gate_W, gate_b, coef);
    // MoE (pure fp16)
    mma_gemm<2><<<dim3(128, 16), 512, MMG_SMEM>>>(hh, 1024, B1h, 1024,
                                                  eb1, nullptr, coef, hidh, nullptr, 1024);
    mma_gemm<3><<<dim3(8, 16), 512, MMG_SMEM>>>(hidh, 16384, B2h, 16384,
                                                eb2, hbuf, coef, nullptr, x2, 16384);
    // LN2 -> output
    ln_kernel<false><<<4096, 256>>>(x2, ln2_g, ln2_b, out, nullptr);
}